// round 11
// baseline (speedup 1.0000x reference)
#include <cuda_runtime.h>
#include <cuda_bf16.h>
#include <cstdint>

// Shapes (fixed by the problem)
static constexpr int Bc  = 2;
static constexpr int Sc  = 2048;
static constexpr int DMc = 512;
static constexpr int Hc  = 8;
static constexpr int DHc = 64;
static constexpr int BHc = Bc * Hc;          // 16
static constexpr int Mrows = Bc * Sc;        // 4096

// -------- device scratch (no allocations allowed) --------
__device__ float g_qp[Mrows * DMc];          // fp32 qp (for ab_kernel)
__device__ float g_outpre[Mrows * DMc];
__device__ float g_a[BHc * Sc];
__device__ float g_b[BHc * Sc];
// prepacked bf16 hi/lo: Q,K row-major packed 2-per-u32; V transposed per head
__device__ __align__(16) uint32_t g_qph[Mrows * DMc / 2];
__device__ __align__(16) uint32_t g_qpl[Mrows * DMc / 2];
__device__ __align__(16) uint32_t g_kph[Mrows * DMc / 2];
__device__ __align__(16) uint32_t g_kpl[Mrows * DMc / 2];
__device__ __align__(16) __nv_bfloat16 g_vth[Mrows * DMc];   // [bh][d][s]
__device__ __align__(16) __nv_bfloat16 g_vtl[Mrows * DMc];

// ==================== warp-mma helpers ====================
__device__ __forceinline__ uint32_t smem_u32(const void* p) {
    uint32_t a;
    asm("{ .reg .u64 t; cvta.to.shared.u64 t, %1; cvt.u32.u64 %0, t; }" : "=r"(a) : "l"(p));
    return a;
}
__device__ __forceinline__ void ldsm4(uint32_t (&r)[4], uint32_t addr) {
    asm volatile("ldmatrix.sync.aligned.m8n8.x4.shared.b16 {%0,%1,%2,%3}, [%4];"
        : "=r"(r[0]), "=r"(r[1]), "=r"(r[2]), "=r"(r[3]) : "r"(addr));
}
__device__ __forceinline__ void mma16816(float (&c)[4], const uint32_t (&a)[4],
                                         uint32_t b0, uint32_t b1) {
    asm volatile(
        "mma.sync.aligned.m16n8k16.row.col.f32.bf16.bf16.f32 "
        "{%0,%1,%2,%3}, {%4,%5,%6,%7}, {%8,%9}, {%0,%1,%2,%3};"
        : "+f"(c[0]), "+f"(c[1]), "+f"(c[2]), "+f"(c[3])
        : "r"(a[0]), "r"(a[1]), "r"(a[2]), "r"(a[3]), "r"(b0), "r"(b1));
}
__device__ __forceinline__ uint32_t addrA(uint32_t base, int r0, int k0, int lane, int stride) {
    return base + (uint32_t)(((r0 + (lane & 15)) * stride + (k0 >> 1) + (lane >> 4) * 4) * 4);
}
__device__ __forceinline__ uint32_t addrB(uint32_t base, int n0, int k0, int lane, int stride) {
    int r = n0 + (lane & 7) + ((lane >> 4) & 1) * 8;
    int c = (k0 >> 1) + ((lane >> 3) & 1) * 4;
    return base + (uint32_t)((r * stride + c) * 4);
}
__device__ __forceinline__ void split2(float x0, float x1, uint32_t& hi, uint32_t& lo) {
    __nv_bfloat16 h0 = __float2bfloat16(x0), h1 = __float2bfloat16(x1);
    float r0 = x0 - __bfloat162float(h0), r1 = x1 - __bfloat162float(h1);
    __nv_bfloat16 l0 = __float2bfloat16(r0), l1 = __float2bfloat16(r1);
    hi = (uint32_t)__bfloat16_as_ushort(h0) | ((uint32_t)__bfloat16_as_ushort(h1) << 16);
    lo = (uint32_t)__bfloat16_as_ushort(l0) | ((uint32_t)__bfloat16_as_ushort(l1) << 16);
}

// ============================================================
// GEMM body: C[M,512] = A[M,512] @ W[512,512] + bias  (split precision)
// ============================================================
__device__ __forceinline__ void gemm_body(
    const float* __restrict__ A, const float* __restrict__ W,
    const float* __restrict__ bias,
    float* __restrict__ C, uint32_t* __restrict__ Hp, uint32_t* __restrict__ Lp,
    __nv_bfloat16* __restrict__ Ht, __nv_bfloat16* __restrict__ Lt,
    bool writeF, bool writeP, bool writeT, int mb, int nb)
{
    __shared__ uint32_t sm[4 * 128 * 20];
    const int ASH = 0, ASL = 2560, BSH = 5120, BSL = 7680, RS = 20;

    const int tid = threadIdx.x;
    const int w = tid >> 5, lane = tid & 31;
    const int g = lane >> 2, t = lane & 3;
    const int wm = (w >> 1) * 32, wn = (w & 1) * 64;
    const uint32_t sbase = smem_u32(sm);

    float c[2][8][4];
#pragma unroll
    for (int mi = 0; mi < 2; mi++)
#pragma unroll
        for (int nf = 0; nf < 8; nf++)
#pragma unroll
            for (int r = 0; r < 4; r++) c[mi][nf][r] = 0.f;

    const int arow_i = tid >> 1, aseg = tid & 1;
    const float* arow = A + (size_t)(mb + arow_i) * DMc;
    const int bn = tid & 127, bkh = tid >> 7;

    for (int kc = 0; kc < 16; kc++) {
#pragma unroll
        for (int i = 0; i < 4; i++) {
            int f4 = aseg * 4 + i;
            float4 v = *(const float4*)(arow + kc * 32 + f4 * 4);
            uint32_t h0, l0, h1, l1;
            split2(v.x, v.y, h0, l0);
            split2(v.z, v.w, h1, l1);
            sm[ASH + arow_i * RS + f4 * 2]     = h0;
            sm[ASH + arow_i * RS + f4 * 2 + 1] = h1;
            sm[ASL + arow_i * RS + f4 * 2]     = l0;
            sm[ASL + arow_i * RS + f4 * 2 + 1] = l1;
        }
#pragma unroll
        for (int i = 0; i < 8; i++) {
            int kp = bkh * 8 + i;
            const float* wp = W + (size_t)(kc * 32 + 2 * kp) * DMc + nb + bn;
            float w0 = wp[0], w1 = wp[DMc];
            uint32_t hi, lo;
            split2(w0, w1, hi, lo);
            sm[BSH + bn * RS + kp] = hi;
            sm[BSL + bn * RS + kp] = lo;
        }
        __syncthreads();

#pragma unroll
        for (int kk = 0; kk < 2; kk++) {
            uint32_t ah[2][4], al[2][4];
#pragma unroll
            for (int mi = 0; mi < 2; mi++) {
                ldsm4(ah[mi], addrA(sbase + ASH * 4, wm + mi * 16, kk * 16, lane, RS));
                ldsm4(al[mi], addrA(sbase + ASL * 4, wm + mi * 16, kk * 16, lane, RS));
            }
#pragma unroll
            for (int nb2 = 0; nb2 < 4; nb2++) {
                uint32_t bhf[4], blf[4];
                ldsm4(bhf, addrB(sbase + BSH * 4, wn + nb2 * 16, kk * 16, lane, RS));
                ldsm4(blf, addrB(sbase + BSL * 4, wn + nb2 * 16, kk * 16, lane, RS));
#pragma unroll
                for (int mi = 0; mi < 2; mi++) {
                    mma16816(c[mi][2 * nb2],     ah[mi], bhf[0], bhf[1]);
                    mma16816(c[mi][2 * nb2],     ah[mi], blf[0], blf[1]);
                    mma16816(c[mi][2 * nb2],     al[mi], bhf[0], bhf[1]);
                    mma16816(c[mi][2 * nb2 + 1], ah[mi], bhf[2], bhf[3]);
                    mma16816(c[mi][2 * nb2 + 1], ah[mi], blf[2], blf[3]);
                    mma16816(c[mi][2 * nb2 + 1], al[mi], bhf[2], bhf[3]);
                }
            }
        }
        __syncthreads();
    }

#pragma unroll
    for (int mi = 0; mi < 2; mi++)
#pragma unroll
        for (int hh = 0; hh < 2; hh++) {
            int row = mb + wm + mi * 16 + hh * 8 + g;
#pragma unroll
            for (int nf = 0; nf < 8; nf++) {
                int col = nb + wn + nf * 8 + 2 * t;
                float2 bv = *(const float2*)(bias + col);
                float ox = c[mi][nf][hh * 2 + 0] + bv.x;
                float oy = c[mi][nf][hh * 2 + 1] + bv.y;
                if (writeF)
                    *(float2*)(C + (size_t)row * DMc + col) = make_float2(ox, oy);
                if (writeP) {
                    uint32_t hi, lo;
                    split2(ox, oy, hi, lo);
                    size_t pi = ((size_t)row * DMc + col) >> 1;
                    Hp[pi] = hi;
                    Lp[pi] = lo;
                }
                if (writeT) {
                    __nv_bfloat16 h0 = __float2bfloat16(ox);
                    __nv_bfloat16 l0 = __float2bfloat16(ox - __bfloat162float(h0));
                    __nv_bfloat16 h1 = __float2bfloat16(oy);
                    __nv_bfloat16 l1 = __float2bfloat16(oy - __bfloat162float(h1));
                    size_t i0 = ((size_t)(((row >> 11) * Hc + (col >> 6)) * DHc + (col & 63))) * Sc
                              + (row & (Sc - 1));
                    Ht[i0] = h0; Lt[i0] = l0;
                    Ht[i0 + Sc] = h1; Lt[i0 + Sc] = l1;
                }
            }
        }
}

// K1: fused Q/K/V projections. grid = (4, 32, 3), block 256.
__global__ __launch_bounds__(256, 1)
void qkv_kernel(const float* __restrict__ q, const float* __restrict__ k,
                const float* __restrict__ v,
                const float* __restrict__ Wq, const float* __restrict__ Wk,
                const float* __restrict__ Wv,
                const float* __restrict__ bq, const float* __restrict__ bk,
                const float* __restrict__ bv)
{
    const int mb = blockIdx.y * 128, nb = blockIdx.x * 128;
    if (blockIdx.z == 0)
        gemm_body(q, Wq, bq, g_qp, g_qph, g_qpl, nullptr, nullptr, true, true, false, mb, nb);
    else if (blockIdx.z == 1)
        gemm_body(k, Wk, bk, nullptr, g_kph, g_kpl, nullptr, nullptr, false, true, false, mb, nb);
    else
        gemm_body(v, Wv, bv, nullptr, nullptr, nullptr, g_vth, g_vtl, false, false, true, mb, nb);
}

// K4: final projection. grid = (4, 32).
__global__ __launch_bounds__(256, 1)
void out_kernel(const float* __restrict__ Wo, const float* __restrict__ bo,
                float* __restrict__ out)
{
    gemm_body(g_outpre, Wo, bo, out, nullptr, nullptr, nullptr, nullptr,
              true, false, false, blockIdx.y * 128, blockIdx.x * 128);
}

// ============================================================
// K2: a,b heads. grid = 128, block 256.
// ============================================================
__global__ __launch_bounds__(256)
void ab_kernel(const float* __restrict__ Wa, const float* __restrict__ ba,
               const float* __restrict__ Wb, const float* __restrict__ bb)
{
    __shared__ float4 sWa[512][2];
    __shared__ float4 sWb[512][2];
    const int tid = threadIdx.x;
#pragma unroll
    for (int i = 0; i < 4; i++) {
        int idx = tid + i * 256;
        ((float4*)sWa)[idx] = ((const float4*)Wa)[idx];
        ((float4*)sWb)[idx] = ((const float4*)Wb)[idx];
    }
    __syncthreads();

    const int w = tid >> 5, lane = tid & 31;
    const int rbase = blockIdx.x * 32 + w * 4;

    float acc[4][16];
#pragma unroll
    for (int j = 0; j < 4; j++)
#pragma unroll
        for (int h = 0; h < 16; h++) acc[j][h] = 0.f;

#pragma unroll
    for (int tt = 0; tt < 4; tt++) {
        const int d0 = tt * 128 + lane * 4;
        float4 x[4];
#pragma unroll
        for (int j = 0; j < 4; j++)
            x[j] = *(const float4*)(g_qp + (size_t)(rbase + j) * DMc + d0);
#pragma unroll
        for (int dd = 0; dd < 4; dd++) {
            float4 wa0 = sWa[d0 + dd][0], wa1 = sWa[d0 + dd][1];
            float4 wb0 = sWb[d0 + dd][0], wb1 = sWb[d0 + dd][1];
#pragma unroll
            for (int j = 0; j < 4; j++) {
                float xv = (&x[j].x)[dd];
                acc[j][0]  = fmaf(xv, wa0.x, acc[j][0]);
                acc[j][1]  = fmaf(xv, wa0.y, acc[j][1]);
                acc[j][2]  = fmaf(xv, wa0.z, acc[j][2]);
                acc[j][3]  = fmaf(xv, wa0.w, acc[j][3]);
                acc[j][4]  = fmaf(xv, wa1.x, acc[j][4]);
                acc[j][5]  = fmaf(xv, wa1.y, acc[j][5]);
                acc[j][6]  = fmaf(xv, wa1.z, acc[j][6]);
                acc[j][7]  = fmaf(xv, wa1.w, acc[j][7]);
                acc[j][8]  = fmaf(xv, wb0.x, acc[j][8]);
                acc[j][9]  = fmaf(xv, wb0.y, acc[j][9]);
                acc[j][10] = fmaf(xv, wb0.z, acc[j][10]);
                acc[j][11] = fmaf(xv, wb0.w, acc[j][11]);
                acc[j][12] = fmaf(xv, wb1.x, acc[j][12]);
                acc[j][13] = fmaf(xv, wb1.y, acc[j][13]);
                acc[j][14] = fmaf(xv, wb1.z, acc[j][14]);
                acc[j][15] = fmaf(xv, wb1.w, acc[j][15]);
            }
        }
    }
#pragma unroll
    for (int o = 16; o > 0; o >>= 1)
#pragma unroll
        for (int j = 0; j < 4; j++)
#pragma unroll
            for (int h = 0; h < 16; h++)
                acc[j][h] += __shfl_xor_sync(0xffffffff, acc[j][h], o);

    if (lane < 4) {
        int row = rbase + lane;
        int b = row >> 11, s = row & (Sc - 1);
#pragma unroll
        for (int h = 0; h < 8; h++) {
            g_a[(b * Hc + h) * Sc + s] = acc[lane][h] + ba[h];
            g_b[(b * Hc + h) * Sc + s] = acc[lane][h + 8] + bb[h];
        }
    }
}

// ============================================================
// Fused flash attention. grid = (32 qtile64, 16 bh), block = 256.
// smem layout (u32 words):
//   QH[64][36], QL[64][36], KH[128][36], KL[128][36],
//   VH[64][68], VL[64][68], RMT[16][8][16]
// ============================================================
static constexpr int QH_O = 0, QL_O = 2304, KH_O = 4608, KL_O = 9216;
static constexpr int VH_O = 13824, VL_O = 18176, RMT_O = 22528;
static constexpr int RSQ = 36, RSV = 68;
static constexpr int FUSE_SMEM = 24576 * 4;   // 98304 B

template<int NROWS>
__device__ __forceinline__ void stage_copy(uint32_t* sm, int offH, int offL,
        const uint32_t* __restrict__ srcH, const uint32_t* __restrict__ srcL,
        size_t rowbase, int tid)
{
    const int row = tid >> 1, half = tid & 1;
    if (row < NROWS) {
        const size_t s0 = rowbase + (size_t)row * (DMc / 2) + half * 16;
        const uint4* sH = (const uint4*)(srcH + s0);
        const uint4* sL = (const uint4*)(srcL + s0);
        uint4* dH = (uint4*)(sm + offH + row * RSQ + half * 16);
        uint4* dL = (uint4*)(sm + offL + row * RSQ + half * 16);
#pragma unroll
        for (int i = 0; i < 4; i++) { dH[i] = sH[i]; dL[i] = sL[i]; }
    }
}

__device__ __forceinline__ void score_mma64(float (&c)[8][4], uint32_t sbase,
                                            int wm, int wn, int lane)
{
#pragma unroll
    for (int nf = 0; nf < 8; nf++)
#pragma unroll
        for (int r = 0; r < 4; r++) c[nf][r] = 0.f;
#pragma unroll
    for (int kk = 0; kk < 4; kk++) {
        uint32_t ah[4], al[4];
        ldsm4(ah, addrA(sbase + QH_O * 4, wm, kk * 16, lane, RSQ));
        ldsm4(al, addrA(sbase + QL_O * 4, wm, kk * 16, lane, RSQ));
#pragma unroll
        for (int nb2 = 0; nb2 < 4; nb2++) {
            uint32_t bhf[4], blf[4];
            ldsm4(bhf, addrB(sbase + KH_O * 4, wn + nb2 * 16, kk * 16, lane, RSQ));
            ldsm4(blf, addrB(sbase + KL_O * 4, wn + nb2 * 16, kk * 16, lane, RSQ));
            mma16816(c[2 * nb2],     ah, bhf[0], bhf[1]);
            mma16816(c[2 * nb2],     ah, blf[0], blf[1]);
            mma16816(c[2 * nb2],     al, bhf[0], bhf[1]);
            mma16816(c[2 * nb2 + 1], ah, bhf[2], bhf[3]);
            mma16816(c[2 * nb2 + 1], ah, blf[2], blf[3]);
            mma16816(c[2 * nb2 + 1], al, bhf[2], bhf[3]);
        }
    }
}

__global__ __launch_bounds__(256, 2)
void fused_attn_kernel(const float* __restrict__ xdiff, const int* __restrict__ mask,
                       float* __restrict__ attn)
{
    extern __shared__ uint32_t sm[];
    const int tid = threadIdx.x, w = tid >> 5, lane = tid & 31;
    const int g = lane >> 2, t = lane & 3;
    const int bh = blockIdx.y, b = bh >> 3, h = bh & 7;
    const int qb = blockIdx.x * 64;
    const int wm = (w >> 1) * 16, wn = (w & 1) * 64;
    const uint32_t sbase = smem_u32(sm);

    // stage Q (64 rows) once
    stage_copy<64>(sm, QH_O, QL_O, g_qph, g_qpl,
                   (size_t)(b * Sc + qb) * (DMc / 2) + h * (DHc / 2), tid);

    const int lr0 = wm + g, lr1 = wm + 8 + g;
    float rm0 = -3.0e38f, rm1 = -3.0e38f, rs0 = 0.f, rs1 = 0.f;
    const float aq0 = g_a[bh * Sc + qb + lr0], bq0 = g_b[bh * Sc + qb + lr0];
    const float aq1 = g_a[bh * Sc + qb + lr1], bq1 = g_b[bh * Sc + qb + lr1];
    const float* xr0 = xdiff + ((size_t)b * Sc + qb + lr0) * Sc;
    const float* xr1 = xdiff + ((size_t)b * Sc + qb + lr1) * Sc;
    float* lrow0 = attn + ((size_t)bh * Sc + qb + lr0) * Sc;
    float* lrow1 = attn + ((size_t)bh * Sc + qb + lr1) * Sc;
    const int* mrow = mask + b * Sc;
    const int vrow = tid >> 2, vseg = tid & 3;

    float o[8][4];
#pragma unroll
    for (int nf = 0; nf < 8; nf++)
#pragma unroll
        for (int r = 0; r < 4; r++) o[nf][r] = 0.f;

    for (int kt = 0; kt < 16; kt++) {
        const int kb = kt * 128;
        // stage K tile
        stage_copy<128>(sm, KH_O, KL_O, g_kph, g_kpl,
                        (size_t)(b * Sc + kb) * (DMc / 2) + h * (DHc / 2), tid);
        // stage V^T tile (64 d x 128 k)
        {
            const uint4* sH = (const uint4*)g_vth + ((size_t)(bh * DHc + vrow) * Sc + kb) / 8;
            const uint4* sL = (const uint4*)g_vtl + ((size_t)(bh * DHc + vrow) * Sc + kb) / 8;
            uint4* dH = (uint4*)(sm + VH_O + vrow * RSV);
            uint4* dL = (uint4*)(sm + VL_O + vrow * RSV);
#pragma unroll
            for (int i = 0; i < 4; i++) {
                dH[vseg * 4 + i] = sH[vseg * 4 + i];
                dL[vseg * 4 + i] = sL[vseg * 4 + i];
            }
        }
        __syncthreads();

        float c[8][4];
        score_mma64(c, sbase, wm, wn, lane);

        // epilogue: scores -> full logits in c, track tile max
        float tm0 = -3.0e38f, tm1 = -3.0e38f;
#pragma unroll
        for (int nf = 0; nf < 8; nf++) {
            int col = kb + wn + nf * 8 + 2 * t;
            int2 mv = *(const int2*)(mrow + col);
            float mt0 = (float)mv.x * -1e9f, mt1 = (float)mv.y * -1e9f;
            float2 x0 = *(const float2*)(xr0 + col);
            float2 x1 = *(const float2*)(xr1 + col);
            c[nf][0] = c[nf][0] * 0.125f + mt0 + aq0 * x0.x + bq0 * x0.x * x0.x;
            c[nf][1] = c[nf][1] * 0.125f + mt1 + aq0 * x0.y + bq0 * x0.y * x0.y;
            c[nf][2] = c[nf][2] * 0.125f + mt0 + aq1 * x1.x + bq1 * x1.x * x1.x;
            c[nf][3] = c[nf][3] * 0.125f + mt1 + aq1 * x1.y + bq1 * x1.y * x1.y;
            tm0 = fmaxf(tm0, fmaxf(c[nf][0], c[nf][1]));
            tm1 = fmaxf(tm1, fmaxf(c[nf][2], c[nf][3]));
        }
        // quad-sync max, flash rescale
        tm0 = fmaxf(tm0, __shfl_xor_sync(0xffffffff, tm0, 1));
        tm0 = fmaxf(tm0, __shfl_xor_sync(0xffffffff, tm0, 2));
        tm1 = fmaxf(tm1, __shfl_xor_sync(0xffffffff, tm1, 1));
        tm1 = fmaxf(tm1, __shfl_xor_sync(0xffffffff, tm1, 2));
        float m0 = fmaxf(rm0, tm0), m1 = fmaxf(rm1, tm1);
        float sc0 = __expf(rm0 - m0), sc1 = __expf(rm1 - m1);
        rs0 *= sc0; rs1 *= sc1;
#pragma unroll
        for (int nf = 0; nf < 8; nf++) {
            o[nf][0] *= sc0; o[nf][1] *= sc0;
            o[nf][2] *= sc1; o[nf][3] *= sc1;
        }
        rm0 = m0; rm1 = m1;
        if (t == 0) {
            float* rmt = (float*)(sm + RMT_O);
            rmt[(kt * 8 + w) * 16 + g]     = rm0;
            rmt[(kt * 8 + w) * 16 + 8 + g] = rm1;
        }

        // P: write unnormalized exp to attn, feed P@V MMA
#pragma unroll
        for (int j = 0; j < 4; j++) {
            uint32_t pah[4], pal[4];
#pragma unroll
            for (int nn = 0; nn < 2; nn++) {
                int nf = 2 * j + nn;
                int col = kb + wn + nf * 8 + 2 * t;
                float p0 = __expf(c[nf][0] - rm0), p1 = __expf(c[nf][1] - rm0);
                float p2 = __expf(c[nf][2] - rm1), p3 = __expf(c[nf][3] - rm1);
                rs0 += p0 + p1; rs1 += p2 + p3;
                *(float2*)(lrow0 + col) = make_float2(p0, p1);
                *(float2*)(lrow1 + col) = make_float2(p2, p3);
                split2(p0, p1, pah[nn * 2 + 0], pal[nn * 2 + 0]);
                split2(p2, p3, pah[nn * 2 + 1], pal[nn * 2 + 1]);
            }
#pragma unroll
            for (int nd = 0; nd < 4; nd++) {
                uint32_t vh[4], vl[4];
                ldsm4(vh, addrB(sbase + VH_O * 4, nd * 16, wn + j * 16, lane, RSV));
                ldsm4(vl, addrB(sbase + VL_O * 4, nd * 16, wn + j * 16, lane, RSV));
                mma16816(o[2 * nd],     pah, vh[0], vh[1]);
                mma16816(o[2 * nd],     pah, vl[0], vl[1]);
                mma16816(o[2 * nd],     pal, vh[0], vh[1]);
                mma16816(o[2 * nd + 1], pah, vh[2], vh[3]);
                mma16816(o[2 * nd + 1], pah, vl[2], vl[3]);
                mma16816(o[2 * nd + 1], pal, vh[2], vh[3]);
            }
        }
        __syncthreads();
    }

    // quad-reduce partial sums (max already quad-uniform)
    rs0 += __shfl_xor_sync(0xffffffff, rs0, 1);
    rs0 += __shfl_xor_sync(0xffffffff, rs0, 2);
    rs1 += __shfl_xor_sync(0xffffffff, rs1, 1);
    rs1 += __shfl_xor_sync(0xffffffff, rs1, 2);

    // stats merge across warp halves
    float2* sred = (float2*)sm;                       // QH area
    if (t == 0) {
        sred[w * 16 + g]     = make_float2(rm0, rs0);
        sred[w * 16 + 8 + g] = make_float2(rm1, rs1);
    }
    __syncthreads();
    float* mfin = (float*)(sm + QL_O);                // [64]
    float* ifin = mfin + 64;                          // [64]
    if (!(w & 1) && t == 0) {
#pragma unroll
        for (int hh = 0; hh < 2; hh++) {
            int rl = hh * 8 + g;
            float2 A2 = sred[w * 16 + rl], B2 = sred[(w ^ 1) * 16 + rl];
            float mf = fmaxf(A2.x, B2.x);
            float sf = A2.y * __expf(A2.x - mf) + B2.y * __expf(B2.x - mf);
            mfin[wm + rl] = mf;
            ifin[wm + rl] = 1.0f / sf;
        }
    }
    __syncthreads();

    // scale table: rmt -> exp(rmt - m_final) * inv (in place)
    {
        float* rmt = (float*)(sm + RMT_O);
        for (int i = tid; i < 2048; i += 256) {
            int ww = (i >> 4) & 7, r = i & 15;
            int row = (ww >> 1) * 16 + r;
            rmt[i] = __expf(rmt[i] - mfin[row]) * ifin[row];
        }
    }
    // o merge across warp halves
    float f0 = __expf(rm0 - mfin[lr0]);
    float f1 = __expf(rm1 - mfin[lr1]);
    float* red = (float*)(sm + KH_O);
    if (w & 1) {
        float* dst = red + ((w >> 1) * 32 + lane) * 33;
#pragma unroll
        for (int nf = 0; nf < 8; nf++) {
            dst[nf * 4 + 0] = o[nf][0] * f0;
            dst[nf * 4 + 1] = o[nf][1] * f0;
            dst[nf * 4 + 2] = o[nf][2] * f1;
            dst[nf * 4 + 3] = o[nf][3] * f1;
        }
    }
    __syncthreads();
    if (!(w & 1)) {
        const float* src = red + ((w >> 1) * 32 + lane) * 33;
        float i0 = ifin[lr0], i1 = ifin[lr1];
        int q0 = qb + lr0, q1 = qb + lr1;
#pragma unroll
        for (int nf = 0; nf < 8; nf++) {
            float v0 = (o[nf][0] * f0 + src[nf * 4 + 0]) * i0;
            float v1 = (o[nf][1] * f0 + src[nf * 4 + 1]) * i0;
            float v2 = (o[nf][2] * f1 + src[nf * 4 + 2]) * i1;
            float v3 = (o[nf][3] * f1 + src[nf * 4 + 3]) * i1;
            *(float2*)(g_outpre + (size_t)(b * Sc + q0) * DMc + h * DHc + nf * 8 + 2 * t) = make_float2(v0, v1);
            *(float2*)(g_outpre + (size_t)(b * Sc + q1) * DMc + h * DHc + nf * 8 + 2 * t) = make_float2(v2, v3);
        }
    }

    // phase 3: normalize attn in place (coalesced, L2-hot)
    const float* rmt = (const float*)(sm + RMT_O);
    const size_t abase = ((size_t)bh * Sc + qb) * Sc;
    for (int i = 0; i < 128; i++) {
        int f4 = i * 256 + tid;
        int row = f4 >> 9;
        int col = (f4 & 511) * 4;
        int tile = col >> 7;
        int half = (col >> 6) & 1;
        int wwr = (row >> 4) * 2 + half;
        float s = rmt[(tile * 8 + wwr) * 16 + (row & 15)];
        float* ptr = attn + abase + (size_t)row * Sc + col;
        float4 P = *(float4*)ptr;
        P.x *= s; P.y *= s; P.z *= s; P.w *= s;
        *(float4*)ptr = P;
    }
}

// ============================================================
extern "C" void kernel_launch(void* const* d_in, const int* in_sizes, int n_in,
                              void* d_out, int out_size)
{
    const float* q     = (const float*)d_in[0];
    const float* k     = (const float*)d_in[1];
    const float* v     = (const float*)d_in[2];
    const float* xdiff = (const float*)d_in[3];
    const int*   mask  = (const int*)d_in[4];
    const float* Wq = (const float*)d_in[5];
    const float* bq = (const float*)d_in[6];
    const float* Wk = (const float*)d_in[7];
    const float* bk = (const float*)d_in[8];
    const float* Wv = (const float*)d_in[9];
    const float* bv = (const float*)d_in[10];
    const float* Wa = (const float*)d_in[11];
    const float* ba = (const float*)d_in[12];
    const float* Wb = (const float*)d_in[13];
    const float* bb = (const float*)d_in[14];
    const float* Wo = (const float*)d_in[15];
    const float* bo = (const float*)d_in[16];

    float* out  = (float*)d_out;                 // (B,S,DM)
    float* attn = out + (size_t)Bc * Sc * DMc;   // (B,H,S,S)

    cudaFuncSetAttribute(fused_attn_kernel, cudaFuncAttributeMaxDynamicSharedMemorySize, FUSE_SMEM);

    qkv_kernel<<<dim3(DMc / 128, Mrows / 128, 3), 256>>>(q, k, v, Wq, Wk, Wv, bq, bk, bv);
    ab_kernel<<<Mrows / 32, 256>>>(Wa, ba, Wb, bb);
    fused_attn_kernel<<<dim3(Sc / 64, BHc), 256, FUSE_SMEM>>>(xdiff, mask, attn);
    out_kernel<<<dim3(DMc / 128, Mrows / 128), 256>>>(Wo, bo, out);
}

// round 12
// speedup vs baseline: 1.1370x; 1.1370x over previous
#include <cuda_runtime.h>
#include <cuda_bf16.h>
#include <cstdint>

// Shapes (fixed by the problem)
static constexpr int Bc  = 2;
static constexpr int Sc  = 2048;
static constexpr int DMc = 512;
static constexpr int Hc  = 8;
static constexpr int DHc = 64;
static constexpr int BHc = Bc * Hc;          // 16
static constexpr int Mrows = Bc * Sc;        // 4096

// -------- device scratch (no allocations allowed) --------
__device__ float g_qp[Mrows * DMc];          // fp32 qp (for ab_kernel)
__device__ float g_outpre[Mrows * DMc];
__device__ float g_a[BHc * Sc];
__device__ float g_b[BHc * Sc];
// prepacked bf16 hi/lo: Q,K row-major packed 2-per-u32; V transposed per head
__device__ __align__(16) uint32_t g_qph[Mrows * DMc / 2];
__device__ __align__(16) uint32_t g_qpl[Mrows * DMc / 2];
__device__ __align__(16) uint32_t g_kph[Mrows * DMc / 2];
__device__ __align__(16) uint32_t g_kpl[Mrows * DMc / 2];
__device__ __align__(16) __nv_bfloat16 g_vth[Mrows * DMc];   // [bh][d][s]
__device__ __align__(16) __nv_bfloat16 g_vtl[Mrows * DMc];

// ==================== warp-mma helpers ====================
__device__ __forceinline__ uint32_t smem_u32(const void* p) {
    uint32_t a;
    asm("{ .reg .u64 t; cvta.to.shared.u64 t, %1; cvt.u32.u64 %0, t; }" : "=r"(a) : "l"(p));
    return a;
}
__device__ __forceinline__ void ldsm4(uint32_t (&r)[4], uint32_t addr) {
    asm volatile("ldmatrix.sync.aligned.m8n8.x4.shared.b16 {%0,%1,%2,%3}, [%4];"
        : "=r"(r[0]), "=r"(r[1]), "=r"(r[2]), "=r"(r[3]) : "r"(addr));
}
__device__ __forceinline__ void mma16816(float (&c)[4], const uint32_t (&a)[4],
                                         uint32_t b0, uint32_t b1) {
    asm volatile(
        "mma.sync.aligned.m16n8k16.row.col.f32.bf16.bf16.f32 "
        "{%0,%1,%2,%3}, {%4,%5,%6,%7}, {%8,%9}, {%0,%1,%2,%3};"
        : "+f"(c[0]), "+f"(c[1]), "+f"(c[2]), "+f"(c[3])
        : "r"(a[0]), "r"(a[1]), "r"(a[2]), "r"(a[3]), "r"(b0), "r"(b1));
}
__device__ __forceinline__ uint32_t addrA(uint32_t base, int r0, int k0, int lane, int stride) {
    return base + (uint32_t)(((r0 + (lane & 15)) * stride + (k0 >> 1) + (lane >> 4) * 4) * 4);
}
__device__ __forceinline__ uint32_t addrB(uint32_t base, int n0, int k0, int lane, int stride) {
    int r = n0 + (lane & 7) + ((lane >> 4) & 1) * 8;
    int c = (k0 >> 1) + ((lane >> 3) & 1) * 4;
    return base + (uint32_t)((r * stride + c) * 4);
}
// fast split: one bf16x2 cvt for hi pair, residual via bit ops, one cvt for lo pair.
// hi = {low16: bf16(x0), high16: bf16(x1)}
__device__ __forceinline__ void split2(float x0, float x1, uint32_t& hi, uint32_t& lo) {
    uint32_t h;
    asm("cvt.rn.bf16x2.f32 %0, %1, %2;" : "=r"(h) : "f"(x1), "f"(x0));
    float f0 = __uint_as_float(h << 16);
    float f1 = __uint_as_float(h & 0xffff0000u);
    float r0 = x0 - f0, r1 = x1 - f1;
    asm("cvt.rn.bf16x2.f32 %0, %1, %2;" : "=r"(lo) : "f"(r1), "f"(r0));
    hi = h;
}
// cp.async helpers
__device__ __forceinline__ void cpa16(uint32_t dst, const void* src) {
    asm volatile("cp.async.cg.shared.global [%0], [%1], 16;" :: "r"(dst), "l"(src));
}
#define CPA_COMMIT() asm volatile("cp.async.commit_group;" ::: "memory")
#define CPA_WAIT1()  asm volatile("cp.async.wait_group 1;" ::: "memory")
#define CPA_WAIT0()  asm volatile("cp.async.wait_group 0;" ::: "memory")

// ============================================================
// GEMM body: C[M,512] = A[M,512] @ W[512,512] + bias  (split precision)
// ============================================================
__device__ __forceinline__ void gemm_body(
    const float* __restrict__ A, const float* __restrict__ W,
    const float* __restrict__ bias,
    float* __restrict__ C, uint32_t* __restrict__ Hp, uint32_t* __restrict__ Lp,
    __nv_bfloat16* __restrict__ Ht, __nv_bfloat16* __restrict__ Lt,
    bool writeF, bool writeP, bool writeT, int mb, int nb)
{
    __shared__ uint32_t sm[4 * 128 * 20];
    const int ASH = 0, ASL = 2560, BSH = 5120, BSL = 7680, RS = 20;

    const int tid = threadIdx.x;
    const int w = tid >> 5, lane = tid & 31;
    const int g = lane >> 2, t = lane & 3;
    const int wm = (w >> 1) * 32, wn = (w & 1) * 64;
    const uint32_t sbase = smem_u32(sm);

    float c[2][8][4];
#pragma unroll
    for (int mi = 0; mi < 2; mi++)
#pragma unroll
        for (int nf = 0; nf < 8; nf++)
#pragma unroll
            for (int r = 0; r < 4; r++) c[mi][nf][r] = 0.f;

    const int arow_i = tid >> 1, aseg = tid & 1;
    const float* arow = A + (size_t)(mb + arow_i) * DMc;
    const int bn = tid & 127, bkh = tid >> 7;

    for (int kc = 0; kc < 16; kc++) {
#pragma unroll
        for (int i = 0; i < 4; i++) {
            int f4 = aseg * 4 + i;
            float4 v = *(const float4*)(arow + kc * 32 + f4 * 4);
            uint32_t h0, l0, h1, l1;
            split2(v.x, v.y, h0, l0);
            split2(v.z, v.w, h1, l1);
            sm[ASH + arow_i * RS + f4 * 2]     = h0;
            sm[ASH + arow_i * RS + f4 * 2 + 1] = h1;
            sm[ASL + arow_i * RS + f4 * 2]     = l0;
            sm[ASL + arow_i * RS + f4 * 2 + 1] = l1;
        }
#pragma unroll
        for (int i = 0; i < 8; i++) {
            int kp = bkh * 8 + i;
            const float* wp = W + (size_t)(kc * 32 + 2 * kp) * DMc + nb + bn;
            float w0 = wp[0], w1 = wp[DMc];
            uint32_t hi, lo;
            split2(w0, w1, hi, lo);
            sm[BSH + bn * RS + kp] = hi;
            sm[BSL + bn * RS + kp] = lo;
        }
        __syncthreads();

#pragma unroll
        for (int kk = 0; kk < 2; kk++) {
            uint32_t ah[2][4], al[2][4];
#pragma unroll
            for (int mi = 0; mi < 2; mi++) {
                ldsm4(ah[mi], addrA(sbase + ASH * 4, wm + mi * 16, kk * 16, lane, RS));
                ldsm4(al[mi], addrA(sbase + ASL * 4, wm + mi * 16, kk * 16, lane, RS));
            }
#pragma unroll
            for (int nb2 = 0; nb2 < 4; nb2++) {
                uint32_t bhf[4], blf[4];
                ldsm4(bhf, addrB(sbase + BSH * 4, wn + nb2 * 16, kk * 16, lane, RS));
                ldsm4(blf, addrB(sbase + BSL * 4, wn + nb2 * 16, kk * 16, lane, RS));
#pragma unroll
                for (int mi = 0; mi < 2; mi++) {
                    mma16816(c[mi][2 * nb2],     ah[mi], bhf[0], bhf[1]);
                    mma16816(c[mi][2 * nb2],     ah[mi], blf[0], blf[1]);
                    mma16816(c[mi][2 * nb2],     al[mi], bhf[0], bhf[1]);
                    mma16816(c[mi][2 * nb2 + 1], ah[mi], bhf[2], bhf[3]);
                    mma16816(c[mi][2 * nb2 + 1], ah[mi], blf[2], blf[3]);
                    mma16816(c[mi][2 * nb2 + 1], al[mi], bhf[2], bhf[3]);
                }
            }
        }
        __syncthreads();
    }

#pragma unroll
    for (int mi = 0; mi < 2; mi++)
#pragma unroll
        for (int hh = 0; hh < 2; hh++) {
            int row = mb + wm + mi * 16 + hh * 8 + g;
#pragma unroll
            for (int nf = 0; nf < 8; nf++) {
                int col = nb + wn + nf * 8 + 2 * t;
                float2 bv = *(const float2*)(bias + col);
                float ox = c[mi][nf][hh * 2 + 0] + bv.x;
                float oy = c[mi][nf][hh * 2 + 1] + bv.y;
                if (writeF)
                    *(float2*)(C + (size_t)row * DMc + col) = make_float2(ox, oy);
                if (writeP) {
                    uint32_t hi, lo;
                    split2(ox, oy, hi, lo);
                    size_t pi = ((size_t)row * DMc + col) >> 1;
                    Hp[pi] = hi;
                    Lp[pi] = lo;
                }
                if (writeT) {
                    uint32_t hi, lo;
                    split2(ox, oy, hi, lo);
                    size_t i0 = ((size_t)(((row >> 11) * Hc + (col >> 6)) * DHc + (col & 63))) * Sc
                              + (row & (Sc - 1));
                    Ht[i0] = __ushort_as_bfloat16((unsigned short)(hi & 0xffff));
                    Lt[i0] = __ushort_as_bfloat16((unsigned short)(lo & 0xffff));
                    Ht[i0 + Sc] = __ushort_as_bfloat16((unsigned short)(hi >> 16));
                    Lt[i0 + Sc] = __ushort_as_bfloat16((unsigned short)(lo >> 16));
                }
            }
        }
}

// K1: fused Q/K/V projections. grid = (4, 32, 3), block 256.
__global__ __launch_bounds__(256, 1)
void qkv_kernel(const float* __restrict__ q, const float* __restrict__ k,
                const float* __restrict__ v,
                const float* __restrict__ Wq, const float* __restrict__ Wk,
                const float* __restrict__ Wv,
                const float* __restrict__ bq, const float* __restrict__ bk,
                const float* __restrict__ bv)
{
    const int mb = blockIdx.y * 128, nb = blockIdx.x * 128;
    if (blockIdx.z == 0)
        gemm_body(q, Wq, bq, g_qp, g_qph, g_qpl, nullptr, nullptr, true, true, false, mb, nb);
    else if (blockIdx.z == 1)
        gemm_body(k, Wk, bk, nullptr, g_kph, g_kpl, nullptr, nullptr, false, true, false, mb, nb);
    else
        gemm_body(v, Wv, bv, nullptr, nullptr, nullptr, g_vth, g_vtl, false, false, true, mb, nb);
}

// K4: final projection. grid = (4, 32).
__global__ __launch_bounds__(256, 1)
void out_kernel(const float* __restrict__ Wo, const float* __restrict__ bo,
                float* __restrict__ out)
{
    gemm_body(g_outpre, Wo, bo, out, nullptr, nullptr, nullptr, nullptr,
              true, false, false, blockIdx.y * 128, blockIdx.x * 128);
}

// ============================================================
// K2: a,b heads. grid = 128, block 256.
// ============================================================
__global__ __launch_bounds__(256)
void ab_kernel(const float* __restrict__ Wa, const float* __restrict__ ba,
               const float* __restrict__ Wb, const float* __restrict__ bb)
{
    __shared__ float4 sWa[512][2];
    __shared__ float4 sWb[512][2];
    const int tid = threadIdx.x;
#pragma unroll
    for (int i = 0; i < 4; i++) {
        int idx = tid + i * 256;
        ((float4*)sWa)[idx] = ((const float4*)Wa)[idx];
        ((float4*)sWb)[idx] = ((const float4*)Wb)[idx];
    }
    __syncthreads();

    const int w = tid >> 5, lane = tid & 31;
    const int rbase = blockIdx.x * 32 + w * 4;

    float acc[4][16];
#pragma unroll
    for (int j = 0; j < 4; j++)
#pragma unroll
        for (int h = 0; h < 16; h++) acc[j][h] = 0.f;

#pragma unroll
    for (int tt = 0; tt < 4; tt++) {
        const int d0 = tt * 128 + lane * 4;
        float4 x[4];
#pragma unroll
        for (int j = 0; j < 4; j++)
            x[j] = *(const float4*)(g_qp + (size_t)(rbase + j) * DMc + d0);
#pragma unroll
        for (int dd = 0; dd < 4; dd++) {
            float4 wa0 = sWa[d0 + dd][0], wa1 = sWa[d0 + dd][1];
            float4 wb0 = sWb[d0 + dd][0], wb1 = sWb[d0 + dd][1];
#pragma unroll
            for (int j = 0; j < 4; j++) {
                float xv = (&x[j].x)[dd];
                acc[j][0]  = fmaf(xv, wa0.x, acc[j][0]);
                acc[j][1]  = fmaf(xv, wa0.y, acc[j][1]);
                acc[j][2]  = fmaf(xv, wa0.z, acc[j][2]);
                acc[j][3]  = fmaf(xv, wa0.w, acc[j][3]);
                acc[j][4]  = fmaf(xv, wa1.x, acc[j][4]);
                acc[j][5]  = fmaf(xv, wa1.y, acc[j][5]);
                acc[j][6]  = fmaf(xv, wa1.z, acc[j][6]);
                acc[j][7]  = fmaf(xv, wa1.w, acc[j][7]);
                acc[j][8]  = fmaf(xv, wb0.x, acc[j][8]);
                acc[j][9]  = fmaf(xv, wb0.y, acc[j][9]);
                acc[j][10] = fmaf(xv, wb0.z, acc[j][10]);
                acc[j][11] = fmaf(xv, wb0.w, acc[j][11]);
                acc[j][12] = fmaf(xv, wb1.x, acc[j][12]);
                acc[j][13] = fmaf(xv, wb1.y, acc[j][13]);
                acc[j][14] = fmaf(xv, wb1.z, acc[j][14]);
                acc[j][15] = fmaf(xv, wb1.w, acc[j][15]);
            }
        }
    }
#pragma unroll
    for (int o = 16; o > 0; o >>= 1)
#pragma unroll
        for (int j = 0; j < 4; j++)
#pragma unroll
            for (int h = 0; h < 16; h++)
                acc[j][h] += __shfl_xor_sync(0xffffffff, acc[j][h], o);

    if (lane < 4) {
        int row = rbase + lane;
        int b = row >> 11, s = row & (Sc - 1);
#pragma unroll
        for (int h = 0; h < 8; h++) {
            g_a[(b * Hc + h) * Sc + s] = acc[lane][h] + ba[h];
            g_b[(b * Hc + h) * Sc + s] = acc[lane][h + 8] + bb[h];
        }
    }
}

// ============================================================
// Fused flash attention with cp.async double-buffered K/V.
// grid = (32 qtile64, 16 bh), block = 256 (8 warps: 4 m16 x 2 k32).
// smem (u32 words):
//   QH[64][36]=2304 @0, QL @2304,
//   KH[2][64][36] @4608, KL[2] @9216, VH[2] @13824, VL[2] @18432,
//   RMT[32][8][16] @23040 .. 27136
// ============================================================
static constexpr int QH_O = 0, QL_O = 2304, KH_O = 4608, KL_O = 9216;
static constexpr int VH_O = 13824, VL_O = 18432, RMT_O = 23040;
static constexpr int RSQ = 36;
static constexpr int TILE_W = 2304;           // words per K/V buffer
static constexpr int FUSE_SMEM = 27136 * 4;   // 108544 B

template<int NROWS>
__device__ __forceinline__ void stage_copy(uint32_t* sm, int offH, int offL,
        const uint32_t* __restrict__ srcH, const uint32_t* __restrict__ srcL,
        size_t rowbase, int tid)
{
    const int row = tid >> 1, half = tid & 1;
    if (row < NROWS) {
        const size_t s0 = rowbase + (size_t)row * (DMc / 2) + half * 16;
        const uint4* sH = (const uint4*)(srcH + s0);
        const uint4* sL = (const uint4*)(srcL + s0);
        uint4* dH = (uint4*)(sm + offH + row * RSQ + half * 16);
        uint4* dL = (uint4*)(sm + offL + row * RSQ + half * 16);
#pragma unroll
        for (int i = 0; i < 4; i++) { dH[i] = sH[i]; dL[i] = sL[i]; }
    }
}

// async stage of one 64-key tile: K rows (seq) + V^T rows (d), hi/lo. 8 cp.async/thread.
__device__ __forceinline__ void stage_async(uint32_t sbase, int buf, int b, int bh, int h,
                                            int kb, int tid)
{
    const int row = tid >> 2;            // 0..63
    const int ch  = (tid & 3) * 2;       // chunk pair: ch, ch+1 (16B each)
    // K (row = key index)
    const uint32_t* kh = g_kph + (size_t)(b * Sc + kb + row) * 256 + h * 32 + ch * 4;
    const uint32_t* kl = g_kpl + (size_t)(b * Sc + kb + row) * 256 + h * 32 + ch * 4;
    uint32_t dkh = sbase + (uint32_t)(KH_O + buf * TILE_W + row * RSQ + ch * 4) * 4;
    uint32_t dkl = sbase + (uint32_t)(KL_O + buf * TILE_W + row * RSQ + ch * 4) * 4;
    cpa16(dkh, kh); cpa16(dkh + 16, kh + 4);
    cpa16(dkl, kl); cpa16(dkl + 16, kl + 4);
    // V^T (row = d index)
    const uint32_t* vh = (const uint32_t*)g_vth + (size_t)(bh * DHc + row) * 1024 + (kb >> 1) + ch * 4;
    const uint32_t* vl = (const uint32_t*)g_vtl + (size_t)(bh * DHc + row) * 1024 + (kb >> 1) + ch * 4;
    uint32_t dvh = sbase + (uint32_t)(VH_O + buf * TILE_W + row * RSQ + ch * 4) * 4;
    uint32_t dvl = sbase + (uint32_t)(VL_O + buf * TILE_W + row * RSQ + ch * 4) * 4;
    cpa16(dvh, vh); cpa16(dvh + 16, vh + 4);
    cpa16(dvl, vl); cpa16(dvl + 16, vl + 4);
}

__global__ __launch_bounds__(256, 2)
void fused_attn_kernel(const float* __restrict__ xdiff, const int* __restrict__ mask,
                       float* __restrict__ attn)
{
    extern __shared__ uint32_t sm[];
    const int tid = threadIdx.x, w = tid >> 5, lane = tid & 31;
    const int g = lane >> 2, t = lane & 3;
    const int bh = blockIdx.y, b = bh >> 3, h = bh & 7;
    const int qb = blockIdx.x * 64;
    const int wm = (w >> 1) * 16, wn = (w & 1) * 32;
    const uint32_t sbase = smem_u32(sm);

    // prefetch tile 0 + stage Q synchronously
    stage_async(sbase, 0, b, bh, h, 0, tid);
    CPA_COMMIT();
    stage_copy<64>(sm, QH_O, QL_O, g_qph, g_qpl,
                   (size_t)(b * Sc + qb) * (DMc / 2) + h * (DHc / 2), tid);

    const int lr0 = wm + g, lr1 = wm + 8 + g;
    float rm0 = -3.0e38f, rm1 = -3.0e38f, rs0 = 0.f, rs1 = 0.f;
    const float aq0 = g_a[bh * Sc + qb + lr0], bq0 = g_b[bh * Sc + qb + lr0];
    const float aq1 = g_a[bh * Sc + qb + lr1], bq1 = g_b[bh * Sc + qb + lr1];
    const float* xr0 = xdiff + ((size_t)b * Sc + qb + lr0) * Sc;
    const float* xr1 = xdiff + ((size_t)b * Sc + qb + lr1) * Sc;
    float* lrow0 = attn + ((size_t)bh * Sc + qb + lr0) * Sc;
    float* lrow1 = attn + ((size_t)bh * Sc + qb + lr1) * Sc;
    const int* mrow = mask + b * Sc;

    float o[8][4];
#pragma unroll
    for (int nf = 0; nf < 8; nf++)
#pragma unroll
        for (int r = 0; r < 4; r++) o[nf][r] = 0.f;

    for (int kt = 0; kt < 32; kt++) {
        const int kb = kt * 64;
        const int cur = kt & 1;
        if (kt < 31) {
            stage_async(sbase, cur ^ 1, b, bh, h, (kt + 1) * 64, tid);
            CPA_COMMIT();
            CPA_WAIT1();
        } else {
            CPA_WAIT0();
        }
        __syncthreads();

        // score MMA: warp 16q x 32keys, c[4][4]
        float c[4][4];
#pragma unroll
        for (int nf = 0; nf < 4; nf++)
#pragma unroll
            for (int r = 0; r < 4; r++) c[nf][r] = 0.f;
        const uint32_t kh_b = sbase + (uint32_t)(KH_O + cur * TILE_W) * 4;
        const uint32_t kl_b = sbase + (uint32_t)(KL_O + cur * TILE_W) * 4;
#pragma unroll
        for (int kk = 0; kk < 4; kk++) {
            uint32_t ah[4], al[4];
            ldsm4(ah, addrA(sbase + QH_O * 4, wm, kk * 16, lane, RSQ));
            ldsm4(al, addrA(sbase + QL_O * 4, wm, kk * 16, lane, RSQ));
#pragma unroll
            for (int nb2 = 0; nb2 < 2; nb2++) {
                uint32_t bhf[4], blf[4];
                ldsm4(bhf, addrB(kh_b, wn + nb2 * 16, kk * 16, lane, RSQ));
                ldsm4(blf, addrB(kl_b, wn + nb2 * 16, kk * 16, lane, RSQ));
                mma16816(c[2 * nb2],     ah, bhf[0], bhf[1]);
                mma16816(c[2 * nb2],     ah, blf[0], blf[1]);
                mma16816(c[2 * nb2],     al, bhf[0], bhf[1]);
                mma16816(c[2 * nb2 + 1], ah, bhf[2], bhf[3]);
                mma16816(c[2 * nb2 + 1], ah, blf[2], blf[3]);
                mma16816(c[2 * nb2 + 1], al, bhf[2], bhf[3]);
            }
        }

        // epilogue: full logits + tile max
        float tm0 = -3.0e38f, tm1 = -3.0e38f;
#pragma unroll
        for (int nf = 0; nf < 4; nf++) {
            int col = kb + wn + nf * 8 + 2 * t;
            int2 mv = *(const int2*)(mrow + col);
            float mt0 = (float)mv.x * -1e9f, mt1 = (float)mv.y * -1e9f;
            float2 x0 = *(const float2*)(xr0 + col);
            float2 x1 = *(const float2*)(xr1 + col);
            c[nf][0] = c[nf][0] * 0.125f + mt0 + aq0 * x0.x + bq0 * x0.x * x0.x;
            c[nf][1] = c[nf][1] * 0.125f + mt1 + aq0 * x0.y + bq0 * x0.y * x0.y;
            c[nf][2] = c[nf][2] * 0.125f + mt0 + aq1 * x1.x + bq1 * x1.x * x1.x;
            c[nf][3] = c[nf][3] * 0.125f + mt1 + aq1 * x1.y + bq1 * x1.y * x1.y;
            tm0 = fmaxf(tm0, fmaxf(c[nf][0], c[nf][1]));
            tm1 = fmaxf(tm1, fmaxf(c[nf][2], c[nf][3]));
        }
        tm0 = fmaxf(tm0, __shfl_xor_sync(0xffffffff, tm0, 1));
        tm0 = fmaxf(tm0, __shfl_xor_sync(0xffffffff, tm0, 2));
        tm1 = fmaxf(tm1, __shfl_xor_sync(0xffffffff, tm1, 1));
        tm1 = fmaxf(tm1, __shfl_xor_sync(0xffffffff, tm1, 2));
        float m0 = fmaxf(rm0, tm0), m1 = fmaxf(rm1, tm1);
        float sc0 = __expf(rm0 - m0), sc1 = __expf(rm1 - m1);
        rs0 *= sc0; rs1 *= sc1;
#pragma unroll
        for (int nf = 0; nf < 8; nf++) {
            o[nf][0] *= sc0; o[nf][1] *= sc0;
            o[nf][2] *= sc1; o[nf][3] *= sc1;
        }
        rm0 = m0; rm1 = m1;
        if (t == 0) {
            float* rmt = (float*)(sm + RMT_O);
            rmt[(kt * 8 + w) * 16 + g]     = rm0;
            rmt[(kt * 8 + w) * 16 + 8 + g] = rm1;
        }

        // P + P@V
        const uint32_t vh_b = sbase + (uint32_t)(VH_O + cur * TILE_W) * 4;
        const uint32_t vl_b = sbase + (uint32_t)(VL_O + cur * TILE_W) * 4;
#pragma unroll
        for (int j = 0; j < 2; j++) {
            uint32_t pah[4], pal[4];
#pragma unroll
            for (int nn = 0; nn < 2; nn++) {
                int nf = 2 * j + nn;
                int col = kb + wn + nf * 8 + 2 * t;
                float p0 = __expf(c[nf][0] - rm0), p1 = __expf(c[nf][1] - rm0);
                float p2 = __expf(c[nf][2] - rm1), p3 = __expf(c[nf][3] - rm1);
                rs0 += p0 + p1; rs1 += p2 + p3;
                *(float2*)(lrow0 + col) = make_float2(p0, p1);
                *(float2*)(lrow1 + col) = make_float2(p2, p3);
                split2(p0, p1, pah[nn * 2 + 0], pal[nn * 2 + 0]);
                split2(p2, p3, pah[nn * 2 + 1], pal[nn * 2 + 1]);
            }
#pragma unroll
            for (int nd = 0; nd < 4; nd++) {
                uint32_t vh[4], vl[4];
                ldsm4(vh, addrB(vh_b, nd * 16, wn + j * 16, lane, RSQ));
                ldsm4(vl, addrB(vl_b, nd * 16, wn + j * 16, lane, RSQ));
                mma16816(o[2 * nd],     pah, vh[0], vh[1]);
                mma16816(o[2 * nd],     pah, vl[0], vl[1]);
                mma16816(o[2 * nd],     pal, vh[0], vh[1]);
                mma16816(o[2 * nd + 1], pah, vh[2], vh[3]);
                mma16816(o[2 * nd + 1], pah, vl[2], vl[3]);
                mma16816(o[2 * nd + 1], pal, vh[2], vh[3]);
            }
        }
        __syncthreads();
    }

    // quad-reduce partial sums
    rs0 += __shfl_xor_sync(0xffffffff, rs0, 1);
    rs0 += __shfl_xor_sync(0xffffffff, rs0, 2);
    rs1 += __shfl_xor_sync(0xffffffff, rs1, 1);
    rs1 += __shfl_xor_sync(0xffffffff, rs1, 2);

    // stats merge across warp halves (k32 pairs)
    float2* sred = (float2*)sm;                       // QH area
    if (t == 0) {
        sred[w * 16 + g]     = make_float2(rm0, rs0);
        sred[w * 16 + 8 + g] = make_float2(rm1, rs1);
    }
    __syncthreads();
    float* mfin = (float*)(sm + QL_O);                // [64]
    float* ifin = mfin + 64;                          // [64]
    if (!(w & 1) && t == 0) {
#pragma unroll
        for (int hh = 0; hh < 2; hh++) {
            int rl = hh * 8 + g;
            float2 A2 = sred[w * 16 + rl], B2 = sred[(w ^ 1) * 16 + rl];
            float mf = fmaxf(A2.x, B2.x);
            float sf = A2.y * __expf(A2.x - mf) + B2.y * __expf(B2.x - mf);
            mfin[wm + rl] = mf;
            ifin[wm + rl] = 1.0f / sf;
        }
    }
    __syncthreads();

    // scale table: rmt -> exp(rmt - m_final) * inv
    {
        float* rmt = (float*)(sm + RMT_O);
        for (int i = tid; i < 4096; i += 256) {
            int ww = (i >> 4) & 7, r = i & 15;
            int row = (ww >> 1) * 16 + r;
            rmt[i] = __expf(rmt[i] - mfin[row]) * ifin[row];
        }
    }
    // o merge across warp halves
    float f0 = __expf(rm0 - mfin[lr0]);
    float f1 = __expf(rm1 - mfin[lr1]);
    float* red = (float*)(sm + KH_O);
    if (w & 1) {
        float* dst = red + ((w >> 1) * 32 + lane) * 33;
#pragma unroll
        for (int nf = 0; nf < 8; nf++) {
            dst[nf * 4 + 0] = o[nf][0] * f0;
            dst[nf * 4 + 1] = o[nf][1] * f0;
            dst[nf * 4 + 2] = o[nf][2] * f1;
            dst[nf * 4 + 3] = o[nf][3] * f1;
        }
    }
    __syncthreads();
    if (!(w & 1)) {
        const float* src = red + ((w >> 1) * 32 + lane) * 33;
        float i0 = ifin[lr0], i1 = ifin[lr1];
        int q0 = qb + lr0, q1 = qb + lr1;
#pragma unroll
        for (int nf = 0; nf < 8; nf++) {
            float v0 = (o[nf][0] * f0 + src[nf * 4 + 0]) * i0;
            float v1 = (o[nf][1] * f0 + src[nf * 4 + 1]) * i0;
            float v2 = (o[nf][2] * f1 + src[nf * 4 + 2]) * i1;
            float v3 = (o[nf][3] * f1 + src[nf * 4 + 3]) * i1;
            *(float2*)(g_outpre + (size_t)(b * Sc + q0) * DMc + h * DHc + nf * 8 + 2 * t) = make_float2(v0, v1);
            *(float2*)(g_outpre + (size_t)(b * Sc + q1) * DMc + h * DHc + nf * 8 + 2 * t) = make_float2(v2, v3);
        }
    }

    // phase 3: normalize attn in place (coalesced)
    const float* rmt = (const float*)(sm + RMT_O);
    const size_t abase = ((size_t)bh * Sc + qb) * Sc;
    for (int i = 0; i < 128; i++) {
        int f4 = i * 256 + tid;
        int row = f4 >> 9;
        int col = (f4 & 511) * 4;
        int tile = col >> 6;
        int half = (col >> 5) & 1;
        int wwr = (row >> 4) * 2 + half;
        float s = rmt[(tile * 8 + wwr) * 16 + (row & 15)];
        float* ptr = attn + abase + (size_t)row * Sc + col;
        float4 P = *(float4*)ptr;
        P.x *= s; P.y *= s; P.z *= s; P.w *= s;
        *(float4*)ptr = P;
    }
}

// ============================================================
extern "C" void kernel_launch(void* const* d_in, const int* in_sizes, int n_in,
                              void* d_out, int out_size)
{
    const float* q     = (const float*)d_in[0];
    const float* k     = (const float*)d_in[1];
    const float* v     = (const float*)d_in[2];
    const float* xdiff = (const float*)d_in[3];
    const int*   mask  = (const int*)d_in[4];
    const float* Wq = (const float*)d_in[5];
    const float* bq = (const float*)d_in[6];
    const float* Wk = (const float*)d_in[7];
    const float* bk = (const float*)d_in[8];
    const float* Wv = (const float*)d_in[9];
    const float* bv = (const float*)d_in[10];
    const float* Wa = (const float*)d_in[11];
    const float* ba = (const float*)d_in[12];
    const float* Wb = (const float*)d_in[13];
    const float* bb = (const float*)d_in[14];
    const float* Wo = (const float*)d_in[15];
    const float* bo = (const float*)d_in[16];

    float* out  = (float*)d_out;                 // (B,S,DM)
    float* attn = out + (size_t)Bc * Sc * DMc;   // (B,H,S,S)

    cudaFuncSetAttribute(fused_attn_kernel, cudaFuncAttributeMaxDynamicSharedMemorySize, FUSE_SMEM);

    qkv_kernel<<<dim3(DMc / 128, Mrows / 128, 3), 256>>>(q, k, v, Wq, Wk, Wv, bq, bk, bv);
    ab_kernel<<<Mrows / 32, 256>>>(Wa, ba, Wb, bb);
    fused_attn_kernel<<<dim3(Sc / 64, BHc), 256, FUSE_SMEM>>>(xdiff, mask, attn);
    out_kernel<<<dim3(DMc / 128, Mrows / 128), 256>>>(Wo, bo, out);
}

// round 13
// speedup vs baseline: 1.2174x; 1.0708x over previous
#include <cuda_runtime.h>
#include <cuda_bf16.h>
#include <cstdint>

// Shapes (fixed by the problem)
static constexpr int Bc  = 2;
static constexpr int Sc  = 2048;
static constexpr int DMc = 512;
static constexpr int Hc  = 8;
static constexpr int DHc = 64;
static constexpr int BHc = Bc * Hc;          // 16
static constexpr int Mrows = Bc * Sc;        // 4096

// -------- device scratch (no allocations allowed) --------
__device__ float g_qp[Mrows * DMc];          // fp32 qp (for ab_kernel)
__device__ float g_outpre[Mrows * DMc];
__device__ float g_a[BHc * Sc];
__device__ float g_b[BHc * Sc];
// prepacked bf16 hi/lo: Q,K row-major packed 2-per-u32; V transposed per head
__device__ __align__(16) uint32_t g_qph[Mrows * DMc / 2];
__device__ __align__(16) uint32_t g_qpl[Mrows * DMc / 2];
__device__ __align__(16) uint32_t g_kph[Mrows * DMc / 2];
__device__ __align__(16) uint32_t g_kpl[Mrows * DMc / 2];
__device__ __align__(16) __nv_bfloat16 g_vth[Mrows * DMc];   // [bh][d][s]
__device__ __align__(16) __nv_bfloat16 g_vtl[Mrows * DMc];

// ==================== warp-mma helpers ====================
__device__ __forceinline__ uint32_t smem_u32(const void* p) {
    uint32_t a;
    asm("{ .reg .u64 t; cvta.to.shared.u64 t, %1; cvt.u32.u64 %0, t; }" : "=r"(a) : "l"(p));
    return a;
}
__device__ __forceinline__ void ldsm4(uint32_t (&r)[4], uint32_t addr) {
    asm volatile("ldmatrix.sync.aligned.m8n8.x4.shared.b16 {%0,%1,%2,%3}, [%4];"
        : "=r"(r[0]), "=r"(r[1]), "=r"(r[2]), "=r"(r[3]) : "r"(addr));
}
__device__ __forceinline__ void mma16816(float (&c)[4], const uint32_t (&a)[4],
                                         uint32_t b0, uint32_t b1) {
    asm volatile(
        "mma.sync.aligned.m16n8k16.row.col.f32.bf16.bf16.f32 "
        "{%0,%1,%2,%3}, {%4,%5,%6,%7}, {%8,%9}, {%0,%1,%2,%3};"
        : "+f"(c[0]), "+f"(c[1]), "+f"(c[2]), "+f"(c[3])
        : "r"(a[0]), "r"(a[1]), "r"(a[2]), "r"(a[3]), "r"(b0), "r"(b1));
}
__device__ __forceinline__ uint32_t addrA(uint32_t base, int r0, int k0, int lane, int stride) {
    return base + (uint32_t)(((r0 + (lane & 15)) * stride + (k0 >> 1) + (lane >> 4) * 4) * 4);
}
__device__ __forceinline__ uint32_t addrB(uint32_t base, int n0, int k0, int lane, int stride) {
    int r = n0 + (lane & 7) + ((lane >> 4) & 1) * 8;
    int c = (k0 >> 1) + ((lane >> 3) & 1) * 4;
    return base + (uint32_t)((r * stride + c) * 4);
}
// fast split: one bf16x2 cvt for hi pair, residual via bit ops, one cvt for lo pair.
__device__ __forceinline__ void split2(float x0, float x1, uint32_t& hi, uint32_t& lo) {
    uint32_t h;
    asm("cvt.rn.bf16x2.f32 %0, %1, %2;" : "=r"(h) : "f"(x1), "f"(x0));
    float f0 = __uint_as_float(h << 16);
    float f1 = __uint_as_float(h & 0xffff0000u);
    float r0 = x0 - f0, r1 = x1 - f1;
    asm("cvt.rn.bf16x2.f32 %0, %1, %2;" : "=r"(lo) : "f"(r1), "f"(r0));
    hi = h;
}
// cp.async helpers
__device__ __forceinline__ void cpa16(uint32_t dst, const void* src) {
    asm volatile("cp.async.cg.shared.global [%0], [%1], 16;" :: "r"(dst), "l"(src));
}
#define CPA_COMMIT() asm volatile("cp.async.commit_group;" ::: "memory")
#define CPA_WAIT1()  asm volatile("cp.async.wait_group 1;" ::: "memory")
#define CPA_WAIT0()  asm volatile("cp.async.wait_group 0;" ::: "memory")

// ============================================================
// GEMM body: C[M,512] = A[M,512] @ W[512,512] + bias  (split precision)
// Software-pipelined: chunk kc+1 global loads overlap chunk kc MMAs.
// ============================================================
__device__ __forceinline__ void gemm_body(
    const float* __restrict__ A, const float* __restrict__ W,
    const float* __restrict__ bias,
    float* __restrict__ C, uint32_t* __restrict__ Hp, uint32_t* __restrict__ Lp,
    __nv_bfloat16* __restrict__ Ht, __nv_bfloat16* __restrict__ Lt,
    bool writeF, bool writeP, bool writeT, int mb, int nb)
{
    __shared__ uint32_t sm[4 * 128 * 20];
    const int ASH = 0, ASL = 2560, BSH = 5120, BSL = 7680, RS = 20;

    const int tid = threadIdx.x;
    const int w = tid >> 5, lane = tid & 31;
    const int g = lane >> 2, t = lane & 3;
    const int wm = (w >> 1) * 32, wn = (w & 1) * 64;
    const uint32_t sbase = smem_u32(sm);

    float c[2][8][4];
#pragma unroll
    for (int mi = 0; mi < 2; mi++)
#pragma unroll
        for (int nf = 0; nf < 8; nf++)
#pragma unroll
            for (int r = 0; r < 4; r++) c[mi][nf][r] = 0.f;

    const int arow_i = tid >> 1, aseg = tid & 1;
    const float* arow = A + (size_t)(mb + arow_i) * DMc;
    const int bn = tid & 127, bkh = tid >> 7;

    // preload chunk 0 into registers
    float4 va[4];
    float w0r[8], w1r[8];
#pragma unroll
    for (int i = 0; i < 4; i++)
        va[i] = *(const float4*)(arow + (aseg * 4 + i) * 4);
#pragma unroll
    for (int i = 0; i < 8; i++) {
        const float* wp = W + (size_t)(2 * (bkh * 8 + i)) * DMc + nb + bn;
        w0r[i] = wp[0]; w1r[i] = wp[DMc];
    }

    for (int kc = 0; kc < 16; kc++) {
        // store current chunk (from regs) to smem
#pragma unroll
        for (int i = 0; i < 4; i++) {
            int f4 = aseg * 4 + i;
            uint32_t h0, l0, h1, l1;
            split2(va[i].x, va[i].y, h0, l0);
            split2(va[i].z, va[i].w, h1, l1);
            sm[ASH + arow_i * RS + f4 * 2]     = h0;
            sm[ASH + arow_i * RS + f4 * 2 + 1] = h1;
            sm[ASL + arow_i * RS + f4 * 2]     = l0;
            sm[ASL + arow_i * RS + f4 * 2 + 1] = l1;
        }
#pragma unroll
        for (int i = 0; i < 8; i++) {
            int kp = bkh * 8 + i;
            uint32_t hi, lo;
            split2(w0r[i], w1r[i], hi, lo);
            sm[BSH + bn * RS + kp] = hi;
            sm[BSL + bn * RS + kp] = lo;
        }
        __syncthreads();

        // issue next-chunk loads (overlap with MMAs below)
        if (kc < 15) {
#pragma unroll
            for (int i = 0; i < 4; i++)
                va[i] = *(const float4*)(arow + (kc + 1) * 32 + (aseg * 4 + i) * 4);
#pragma unroll
            for (int i = 0; i < 8; i++) {
                const float* wp = W + (size_t)((kc + 1) * 32 + 2 * (bkh * 8 + i)) * DMc + nb + bn;
                w0r[i] = wp[0]; w1r[i] = wp[DMc];
            }
        }

#pragma unroll
        for (int kk = 0; kk < 2; kk++) {
            uint32_t ah[2][4], al[2][4];
#pragma unroll
            for (int mi = 0; mi < 2; mi++) {
                ldsm4(ah[mi], addrA(sbase + ASH * 4, wm + mi * 16, kk * 16, lane, RS));
                ldsm4(al[mi], addrA(sbase + ASL * 4, wm + mi * 16, kk * 16, lane, RS));
            }
#pragma unroll
            for (int nb2 = 0; nb2 < 4; nb2++) {
                uint32_t bhf[4], blf[4];
                ldsm4(bhf, addrB(sbase + BSH * 4, wn + nb2 * 16, kk * 16, lane, RS));
                ldsm4(blf, addrB(sbase + BSL * 4, wn + nb2 * 16, kk * 16, lane, RS));
#pragma unroll
                for (int mi = 0; mi < 2; mi++) {
                    mma16816(c[mi][2 * nb2],     ah[mi], bhf[0], bhf[1]);
                    mma16816(c[mi][2 * nb2],     ah[mi], blf[0], blf[1]);
                    mma16816(c[mi][2 * nb2],     al[mi], bhf[0], bhf[1]);
                    mma16816(c[mi][2 * nb2 + 1], ah[mi], bhf[2], bhf[3]);
                    mma16816(c[mi][2 * nb2 + 1], ah[mi], blf[2], blf[3]);
                    mma16816(c[mi][2 * nb2 + 1], al[mi], bhf[2], bhf[3]);
                }
            }
        }
        __syncthreads();
    }

#pragma unroll
    for (int mi = 0; mi < 2; mi++)
#pragma unroll
        for (int hh = 0; hh < 2; hh++) {
            int row = mb + wm + mi * 16 + hh * 8 + g;
#pragma unroll
            for (int nf = 0; nf < 8; nf++) {
                int col = nb + wn + nf * 8 + 2 * t;
                float2 bv = *(const float2*)(bias + col);
                float ox = c[mi][nf][hh * 2 + 0] + bv.x;
                float oy = c[mi][nf][hh * 2 + 1] + bv.y;
                if (writeF)
                    *(float2*)(C + (size_t)row * DMc + col) = make_float2(ox, oy);
                if (writeP) {
                    uint32_t hi, lo;
                    split2(ox, oy, hi, lo);
                    size_t pi = ((size_t)row * DMc + col) >> 1;
                    Hp[pi] = hi;
                    Lp[pi] = lo;
                }
                if (writeT) {
                    uint32_t hi, lo;
                    split2(ox, oy, hi, lo);
                    size_t i0 = ((size_t)(((row >> 11) * Hc + (col >> 6)) * DHc + (col & 63))) * Sc
                              + (row & (Sc - 1));
                    Ht[i0] = __ushort_as_bfloat16((unsigned short)(hi & 0xffff));
                    Lt[i0] = __ushort_as_bfloat16((unsigned short)(lo & 0xffff));
                    Ht[i0 + Sc] = __ushort_as_bfloat16((unsigned short)(hi >> 16));
                    Lt[i0 + Sc] = __ushort_as_bfloat16((unsigned short)(lo >> 16));
                }
            }
        }
}

// K1: fused Q/K/V projections. grid = (4, 32, 3), block 256.
__global__ __launch_bounds__(256, 1)
void qkv_kernel(const float* __restrict__ q, const float* __restrict__ k,
                const float* __restrict__ v,
                const float* __restrict__ Wq, const float* __restrict__ Wk,
                const float* __restrict__ Wv,
                const float* __restrict__ bq, const float* __restrict__ bk,
                const float* __restrict__ bv)
{
    const int mb = blockIdx.y * 128, nb = blockIdx.x * 128;
    if (blockIdx.z == 0)
        gemm_body(q, Wq, bq, g_qp, g_qph, g_qpl, nullptr, nullptr, true, true, false, mb, nb);
    else if (blockIdx.z == 1)
        gemm_body(k, Wk, bk, nullptr, g_kph, g_kpl, nullptr, nullptr, false, true, false, mb, nb);
    else
        gemm_body(v, Wv, bv, nullptr, nullptr, nullptr, g_vth, g_vtl, false, false, true, mb, nb);
}

// K4: final projection. grid = (4, 32).
__global__ __launch_bounds__(256, 1)
void out_kernel(const float* __restrict__ Wo, const float* __restrict__ bo,
                float* __restrict__ out)
{
    gemm_body(g_outpre, Wo, bo, out, nullptr, nullptr, nullptr, nullptr,
              true, false, false, blockIdx.y * 128, blockIdx.x * 128);
}

// ============================================================
// K2: a,b heads. grid = 128, block 256.
// ============================================================
__global__ __launch_bounds__(256)
void ab_kernel(const float* __restrict__ Wa, const float* __restrict__ ba,
               const float* __restrict__ Wb, const float* __restrict__ bb)
{
    __shared__ float4 sWa[512][2];
    __shared__ float4 sWb[512][2];
    const int tid = threadIdx.x;
#pragma unroll
    for (int i = 0; i < 4; i++) {
        int idx = tid + i * 256;
        ((float4*)sWa)[idx] = ((const float4*)Wa)[idx];
        ((float4*)sWb)[idx] = ((const float4*)Wb)[idx];
    }
    __syncthreads();

    const int w = tid >> 5, lane = tid & 31;
    const int rbase = blockIdx.x * 32 + w * 4;

    float acc[4][16];
#pragma unroll
    for (int j = 0; j < 4; j++)
#pragma unroll
        for (int h = 0; h < 16; h++) acc[j][h] = 0.f;

#pragma unroll
    for (int tt = 0; tt < 4; tt++) {
        const int d0 = tt * 128 + lane * 4;
        float4 x[4];
#pragma unroll
        for (int j = 0; j < 4; j++)
            x[j] = *(const float4*)(g_qp + (size_t)(rbase + j) * DMc + d0);
#pragma unroll
        for (int dd = 0; dd < 4; dd++) {
            float4 wa0 = sWa[d0 + dd][0], wa1 = sWa[d0 + dd][1];
            float4 wb0 = sWb[d0 + dd][0], wb1 = sWb[d0 + dd][1];
#pragma unroll
            for (int j = 0; j < 4; j++) {
                float xv = (&x[j].x)[dd];
                acc[j][0]  = fmaf(xv, wa0.x, acc[j][0]);
                acc[j][1]  = fmaf(xv, wa0.y, acc[j][1]);
                acc[j][2]  = fmaf(xv, wa0.z, acc[j][2]);
                acc[j][3]  = fmaf(xv, wa0.w, acc[j][3]);
                acc[j][4]  = fmaf(xv, wa1.x, acc[j][4]);
                acc[j][5]  = fmaf(xv, wa1.y, acc[j][5]);
                acc[j][6]  = fmaf(xv, wa1.z, acc[j][6]);
                acc[j][7]  = fmaf(xv, wa1.w, acc[j][7]);
                acc[j][8]  = fmaf(xv, wb0.x, acc[j][8]);
                acc[j][9]  = fmaf(xv, wb0.y, acc[j][9]);
                acc[j][10] = fmaf(xv, wb0.z, acc[j][10]);
                acc[j][11] = fmaf(xv, wb0.w, acc[j][11]);
                acc[j][12] = fmaf(xv, wb1.x, acc[j][12]);
                acc[j][13] = fmaf(xv, wb1.y, acc[j][13]);
                acc[j][14] = fmaf(xv, wb1.z, acc[j][14]);
                acc[j][15] = fmaf(xv, wb1.w, acc[j][15]);
            }
        }
    }
#pragma unroll
    for (int o = 16; o > 0; o >>= 1)
#pragma unroll
        for (int j = 0; j < 4; j++)
#pragma unroll
            for (int h = 0; h < 16; h++)
                acc[j][h] += __shfl_xor_sync(0xffffffff, acc[j][h], o);

    if (lane < 4) {
        int row = rbase + lane;
        int b = row >> 11, s = row & (Sc - 1);
#pragma unroll
        for (int h = 0; h < 8; h++) {
            g_a[(b * Hc + h) * Sc + s] = acc[lane][h] + ba[h];
            g_b[(b * Hc + h) * Sc + s] = acc[lane][h + 8] + bb[h];
        }
    }
}

// ============================================================
// Fused flash attention with cp.async double-buffered K/V.
// grid = (32 qtile64, 16 bh), block = 256 (8 warps: 4 m16 x 2 k32).
// ============================================================
static constexpr int QH_O = 0, QL_O = 2304, KH_O = 4608, KL_O = 9216;
static constexpr int VH_O = 13824, VL_O = 18432, RMT_O = 23040;
static constexpr int RSQ = 36;
static constexpr int TILE_W = 2304;           // words per K/V buffer
static constexpr int FUSE_SMEM = 27136 * 4;   // 108544 B

template<int NROWS>
__device__ __forceinline__ void stage_copy(uint32_t* sm, int offH, int offL,
        const uint32_t* __restrict__ srcH, const uint32_t* __restrict__ srcL,
        size_t rowbase, int tid)
{
    const int row = tid >> 1, half = tid & 1;
    if (row < NROWS) {
        const size_t s0 = rowbase + (size_t)row * (DMc / 2) + half * 16;
        const uint4* sH = (const uint4*)(srcH + s0);
        const uint4* sL = (const uint4*)(srcL + s0);
        uint4* dH = (uint4*)(sm + offH + row * RSQ + half * 16);
        uint4* dL = (uint4*)(sm + offL + row * RSQ + half * 16);
#pragma unroll
        for (int i = 0; i < 4; i++) { dH[i] = sH[i]; dL[i] = sL[i]; }
    }
}

// async stage of one 64-key tile: K rows (seq) + V^T rows (d), hi/lo. 8 cp.async/thread.
__device__ __forceinline__ void stage_async(uint32_t sbase, int buf, int b, int bh, int h,
                                            int kb, int tid)
{
    const int row = tid >> 2;            // 0..63
    const int ch  = (tid & 3) * 2;       // chunk pair: ch, ch+1 (16B each)
    const uint32_t* kh = g_kph + (size_t)(b * Sc + kb + row) * 256 + h * 32 + ch * 4;
    const uint32_t* kl = g_kpl + (size_t)(b * Sc + kb + row) * 256 + h * 32 + ch * 4;
    uint32_t dkh = sbase + (uint32_t)(KH_O + buf * TILE_W + row * RSQ + ch * 4) * 4;
    uint32_t dkl = sbase + (uint32_t)(KL_O + buf * TILE_W + row * RSQ + ch * 4) * 4;
    cpa16(dkh, kh); cpa16(dkh + 16, kh + 4);
    cpa16(dkl, kl); cpa16(dkl + 16, kl + 4);
    const uint32_t* vh = (const uint32_t*)g_vth + (size_t)(bh * DHc + row) * 1024 + (kb >> 1) + ch * 4;
    const uint32_t* vl = (const uint32_t*)g_vtl + (size_t)(bh * DHc + row) * 1024 + (kb >> 1) + ch * 4;
    uint32_t dvh = sbase + (uint32_t)(VH_O + buf * TILE_W + row * RSQ + ch * 4) * 4;
    uint32_t dvl = sbase + (uint32_t)(VL_O + buf * TILE_W + row * RSQ + ch * 4) * 4;
    cpa16(dvh, vh); cpa16(dvh + 16, vh + 4);
    cpa16(dvl, vl); cpa16(dvl + 16, vl + 4);
}

__global__ __launch_bounds__(256, 2)
void fused_attn_kernel(const float* __restrict__ xdiff, const int* __restrict__ mask,
                       float* __restrict__ attn)
{
    extern __shared__ uint32_t sm[];
    const int tid = threadIdx.x, w = tid >> 5, lane = tid & 31;
    const int g = lane >> 2, t = lane & 3;
    const int bh = blockIdx.y, b = bh >> 3, h = bh & 7;
    const int qb = blockIdx.x * 64;
    const int wm = (w >> 1) * 16, wn = (w & 1) * 32;
    const uint32_t sbase = smem_u32(sm);

    // prefetch tile 0 + stage Q synchronously
    stage_async(sbase, 0, b, bh, h, 0, tid);
    CPA_COMMIT();
    stage_copy<64>(sm, QH_O, QL_O, g_qph, g_qpl,
                   (size_t)(b * Sc + qb) * (DMc / 2) + h * (DHc / 2), tid);

    const int lr0 = wm + g, lr1 = wm + 8 + g;
    float rm0 = -3.0e38f, rm1 = -3.0e38f, rs0 = 0.f, rs1 = 0.f;
    const float aq0 = g_a[bh * Sc + qb + lr0], bq0 = g_b[bh * Sc + qb + lr0];
    const float aq1 = g_a[bh * Sc + qb + lr1], bq1 = g_b[bh * Sc + qb + lr1];
    const float* xr0 = xdiff + ((size_t)b * Sc + qb + lr0) * Sc;
    const float* xr1 = xdiff + ((size_t)b * Sc + qb + lr1) * Sc;
    float* lrow0 = attn + ((size_t)bh * Sc + qb + lr0) * Sc;
    float* lrow1 = attn + ((size_t)bh * Sc + qb + lr1) * Sc;
    const int* mrow = mask + b * Sc;

    float o[8][4];
#pragma unroll
    for (int nf = 0; nf < 8; nf++)
#pragma unroll
        for (int r = 0; r < 4; r++) o[nf][r] = 0.f;

    for (int kt = 0; kt < 32; kt++) {
        const int kb = kt * 64;
        const int cur = kt & 1;
        if (kt < 31) {
            stage_async(sbase, cur ^ 1, b, bh, h, (kt + 1) * 64, tid);
            CPA_COMMIT();
            CPA_WAIT1();
        } else {
            CPA_WAIT0();
        }
        __syncthreads();

        // prefetch epilogue operands (hide behind score MMA)
        int2 mv[4];
        float2 x0v[4], x1v[4];
#pragma unroll
        for (int nf = 0; nf < 4; nf++) {
            int col = kb + wn + nf * 8 + 2 * t;
            mv[nf]  = *(const int2*)(mrow + col);
            x0v[nf] = *(const float2*)(xr0 + col);
            x1v[nf] = *(const float2*)(xr1 + col);
        }

        // score MMA: warp 16q x 32keys, c[4][4]
        float c[4][4];
#pragma unroll
        for (int nf = 0; nf < 4; nf++)
#pragma unroll
            for (int r = 0; r < 4; r++) c[nf][r] = 0.f;
        const uint32_t kh_b = sbase + (uint32_t)(KH_O + cur * TILE_W) * 4;
        const uint32_t kl_b = sbase + (uint32_t)(KL_O + cur * TILE_W) * 4;
#pragma unroll
        for (int kk = 0; kk < 4; kk++) {
            uint32_t ah[4], al[4];
            ldsm4(ah, addrA(sbase + QH_O * 4, wm, kk * 16, lane, RSQ));
            ldsm4(al, addrA(sbase + QL_O * 4, wm, kk * 16, lane, RSQ));
#pragma unroll
            for (int nb2 = 0; nb2 < 2; nb2++) {
                uint32_t bhf[4], blf[4];
                ldsm4(bhf, addrB(kh_b, wn + nb2 * 16, kk * 16, lane, RSQ));
                ldsm4(blf, addrB(kl_b, wn + nb2 * 16, kk * 16, lane, RSQ));
                mma16816(c[2 * nb2],     ah, bhf[0], bhf[1]);
                mma16816(c[2 * nb2],     ah, blf[0], blf[1]);
                mma16816(c[2 * nb2],     al, bhf[0], bhf[1]);
                mma16816(c[2 * nb2 + 1], ah, bhf[2], bhf[3]);
                mma16816(c[2 * nb2 + 1], ah, blf[2], blf[3]);
                mma16816(c[2 * nb2 + 1], al, bhf[2], bhf[3]);
            }
        }

        // epilogue: full logits + tile max
        float tm0 = -3.0e38f, tm1 = -3.0e38f;
#pragma unroll
        for (int nf = 0; nf < 4; nf++) {
            float mt0 = (float)mv[nf].x * -1e9f, mt1 = (float)mv[nf].y * -1e9f;
            float2 x0 = x0v[nf], x1 = x1v[nf];
            c[nf][0] = c[nf][0] * 0.125f + mt0 + aq0 * x0.x + bq0 * x0.x * x0.x;
            c[nf][1] = c[nf][1] * 0.125f + mt1 + aq0 * x0.y + bq0 * x0.y * x0.y;
            c[nf][2] = c[nf][2] * 0.125f + mt0 + aq1 * x1.x + bq1 * x1.x * x1.x;
            c[nf][3] = c[nf][3] * 0.125f + mt1 + aq1 * x1.y + bq1 * x1.y * x1.y;
            tm0 = fmaxf(tm0, fmaxf(c[nf][0], c[nf][1]));
            tm1 = fmaxf(tm1, fmaxf(c[nf][2], c[nf][3]));
        }
        tm0 = fmaxf(tm0, __shfl_xor_sync(0xffffffff, tm0, 1));
        tm0 = fmaxf(tm0, __shfl_xor_sync(0xffffffff, tm0, 2));
        tm1 = fmaxf(tm1, __shfl_xor_sync(0xffffffff, tm1, 1));
        tm1 = fmaxf(tm1, __shfl_xor_sync(0xffffffff, tm1, 2));
        float m0 = fmaxf(rm0, tm0), m1 = fmaxf(rm1, tm1);
        float sc0 = __expf(rm0 - m0), sc1 = __expf(rm1 - m1);
        rs0 *= sc0; rs1 *= sc1;
#pragma unroll
        for (int nf = 0; nf < 8; nf++) {
            o[nf][0] *= sc0; o[nf][1] *= sc0;
            o[nf][2] *= sc1; o[nf][3] *= sc1;
        }
        rm0 = m0; rm1 = m1;
        if (t == 0) {
            float* rmt = (float*)(sm + RMT_O);
            rmt[(kt * 8 + w) * 16 + g]     = rm0;
            rmt[(kt * 8 + w) * 16 + 8 + g] = rm1;
        }

        // P + P@V
        const uint32_t vh_b = sbase + (uint32_t)(VH_O + cur * TILE_W) * 4;
        const uint32_t vl_b = sbase + (uint32_t)(VL_O + cur * TILE_W) * 4;
#pragma unroll
        for (int j = 0; j < 2; j++) {
            uint32_t pah[4], pal[4];
#pragma unroll
            for (int nn = 0; nn < 2; nn++) {
                int nf = 2 * j + nn;
                int col = kb + wn + nf * 8 + 2 * t;
                float p0 = __expf(c[nf][0] - rm0), p1 = __expf(c[nf][1] - rm0);
                float p2 = __expf(c[nf][2] - rm1), p3 = __expf(c[nf][3] - rm1);
                rs0 += p0 + p1; rs1 += p2 + p3;
                *(float2*)(lrow0 + col) = make_float2(p0, p1);
                *(float2*)(lrow1 + col) = make_float2(p2, p3);
                split2(p0, p1, pah[nn * 2 + 0], pal[nn * 2 + 0]);
                split2(p2, p3, pah[nn * 2 + 1], pal[nn * 2 + 1]);
            }
#pragma unroll
            for (int nd = 0; nd < 4; nd++) {
                uint32_t vh[4], vl[4];
                ldsm4(vh, addrB(vh_b, nd * 16, wn + j * 16, lane, RSQ));
                ldsm4(vl, addrB(vl_b, nd * 16, wn + j * 16, lane, RSQ));
                mma16816(o[2 * nd],     pah, vh[0], vh[1]);
                mma16816(o[2 * nd],     pah, vl[0], vl[1]);
                mma16816(o[2 * nd],     pal, vh[0], vh[1]);
                mma16816(o[2 * nd + 1], pah, vh[2], vh[3]);
                mma16816(o[2 * nd + 1], pah, vl[2], vl[3]);
                mma16816(o[2 * nd + 1], pal, vh[2], vh[3]);
            }
        }
        __syncthreads();
    }

    // quad-reduce partial sums
    rs0 += __shfl_xor_sync(0xffffffff, rs0, 1);
    rs0 += __shfl_xor_sync(0xffffffff, rs0, 2);
    rs1 += __shfl_xor_sync(0xffffffff, rs1, 1);
    rs1 += __shfl_xor_sync(0xffffffff, rs1, 2);

    // stats merge across warp halves (k32 pairs)
    float2* sred = (float2*)sm;                       // QH area
    if (t == 0) {
        sred[w * 16 + g]     = make_float2(rm0, rs0);
        sred[w * 16 + 8 + g] = make_float2(rm1, rs1);
    }
    __syncthreads();
    float* mfin = (float*)(sm + QL_O);                // [64]
    float* ifin = mfin + 64;                          // [64]
    if (!(w & 1) && t == 0) {
#pragma unroll
        for (int hh = 0; hh < 2; hh++) {
            int rl = hh * 8 + g;
            float2 A2 = sred[w * 16 + rl], B2 = sred[(w ^ 1) * 16 + rl];
            float mf = fmaxf(A2.x, B2.x);
            float sf = A2.y * __expf(A2.x - mf) + B2.y * __expf(B2.x - mf);
            mfin[wm + rl] = mf;
            ifin[wm + rl] = 1.0f / sf;
        }
    }
    __syncthreads();

    // scale table: rmt -> exp(rmt - m_final) * inv
    {
        float* rmt = (float*)(sm + RMT_O);
        for (int i = tid; i < 4096; i += 256) {
            int ww = (i >> 4) & 7, r = i & 15;
            int row = (ww >> 1) * 16 + r;
            rmt[i] = __expf(rmt[i] - mfin[row]) * ifin[row];
        }
    }
    // o merge across warp halves
    float f0 = __expf(rm0 - mfin[lr0]);
    float f1 = __expf(rm1 - mfin[lr1]);
    float* red = (float*)(sm + KH_O);
    if (w & 1) {
        float* dst = red + ((w >> 1) * 32 + lane) * 33;
#pragma unroll
        for (int nf = 0; nf < 8; nf++) {
            dst[nf * 4 + 0] = o[nf][0] * f0;
            dst[nf * 4 + 1] = o[nf][1] * f0;
            dst[nf * 4 + 2] = o[nf][2] * f1;
            dst[nf * 4 + 3] = o[nf][3] * f1;
        }
    }
    __syncthreads();
    if (!(w & 1)) {
        const float* src = red + ((w >> 1) * 32 + lane) * 33;
        float i0 = ifin[lr0], i1 = ifin[lr1];
        int q0 = qb + lr0, q1 = qb + lr1;
#pragma unroll
        for (int nf = 0; nf < 8; nf++) {
            float v0 = (o[nf][0] * f0 + src[nf * 4 + 0]) * i0;
            float v1 = (o[nf][1] * f0 + src[nf * 4 + 1]) * i0;
            float v2 = (o[nf][2] * f1 + src[nf * 4 + 2]) * i1;
            float v3 = (o[nf][3] * f1 + src[nf * 4 + 3]) * i1;
            *(float2*)(g_outpre + (size_t)(b * Sc + q0) * DMc + h * DHc + nf * 8 + 2 * t) = make_float2(v0, v1);
            *(float2*)(g_outpre + (size_t)(b * Sc + q1) * DMc + h * DHc + nf * 8 + 2 * t) = make_float2(v2, v3);
        }
    }

    // phase 3: normalize attn in place (coalesced, unrolled for MLP)
    const float* rmt = (const float*)(sm + RMT_O);
    const size_t abase = ((size_t)bh * Sc + qb) * Sc;
#pragma unroll 4
    for (int i = 0; i < 128; i++) {
        int f4 = i * 256 + tid;
        int row = f4 >> 9;
        int col = (f4 & 511) * 4;
        int tile = col >> 6;
        int half = (col >> 5) & 1;
        int wwr = (row >> 4) * 2 + half;
        float s = rmt[(tile * 8 + wwr) * 16 + (row & 15)];
        float* ptr = attn + abase + (size_t)row * Sc + col;
        float4 P = *(float4*)ptr;
        P.x *= s; P.y *= s; P.z *= s; P.w *= s;
        *(float4*)ptr = P;
    }
}

// ============================================================
extern "C" void kernel_launch(void* const* d_in, const int* in_sizes, int n_in,
                              void* d_out, int out_size)
{
    const float* q     = (const float*)d_in[0];
    const float* k     = (const float*)d_in[1];
    const float* v     = (const float*)d_in[2];
    const float* xdiff = (const float*)d_in[3];
    const int*   mask  = (const int*)d_in[4];
    const float* Wq = (const float*)d_in[5];
    const float* bq = (const float*)d_in[6];
    const float* Wk = (const float*)d_in[7];
    const float* bk = (const float*)d_in[8];
    const float* Wv = (const float*)d_in[9];
    const float* bv = (const float*)d_in[10];
    const float* Wa = (const float*)d_in[11];
    const float* ba = (const float*)d_in[12];
    const float* Wb = (const float*)d_in[13];
    const float* bb = (const float*)d_in[14];
    const float* Wo = (const float*)d_in[15];
    const float* bo = (const float*)d_in[16];

    float* out  = (float*)d_out;                 // (B,S,DM)
    float* attn = out + (size_t)Bc * Sc * DMc;   // (B,H,S,S)

    cudaFuncSetAttribute(fused_attn_kernel, cudaFuncAttributeMaxDynamicSharedMemorySize, FUSE_SMEM);

    qkv_kernel<<<dim3(DMc / 128, Mrows / 128, 3), 256>>>(q, k, v, Wq, Wk, Wv, bq, bk, bv);
    ab_kernel<<<Mrows / 32, 256>>>(Wa, ba, Wb, bb);
    fused_attn_kernel<<<dim3(Sc / 64, BHc), 256, FUSE_SMEM>>>(xdiff, mask, attn);
    out_kernel<<<dim3(DMc / 128, Mrows / 128), 256>>>(Wo, bo, out);
}

// round 14
// speedup vs baseline: 1.2520x; 1.0285x over previous
#include <cuda_runtime.h>
#include <cuda_bf16.h>
#include <cstdint>

// Shapes (fixed by the problem)
static constexpr int Bc  = 2;
static constexpr int Sc  = 2048;
static constexpr int DMc = 512;
static constexpr int Hc  = 8;
static constexpr int DHc = 64;
static constexpr int BHc = Bc * Hc;          // 16
static constexpr int Mrows = Bc * Sc;        // 4096
static constexpr int IN_SZ = Mrows * 256;    // packed u32 per input plane
static constexpr int W_SZ  = 512 * 256;      // packed u32 per weight plane

// -------- device scratch (no allocations allowed) --------
__device__ float g_qp[Mrows * DMc];          // fp32 qp (for ab_kernel)
__device__ float g_a[BHc * Sc];
__device__ float g_b[BHc * Sc];
// packed bf16 hi/lo operands
__device__ __align__(16) uint32_t g_inh[3 * IN_SZ];   // q,k,v inputs packed
__device__ __align__(16) uint32_t g_inl[3 * IN_SZ];
__device__ __align__(16) uint32_t g_wph[4 * W_SZ];    // Wq,Wk,Wv,Wo packed [n][kp]
__device__ __align__(16) uint32_t g_wpl[4 * W_SZ];
__device__ __align__(16) uint32_t g_oph[IN_SZ];       // attn@V output packed
__device__ __align__(16) uint32_t g_opl[IN_SZ];
__device__ __align__(16) uint32_t g_qph[IN_SZ];       // projected Q/K packed
__device__ __align__(16) uint32_t g_qpl[IN_SZ];
__device__ __align__(16) uint32_t g_kph[IN_SZ];
__device__ __align__(16) uint32_t g_kpl[IN_SZ];
__device__ __align__(16) __nv_bfloat16 g_vth[Mrows * DMc];   // V^T [bh][d][s]
__device__ __align__(16) __nv_bfloat16 g_vtl[Mrows * DMc];

// ==================== helpers ====================
__device__ __forceinline__ uint32_t smem_u32(const void* p) {
    uint32_t a;
    asm("{ .reg .u64 t; cvta.to.shared.u64 t, %1; cvt.u32.u64 %0, t; }" : "=r"(a) : "l"(p));
    return a;
}
__device__ __forceinline__ void ldsm4(uint32_t (&r)[4], uint32_t addr) {
    asm volatile("ldmatrix.sync.aligned.m8n8.x4.shared.b16 {%0,%1,%2,%3}, [%4];"
        : "=r"(r[0]), "=r"(r[1]), "=r"(r[2]), "=r"(r[3]) : "r"(addr));
}
__device__ __forceinline__ void mma16816(float (&c)[4], const uint32_t (&a)[4],
                                         uint32_t b0, uint32_t b1) {
    asm volatile(
        "mma.sync.aligned.m16n8k16.row.col.f32.bf16.bf16.f32 "
        "{%0,%1,%2,%3}, {%4,%5,%6,%7}, {%8,%9}, {%0,%1,%2,%3};"
        : "+f"(c[0]), "+f"(c[1]), "+f"(c[2]), "+f"(c[3])
        : "r"(a[0]), "r"(a[1]), "r"(a[2]), "r"(a[3]), "r"(b0), "r"(b1));
}
__device__ __forceinline__ uint32_t addrA(uint32_t base, int r0, int k0, int lane, int stride) {
    return base + (uint32_t)(((r0 + (lane & 15)) * stride + (k0 >> 1) + (lane >> 4) * 4) * 4);
}
__device__ __forceinline__ uint32_t addrB(uint32_t base, int n0, int k0, int lane, int stride) {
    int r = n0 + (lane & 7) + ((lane >> 4) & 1) * 8;
    int c = (k0 >> 1) + ((lane >> 3) & 1) * 4;
    return base + (uint32_t)((r * stride + c) * 4);
}
__device__ __forceinline__ void split2(float x0, float x1, uint32_t& hi, uint32_t& lo) {
    uint32_t h;
    asm("cvt.rn.bf16x2.f32 %0, %1, %2;" : "=r"(h) : "f"(x1), "f"(x0));
    float f0 = __uint_as_float(h << 16);
    float f1 = __uint_as_float(h & 0xffff0000u);
    float r0 = x0 - f0, r1 = x1 - f1;
    asm("cvt.rn.bf16x2.f32 %0, %1, %2;" : "=r"(lo) : "f"(r1), "f"(r0));
    hi = h;
}
__device__ __forceinline__ void cpa16(uint32_t dst, const void* src) {
    asm volatile("cp.async.cg.shared.global [%0], [%1], 16;" :: "r"(dst), "l"(src));
}
#define CPA_COMMIT() asm volatile("cp.async.commit_group;" ::: "memory")
#define CPA_WAIT1()  asm volatile("cp.async.wait_group 1;" ::: "memory")
#define CPA_WAIT0()  asm volatile("cp.async.wait_group 0;" ::: "memory")

// ============================================================
// Prep kernels: pack operands to bf16 hi/lo once per launch.
// ============================================================
// inputs q,k,v -> [row][kp] packed. grid (2048, 3), block 256.
__global__ __launch_bounds__(256)
void pack_in_kernel(const float* __restrict__ q, const float* __restrict__ k,
                    const float* __restrict__ v)
{
    const float* src = blockIdx.y == 0 ? q : (blockIdx.y == 1 ? k : v);
    uint32_t* H = g_inh + (size_t)blockIdx.y * IN_SZ;
    uint32_t* L = g_inl + (size_t)blockIdx.y * IN_SZ;
    int idx = blockIdx.x * 256 + threadIdx.x;     // one float4 each
    float4 vv = ((const float4*)src)[idx];
    uint32_t h0, l0, h1, l1;
    split2(vv.x, vv.y, h0, l0);
    split2(vv.z, vv.w, h1, l1);
    H[idx * 2] = h0; H[idx * 2 + 1] = h1;
    L[idx * 2] = l0; L[idx * 2 + 1] = l1;
}

// weights -> transposed [n][kp] packed. grid (8 kp-tiles, 16 n-tiles, 4 mats), block 256.
__global__ __launch_bounds__(256)
void pack_w_kernel(const float* __restrict__ Wq, const float* __restrict__ Wk,
                   const float* __restrict__ Wv, const float* __restrict__ Wo)
{
    __shared__ float smw[64][33];
    const float* W = blockIdx.z == 0 ? Wq : (blockIdx.z == 1 ? Wk :
                     (blockIdx.z == 2 ? Wv : Wo));
    uint32_t* H = g_wph + (size_t)blockIdx.z * W_SZ;
    uint32_t* L = g_wpl + (size_t)blockIdx.z * W_SZ;
    const int k0 = blockIdx.x * 64, n0 = blockIdx.y * 32;
    const int t = threadIdx.x;
#pragma unroll
    for (int i = 0; i < 8; i++) {
        int idx = i * 256 + t;
        int kk = idx >> 5, nn = idx & 31;
        smw[kk][nn] = W[(size_t)(k0 + kk) * DMc + n0 + nn];
    }
    __syncthreads();
#pragma unroll
    for (int i = 0; i < 4; i++) {
        int idx = i * 256 + t;
        int n = idx >> 5, kp = idx & 31;
        uint32_t h, l;
        split2(smw[2 * kp][n], smw[2 * kp + 1][n], h, l);
        size_t o = (size_t)(n0 + n) * 256 + (k0 >> 1) + kp;
        H[o] = h; L[o] = l;
    }
}

// ============================================================
// Packed GEMM body: all operands bf16 hi/lo, cp.async double-buffered.
// block 256 (8 warps: 4 m x 2 n), tile 128x128, warp tile 32x64.
// smem: AH[2]/AL[2]/WH[2]/WL[2] of 2560 words each = 81920 B (dynamic).
// ============================================================
static constexpr int GRS = 20;
static constexpr int GA_H = 0, GA_L = 5120, GW_H = 10240, GW_L = 15360;
static constexpr int GEMM_SMEM = 20480 * 4;

__device__ __forceinline__ void gemm_stage(uint32_t sbase, int buf,
        const uint32_t* __restrict__ Ah, const uint32_t* __restrict__ Al,
        const uint32_t* __restrict__ Wh, const uint32_t* __restrict__ Wl,
        int mb, int nb, int kc, int tid)
{
    const int row = tid >> 1, half = tid & 1;
    size_t asrc = (size_t)(mb + row) * 256 + kc * 16 + half * 8;
    uint32_t d = sbase + (uint32_t)(GA_H + buf * 2560 + row * GRS + half * 8) * 4;
    cpa16(d, Ah + asrc); cpa16(d + 16, Ah + asrc + 4);
    d = sbase + (uint32_t)(GA_L + buf * 2560 + row * GRS + half * 8) * 4;
    cpa16(d, Al + asrc); cpa16(d + 16, Al + asrc + 4);
    size_t wsrc = (size_t)(nb + row) * 256 + kc * 16 + half * 8;
    d = sbase + (uint32_t)(GW_H + buf * 2560 + row * GRS + half * 8) * 4;
    cpa16(d, Wh + wsrc); cpa16(d + 16, Wh + wsrc + 4);
    d = sbase + (uint32_t)(GW_L + buf * 2560 + row * GRS + half * 8) * 4;
    cpa16(d, Wl + wsrc); cpa16(d + 16, Wl + wsrc + 4);
}

__device__ __forceinline__ void gemm_body_pk(
    const uint32_t* __restrict__ Ah, const uint32_t* __restrict__ Al,
    const uint32_t* __restrict__ Wh, const uint32_t* __restrict__ Wl,
    const float* __restrict__ bias,
    float* __restrict__ C, uint32_t* __restrict__ Hp, uint32_t* __restrict__ Lp,
    __nv_bfloat16* __restrict__ Ht, __nv_bfloat16* __restrict__ Lt,
    bool writeF, bool writeP, bool writeT, int mb, int nb)
{
    extern __shared__ uint32_t smp[];
    const int tid = threadIdx.x;
    const int w = tid >> 5, lane = tid & 31;
    const int g = lane >> 2, t = lane & 3;
    const int wm = (w >> 1) * 32, wn = (w & 1) * 64;
    const uint32_t sbase = smem_u32(smp);

    float c[2][8][4];
#pragma unroll
    for (int mi = 0; mi < 2; mi++)
#pragma unroll
        for (int nf = 0; nf < 8; nf++)
#pragma unroll
            for (int r = 0; r < 4; r++) c[mi][nf][r] = 0.f;

    gemm_stage(sbase, 0, Ah, Al, Wh, Wl, mb, nb, 0, tid);
    CPA_COMMIT();

    for (int kc = 0; kc < 16; kc++) {
        const int buf = kc & 1;
        if (kc < 15) {
            gemm_stage(sbase, buf ^ 1, Ah, Al, Wh, Wl, mb, nb, kc + 1, tid);
            CPA_COMMIT();
            CPA_WAIT1();
        } else {
            CPA_WAIT0();
        }
        __syncthreads();

        const uint32_t ah_b = sbase + (uint32_t)(GA_H + buf * 2560) * 4;
        const uint32_t al_b = sbase + (uint32_t)(GA_L + buf * 2560) * 4;
        const uint32_t wh_b = sbase + (uint32_t)(GW_H + buf * 2560) * 4;
        const uint32_t wl_b = sbase + (uint32_t)(GW_L + buf * 2560) * 4;
#pragma unroll
        for (int kk = 0; kk < 2; kk++) {
            uint32_t ah[2][4], al[2][4];
#pragma unroll
            for (int mi = 0; mi < 2; mi++) {
                ldsm4(ah[mi], addrA(ah_b, wm + mi * 16, kk * 16, lane, GRS));
                ldsm4(al[mi], addrA(al_b, wm + mi * 16, kk * 16, lane, GRS));
            }
#pragma unroll
            for (int nb2 = 0; nb2 < 4; nb2++) {
                uint32_t bhf[4], blf[4];
                ldsm4(bhf, addrB(wh_b, wn + nb2 * 16, kk * 16, lane, GRS));
                ldsm4(blf, addrB(wl_b, wn + nb2 * 16, kk * 16, lane, GRS));
#pragma unroll
                for (int mi = 0; mi < 2; mi++) {
                    mma16816(c[mi][2 * nb2],     ah[mi], bhf[0], bhf[1]);
                    mma16816(c[mi][2 * nb2],     ah[mi], blf[0], blf[1]);
                    mma16816(c[mi][2 * nb2],     al[mi], bhf[0], bhf[1]);
                    mma16816(c[mi][2 * nb2 + 1], ah[mi], bhf[2], bhf[3]);
                    mma16816(c[mi][2 * nb2 + 1], ah[mi], blf[2], blf[3]);
                    mma16816(c[mi][2 * nb2 + 1], al[mi], bhf[2], bhf[3]);
                }
            }
        }
        __syncthreads();
    }

#pragma unroll
    for (int mi = 0; mi < 2; mi++)
#pragma unroll
        for (int hh = 0; hh < 2; hh++) {
            int row = mb + wm + mi * 16 + hh * 8 + g;
#pragma unroll
            for (int nf = 0; nf < 8; nf++) {
                int col = nb + wn + nf * 8 + 2 * t;
                float2 bv = *(const float2*)(bias + col);
                float ox = c[mi][nf][hh * 2 + 0] + bv.x;
                float oy = c[mi][nf][hh * 2 + 1] + bv.y;
                if (writeF)
                    *(float2*)(C + (size_t)row * DMc + col) = make_float2(ox, oy);
                if (writeP) {
                    uint32_t hi, lo;
                    split2(ox, oy, hi, lo);
                    size_t pi = ((size_t)row * DMc + col) >> 1;
                    Hp[pi] = hi;
                    Lp[pi] = lo;
                }
                if (writeT) {
                    uint32_t hi, lo;
                    split2(ox, oy, hi, lo);
                    size_t i0 = ((size_t)(((row >> 11) * Hc + (col >> 6)) * DHc + (col & 63))) * Sc
                              + (row & (Sc - 1));
                    Ht[i0] = __ushort_as_bfloat16((unsigned short)(hi & 0xffff));
                    Lt[i0] = __ushort_as_bfloat16((unsigned short)(lo & 0xffff));
                    Ht[i0 + Sc] = __ushort_as_bfloat16((unsigned short)(hi >> 16));
                    Lt[i0 + Sc] = __ushort_as_bfloat16((unsigned short)(lo >> 16));
                }
            }
        }
}

// K1: fused Q/K/V projections. grid = (4, 32, 3), block 256.
__global__ __launch_bounds__(256, 2)
void qkv_kernel(const float* __restrict__ bq, const float* __restrict__ bk,
                const float* __restrict__ bv)
{
    const int mb = blockIdx.y * 128, nb = blockIdx.x * 128;
    const int z = blockIdx.z;
    const uint32_t* Ah = g_inh + (size_t)z * IN_SZ;
    const uint32_t* Al = g_inl + (size_t)z * IN_SZ;
    const uint32_t* Wh = g_wph + (size_t)z * W_SZ;
    const uint32_t* Wl = g_wpl + (size_t)z * W_SZ;
    if (z == 0)
        gemm_body_pk(Ah, Al, Wh, Wl, bq, g_qp, g_qph, g_qpl, nullptr, nullptr,
                     true, true, false, mb, nb);
    else if (z == 1)
        gemm_body_pk(Ah, Al, Wh, Wl, bk, nullptr, g_kph, g_kpl, nullptr, nullptr,
                     false, true, false, mb, nb);
    else
        gemm_body_pk(Ah, Al, Wh, Wl, bv, nullptr, nullptr, nullptr, g_vth, g_vtl,
                     false, false, true, mb, nb);
}

// K4: final projection. grid = (4, 32).
__global__ __launch_bounds__(256, 2)
void out_kernel(const float* __restrict__ bo, float* __restrict__ out)
{
    gemm_body_pk(g_oph, g_opl, g_wph + 3 * (size_t)W_SZ, g_wpl + 3 * (size_t)W_SZ,
                 bo, out, nullptr, nullptr, nullptr, nullptr,
                 true, false, false, blockIdx.y * 128, blockIdx.x * 128);
}

// ============================================================
// K2: a,b heads. grid = 128, block 256.
// ============================================================
__global__ __launch_bounds__(256)
void ab_kernel(const float* __restrict__ Wa, const float* __restrict__ ba,
               const float* __restrict__ Wb, const float* __restrict__ bb)
{
    __shared__ float4 sWa[512][2];
    __shared__ float4 sWb[512][2];
    const int tid = threadIdx.x;
#pragma unroll
    for (int i = 0; i < 4; i++) {
        int idx = tid + i * 256;
        ((float4*)sWa)[idx] = ((const float4*)Wa)[idx];
        ((float4*)sWb)[idx] = ((const float4*)Wb)[idx];
    }
    __syncthreads();

    const int w = tid >> 5, lane = tid & 31;
    const int rbase = blockIdx.x * 32 + w * 4;

    float acc[4][16];
#pragma unroll
    for (int j = 0; j < 4; j++)
#pragma unroll
        for (int h = 0; h < 16; h++) acc[j][h] = 0.f;

#pragma unroll
    for (int tt = 0; tt < 4; tt++) {
        const int d0 = tt * 128 + lane * 4;
        float4 x[4];
#pragma unroll
        for (int j = 0; j < 4; j++)
            x[j] = *(const float4*)(g_qp + (size_t)(rbase + j) * DMc + d0);
#pragma unroll
        for (int dd = 0; dd < 4; dd++) {
            float4 wa0 = sWa[d0 + dd][0], wa1 = sWa[d0 + dd][1];
            float4 wb0 = sWb[d0 + dd][0], wb1 = sWb[d0 + dd][1];
#pragma unroll
            for (int j = 0; j < 4; j++) {
                float xv = (&x[j].x)[dd];
                acc[j][0]  = fmaf(xv, wa0.x, acc[j][0]);
                acc[j][1]  = fmaf(xv, wa0.y, acc[j][1]);
                acc[j][2]  = fmaf(xv, wa0.z, acc[j][2]);
                acc[j][3]  = fmaf(xv, wa0.w, acc[j][3]);
                acc[j][4]  = fmaf(xv, wa1.x, acc[j][4]);
                acc[j][5]  = fmaf(xv, wa1.y, acc[j][5]);
                acc[j][6]  = fmaf(xv, wa1.z, acc[j][6]);
                acc[j][7]  = fmaf(xv, wa1.w, acc[j][7]);
                acc[j][8]  = fmaf(xv, wb0.x, acc[j][8]);
                acc[j][9]  = fmaf(xv, wb0.y, acc[j][9]);
                acc[j][10] = fmaf(xv, wb0.z, acc[j][10]);
                acc[j][11] = fmaf(xv, wb0.w, acc[j][11]);
                acc[j][12] = fmaf(xv, wb1.x, acc[j][12]);
                acc[j][13] = fmaf(xv, wb1.y, acc[j][13]);
                acc[j][14] = fmaf(xv, wb1.z, acc[j][14]);
                acc[j][15] = fmaf(xv, wb1.w, acc[j][15]);
            }
        }
    }
#pragma unroll
    for (int o = 16; o > 0; o >>= 1)
#pragma unroll
        for (int j = 0; j < 4; j++)
#pragma unroll
            for (int h = 0; h < 16; h++)
                acc[j][h] += __shfl_xor_sync(0xffffffff, acc[j][h], o);

    if (lane < 4) {
        int row = rbase + lane;
        int b = row >> 11, s = row & (Sc - 1);
#pragma unroll
        for (int h = 0; h < 8; h++) {
            g_a[(b * Hc + h) * Sc + s] = acc[lane][h] + ba[h];
            g_b[(b * Hc + h) * Sc + s] = acc[lane][h + 8] + bb[h];
        }
    }
}

// ============================================================
// Fused flash attention with cp.async double-buffered K/V.
// grid = (32 qtile64, 16 bh), block = 256 (8 warps: 4 m16 x 2 k32).
// ============================================================
static constexpr int QH_O = 0, QL_O = 2304, KH_O = 4608, KL_O = 9216;
static constexpr int VH_O = 13824, VL_O = 18432, RMT_O = 23040;
static constexpr int RSQ = 36;
static constexpr int TILE_W = 2304;
static constexpr int FUSE_SMEM = 27136 * 4;   // 108544 B

template<int NROWS>
__device__ __forceinline__ void stage_copy(uint32_t* sm, int offH, int offL,
        const uint32_t* __restrict__ srcH, const uint32_t* __restrict__ srcL,
        size_t rowbase, int tid)
{
    const int row = tid >> 1, half = tid & 1;
    if (row < NROWS) {
        const size_t s0 = rowbase + (size_t)row * (DMc / 2) + half * 16;
        const uint4* sH = (const uint4*)(srcH + s0);
        const uint4* sL = (const uint4*)(srcL + s0);
        uint4* dH = (uint4*)(sm + offH + row * RSQ + half * 16);
        uint4* dL = (uint4*)(sm + offL + row * RSQ + half * 16);
#pragma unroll
        for (int i = 0; i < 4; i++) { dH[i] = sH[i]; dL[i] = sL[i]; }
    }
}

__device__ __forceinline__ void stage_async(uint32_t sbase, int buf, int b, int bh, int h,
                                            int kb, int tid)
{
    const int row = tid >> 2;
    const int ch  = (tid & 3) * 2;
    const uint32_t* kh = g_kph + (size_t)(b * Sc + kb + row) * 256 + h * 32 + ch * 4;
    const uint32_t* kl = g_kpl + (size_t)(b * Sc + kb + row) * 256 + h * 32 + ch * 4;
    uint32_t dkh = sbase + (uint32_t)(KH_O + buf * TILE_W + row * RSQ + ch * 4) * 4;
    uint32_t dkl = sbase + (uint32_t)(KL_O + buf * TILE_W + row * RSQ + ch * 4) * 4;
    cpa16(dkh, kh); cpa16(dkh + 16, kh + 4);
    cpa16(dkl, kl); cpa16(dkl + 16, kl + 4);
    const uint32_t* vh = (const uint32_t*)g_vth + (size_t)(bh * DHc + row) * 1024 + (kb >> 1) + ch * 4;
    const uint32_t* vl = (const uint32_t*)g_vtl + (size_t)(bh * DHc + row) * 1024 + (kb >> 1) + ch * 4;
    uint32_t dvh = sbase + (uint32_t)(VH_O + buf * TILE_W + row * RSQ + ch * 4) * 4;
    uint32_t dvl = sbase + (uint32_t)(VL_O + buf * TILE_W + row * RSQ + ch * 4) * 4;
    cpa16(dvh, vh); cpa16(dvh + 16, vh + 4);
    cpa16(dvl, vl); cpa16(dvl + 16, vl + 4);
}

__global__ __launch_bounds__(256, 2)
void fused_attn_kernel(const float* __restrict__ xdiff, const int* __restrict__ mask,
                       float* __restrict__ attn)
{
    extern __shared__ uint32_t sm[];
    const int tid = threadIdx.x, w = tid >> 5, lane = tid & 31;
    const int g = lane >> 2, t = lane & 3;
    const int bh = blockIdx.y, b = bh >> 3, h = bh & 7;
    const int qb = blockIdx.x * 64;
    const int wm = (w >> 1) * 16, wn = (w & 1) * 32;
    const uint32_t sbase = smem_u32(sm);

    stage_async(sbase, 0, b, bh, h, 0, tid);
    CPA_COMMIT();
    stage_copy<64>(sm, QH_O, QL_O, g_qph, g_qpl,
                   (size_t)(b * Sc + qb) * (DMc / 2) + h * (DHc / 2), tid);

    const int lr0 = wm + g, lr1 = wm + 8 + g;
    float rm0 = -3.0e38f, rm1 = -3.0e38f, rs0 = 0.f, rs1 = 0.f;
    const float aq0 = g_a[bh * Sc + qb + lr0], bq0 = g_b[bh * Sc + qb + lr0];
    const float aq1 = g_a[bh * Sc + qb + lr1], bq1 = g_b[bh * Sc + qb + lr1];
    const float* xr0 = xdiff + ((size_t)b * Sc + qb + lr0) * Sc;
    const float* xr1 = xdiff + ((size_t)b * Sc + qb + lr1) * Sc;
    float* lrow0 = attn + ((size_t)bh * Sc + qb + lr0) * Sc;
    float* lrow1 = attn + ((size_t)bh * Sc + qb + lr1) * Sc;
    const int* mrow = mask + b * Sc;

    float o[8][4];
#pragma unroll
    for (int nf = 0; nf < 8; nf++)
#pragma unroll
        for (int r = 0; r < 4; r++) o[nf][r] = 0.f;

    for (int kt = 0; kt < 32; kt++) {
        const int kb = kt * 64;
        const int cur = kt & 1;
        if (kt < 31) {
            stage_async(sbase, cur ^ 1, b, bh, h, (kt + 1) * 64, tid);
            CPA_COMMIT();
            CPA_WAIT1();
        } else {
            CPA_WAIT0();
        }
        __syncthreads();

        int2 mv[4];
        float2 x0v[4], x1v[4];
#pragma unroll
        for (int nf = 0; nf < 4; nf++) {
            int col = kb + wn + nf * 8 + 2 * t;
            mv[nf]  = *(const int2*)(mrow + col);
            x0v[nf] = *(const float2*)(xr0 + col);
            x1v[nf] = *(const float2*)(xr1 + col);
        }

        float c[4][4];
#pragma unroll
        for (int nf = 0; nf < 4; nf++)
#pragma unroll
            for (int r = 0; r < 4; r++) c[nf][r] = 0.f;
        const uint32_t kh_b = sbase + (uint32_t)(KH_O + cur * TILE_W) * 4;
        const uint32_t kl_b = sbase + (uint32_t)(KL_O + cur * TILE_W) * 4;
#pragma unroll
        for (int kk = 0; kk < 4; kk++) {
            uint32_t ah[4], al[4];
            ldsm4(ah, addrA(sbase + QH_O * 4, wm, kk * 16, lane, RSQ));
            ldsm4(al, addrA(sbase + QL_O * 4, wm, kk * 16, lane, RSQ));
#pragma unroll
            for (int nb2 = 0; nb2 < 2; nb2++) {
                uint32_t bhf[4], blf[4];
                ldsm4(bhf, addrB(kh_b, wn + nb2 * 16, kk * 16, lane, RSQ));
                ldsm4(blf, addrB(kl_b, wn + nb2 * 16, kk * 16, lane, RSQ));
                mma16816(c[2 * nb2],     ah, bhf[0], bhf[1]);
                mma16816(c[2 * nb2],     ah, blf[0], blf[1]);
                mma16816(c[2 * nb2],     al, bhf[0], bhf[1]);
                mma16816(c[2 * nb2 + 1], ah, bhf[2], bhf[3]);
                mma16816(c[2 * nb2 + 1], ah, blf[2], blf[3]);
                mma16816(c[2 * nb2 + 1], al, bhf[2], bhf[3]);
            }
        }

        float tm0 = -3.0e38f, tm1 = -3.0e38f;
#pragma unroll
        for (int nf = 0; nf < 4; nf++) {
            float mt0 = (float)mv[nf].x * -1e9f, mt1 = (float)mv[nf].y * -1e9f;
            float2 x0 = x0v[nf], x1 = x1v[nf];
            c[nf][0] = c[nf][0] * 0.125f + mt0 + aq0 * x0.x + bq0 * x0.x * x0.x;
            c[nf][1] = c[nf][1] * 0.125f + mt1 + aq0 * x0.y + bq0 * x0.y * x0.y;
            c[nf][2] = c[nf][2] * 0.125f + mt0 + aq1 * x1.x + bq1 * x1.x * x1.x;
            c[nf][3] = c[nf][3] * 0.125f + mt1 + aq1 * x1.y + bq1 * x1.y * x1.y;
            tm0 = fmaxf(tm0, fmaxf(c[nf][0], c[nf][1]));
            tm1 = fmaxf(tm1, fmaxf(c[nf][2], c[nf][3]));
        }
        tm0 = fmaxf(tm0, __shfl_xor_sync(0xffffffff, tm0, 1));
        tm0 = fmaxf(tm0, __shfl_xor_sync(0xffffffff, tm0, 2));
        tm1 = fmaxf(tm1, __shfl_xor_sync(0xffffffff, tm1, 1));
        tm1 = fmaxf(tm1, __shfl_xor_sync(0xffffffff, tm1, 2));
        float m0 = fmaxf(rm0, tm0), m1 = fmaxf(rm1, tm1);
        float sc0 = __expf(rm0 - m0), sc1 = __expf(rm1 - m1);
        rs0 *= sc0; rs1 *= sc1;
#pragma unroll
        for (int nf = 0; nf < 8; nf++) {
            o[nf][0] *= sc0; o[nf][1] *= sc0;
            o[nf][2] *= sc1; o[nf][3] *= sc1;
        }
        rm0 = m0; rm1 = m1;
        if (t == 0) {
            float* rmt = (float*)(sm + RMT_O);
            rmt[(kt * 8 + w) * 16 + g]     = rm0;
            rmt[(kt * 8 + w) * 16 + 8 + g] = rm1;
        }

        const uint32_t vh_b = sbase + (uint32_t)(VH_O + cur * TILE_W) * 4;
        const uint32_t vl_b = sbase + (uint32_t)(VL_O + cur * TILE_W) * 4;
#pragma unroll
        for (int j = 0; j < 2; j++) {
            uint32_t pah[4], pal[4];
#pragma unroll
            for (int nn = 0; nn < 2; nn++) {
                int nf = 2 * j + nn;
                int col = kb + wn + nf * 8 + 2 * t;
                float p0 = __expf(c[nf][0] - rm0), p1 = __expf(c[nf][1] - rm0);
                float p2 = __expf(c[nf][2] - rm1), p3 = __expf(c[nf][3] - rm1);
                rs0 += p0 + p1; rs1 += p2 + p3;
                *(float2*)(lrow0 + col) = make_float2(p0, p1);
                *(float2*)(lrow1 + col) = make_float2(p2, p3);
                split2(p0, p1, pah[nn * 2 + 0], pal[nn * 2 + 0]);
                split2(p2, p3, pah[nn * 2 + 1], pal[nn * 2 + 1]);
            }
#pragma unroll
            for (int nd = 0; nd < 4; nd++) {
                uint32_t vh[4], vl[4];
                ldsm4(vh, addrB(vh_b, nd * 16, wn + j * 16, lane, RSQ));
                ldsm4(vl, addrB(vl_b, nd * 16, wn + j * 16, lane, RSQ));
                mma16816(o[2 * nd],     pah, vh[0], vh[1]);
                mma16816(o[2 * nd],     pah, vl[0], vl[1]);
                mma16816(o[2 * nd],     pal, vh[0], vh[1]);
                mma16816(o[2 * nd + 1], pah, vh[2], vh[3]);
                mma16816(o[2 * nd + 1], pah, vl[2], vl[3]);
                mma16816(o[2 * nd + 1], pal, vh[2], vh[3]);
            }
        }
        __syncthreads();
    }

    rs0 += __shfl_xor_sync(0xffffffff, rs0, 1);
    rs0 += __shfl_xor_sync(0xffffffff, rs0, 2);
    rs1 += __shfl_xor_sync(0xffffffff, rs1, 1);
    rs1 += __shfl_xor_sync(0xffffffff, rs1, 2);

    float2* sred = (float2*)sm;
    if (t == 0) {
        sred[w * 16 + g]     = make_float2(rm0, rs0);
        sred[w * 16 + 8 + g] = make_float2(rm1, rs1);
    }
    __syncthreads();
    float* mfin = (float*)(sm + QL_O);
    float* ifin = mfin + 64;
    if (!(w & 1) && t == 0) {
#pragma unroll
        for (int hh = 0; hh < 2; hh++) {
            int rl = hh * 8 + g;
            float2 A2 = sred[w * 16 + rl], B2 = sred[(w ^ 1) * 16 + rl];
            float mf = fmaxf(A2.x, B2.x);
            float sf = A2.y * __expf(A2.x - mf) + B2.y * __expf(B2.x - mf);
            mfin[wm + rl] = mf;
            ifin[wm + rl] = 1.0f / sf;
        }
    }
    __syncthreads();

    {
        float* rmt = (float*)(sm + RMT_O);
        for (int i = tid; i < 4096; i += 256) {
            int ww = (i >> 4) & 7, r = i & 15;
            int row = (ww >> 1) * 16 + r;
            rmt[i] = __expf(rmt[i] - mfin[row]) * ifin[row];
        }
    }
    float f0 = __expf(rm0 - mfin[lr0]);
    float f1 = __expf(rm1 - mfin[lr1]);
    float* red = (float*)(sm + KH_O);
    if (w & 1) {
        float* dst = red + ((w >> 1) * 32 + lane) * 33;
#pragma unroll
        for (int nf = 0; nf < 8; nf++) {
            dst[nf * 4 + 0] = o[nf][0] * f0;
            dst[nf * 4 + 1] = o[nf][1] * f0;
            dst[nf * 4 + 2] = o[nf][2] * f1;
            dst[nf * 4 + 3] = o[nf][3] * f1;
        }
    }
    __syncthreads();
    if (!(w & 1)) {
        const float* src = red + ((w >> 1) * 32 + lane) * 33;
        float i0 = ifin[lr0], i1 = ifin[lr1];
        int q0 = qb + lr0, q1 = qb + lr1;
#pragma unroll
        for (int nf = 0; nf < 8; nf++) {
            float v0 = (o[nf][0] * f0 + src[nf * 4 + 0]) * i0;
            float v1 = (o[nf][1] * f0 + src[nf * 4 + 1]) * i0;
            float v2 = (o[nf][2] * f1 + src[nf * 4 + 2]) * i1;
            float v3 = (o[nf][3] * f1 + src[nf * 4 + 3]) * i1;
            // write packed hi/lo for the out-projection
            uint32_t h0, l0, h1, l1;
            split2(v0, v1, h0, l0);
            split2(v2, v3, h1, l1);
            size_t pi0 = (size_t)(b * Sc + q0) * 256 + h * 32 + nf * 4 + t;
            size_t pi1 = (size_t)(b * Sc + q1) * 256 + h * 32 + nf * 4 + t;
            g_oph[pi0] = h0; g_opl[pi0] = l0;
            g_oph[pi1] = h1; g_opl[pi1] = l1;
        }
    }

    // phase 3: normalize attn in place (coalesced)
    const float* rmt = (const float*)(sm + RMT_O);
    const size_t abase = ((size_t)bh * Sc + qb) * Sc;
#pragma unroll 4
    for (int i = 0; i < 128; i++) {
        int f4 = i * 256 + tid;
        int row = f4 >> 9;
        int col = (f4 & 511) * 4;
        int tile = col >> 6;
        int half = (col >> 5) & 1;
        int wwr = (row >> 4) * 2 + half;
        float s = rmt[(tile * 8 + wwr) * 16 + (row & 15)];
        float* ptr = attn + abase + (size_t)row * Sc + col;
        float4 P = *(float4*)ptr;
        P.x *= s; P.y *= s; P.z *= s; P.w *= s;
        *(float4*)ptr = P;
    }
}

// ============================================================
extern "C" void kernel_launch(void* const* d_in, const int* in_sizes, int n_in,
                              void* d_out, int out_size)
{
    const float* q     = (const float*)d_in[0];
    const float* k     = (const float*)d_in[1];
    const float* v     = (const float*)d_in[2];
    const float* xdiff = (const float*)d_in[3];
    const int*   mask  = (const int*)d_in[4];
    const float* Wq = (const float*)d_in[5];
    const float* bq = (const float*)d_in[6];
    const float* Wk = (const float*)d_in[7];
    const float* bk = (const float*)d_in[8];
    const float* Wv = (const float*)d_in[9];
    const float* bv = (const float*)d_in[10];
    const float* Wa = (const float*)d_in[11];
    const float* ba = (const float*)d_in[12];
    const float* Wb = (const float*)d_in[13];
    const float* bb = (const float*)d_in[14];
    const float* Wo = (const float*)d_in[15];
    const float* bo = (const float*)d_in[16];

    float* out  = (float*)d_out;                 // (B,S,DM)
    float* attn = out + (size_t)Bc * Sc * DMc;   // (B,H,S,S)

    cudaFuncSetAttribute(fused_attn_kernel, cudaFuncAttributeMaxDynamicSharedMemorySize, FUSE_SMEM);
    cudaFuncSetAttribute(qkv_kernel, cudaFuncAttributeMaxDynamicSharedMemorySize, GEMM_SMEM);
    cudaFuncSetAttribute(out_kernel, cudaFuncAttributeMaxDynamicSharedMemorySize, GEMM_SMEM);

    pack_w_kernel<<<dim3(8, 16, 4), 256>>>(Wq, Wk, Wv, Wo);
    pack_in_kernel<<<dim3(2048, 3), 256>>>(q, k, v);
    qkv_kernel<<<dim3(DMc / 128, Mrows / 128, 3), 256, GEMM_SMEM>>>(bq, bk, bv);
    ab_kernel<<<Mrows / 32, 256>>>(Wa, ba, Wb, bb);
    fused_attn_kernel<<<dim3(Sc / 64, BHc), 256, FUSE_SMEM>>>(xdiff, mask, attn);
    out_kernel<<<dim3(DMc / 128, Mrows / 128), 256, GEMM_SMEM>>>(bo, out);
}

// round 15
// speedup vs baseline: 1.4093x; 1.1256x over previous
#include <cuda_runtime.h>
#include <cuda_bf16.h>
#include <cstdint>

// Shapes (fixed by the problem)
static constexpr int Bc  = 2;
static constexpr int Sc  = 2048;
static constexpr int DMc = 512;
static constexpr int Hc  = 8;
static constexpr int DHc = 64;
static constexpr int BHc = Bc * Hc;          // 16
static constexpr int Mrows = Bc * Sc;        // 4096
static constexpr int IN_SZ = Mrows * 256;    // packed u32 per input plane
static constexpr int W_SZ  = 512 * 256;      // packed u32 per weight plane

// -------- device scratch (no allocations allowed) --------
__device__ float g_qp[Mrows * DMc];          // fp32 qp (for ab_kernel)
__device__ float g_a[BHc * Sc];
__device__ float g_b[BHc * Sc];
// packed bf16 hi/lo operands
__device__ __align__(16) uint32_t g_inh[3 * IN_SZ];   // q,k,v inputs packed
__device__ __align__(16) uint32_t g_inl[3 * IN_SZ];
__device__ __align__(16) uint32_t g_wph[4 * W_SZ];    // Wq,Wk,Wv,Wo packed [n][kp]
__device__ __align__(16) uint32_t g_wpl[4 * W_SZ];
__device__ __align__(16) uint32_t g_oph[IN_SZ];       // attn@V output packed
__device__ __align__(16) uint32_t g_opl[IN_SZ];
__device__ __align__(16) uint32_t g_qph[IN_SZ];       // projected Q/K packed
__device__ __align__(16) uint32_t g_qpl[IN_SZ];
__device__ __align__(16) uint32_t g_kph[IN_SZ];
__device__ __align__(16) uint32_t g_kpl[IN_SZ];
__device__ __align__(16) __nv_bfloat16 g_vth[Mrows * DMc];   // V^T [bh][d][s]
__device__ __align__(16) __nv_bfloat16 g_vtl[Mrows * DMc];

// ==================== helpers ====================
__device__ __forceinline__ uint32_t smem_u32(const void* p) {
    uint32_t a;
    asm("{ .reg .u64 t; cvta.to.shared.u64 t, %1; cvt.u32.u64 %0, t; }" : "=r"(a) : "l"(p));
    return a;
}
__device__ __forceinline__ void ldsm4(uint32_t (&r)[4], uint32_t addr) {
    asm volatile("ldmatrix.sync.aligned.m8n8.x4.shared.b16 {%0,%1,%2,%3}, [%4];"
        : "=r"(r[0]), "=r"(r[1]), "=r"(r[2]), "=r"(r[3]) : "r"(addr));
}
__device__ __forceinline__ void mma16816(float (&c)[4], const uint32_t (&a)[4],
                                         uint32_t b0, uint32_t b1) {
    asm volatile(
        "mma.sync.aligned.m16n8k16.row.col.f32.bf16.bf16.f32 "
        "{%0,%1,%2,%3}, {%4,%5,%6,%7}, {%8,%9}, {%0,%1,%2,%3};"
        : "+f"(c[0]), "+f"(c[1]), "+f"(c[2]), "+f"(c[3])
        : "r"(a[0]), "r"(a[1]), "r"(a[2]), "r"(a[3]), "r"(b0), "r"(b1));
}
__device__ __forceinline__ uint32_t addrA(uint32_t base, int r0, int k0, int lane, int stride) {
    return base + (uint32_t)(((r0 + (lane & 15)) * stride + (k0 >> 1) + (lane >> 4) * 4) * 4);
}
__device__ __forceinline__ uint32_t addrB(uint32_t base, int n0, int k0, int lane, int stride) {
    int r = n0 + (lane & 7) + ((lane >> 4) & 1) * 8;
    int c = (k0 >> 1) + ((lane >> 3) & 1) * 4;
    return base + (uint32_t)((r * stride + c) * 4);
}
__device__ __forceinline__ void split2(float x0, float x1, uint32_t& hi, uint32_t& lo) {
    uint32_t h;
    asm("cvt.rn.bf16x2.f32 %0, %1, %2;" : "=r"(h) : "f"(x1), "f"(x0));
    float f0 = __uint_as_float(h << 16);
    float f1 = __uint_as_float(h & 0xffff0000u);
    float r0 = x0 - f0, r1 = x1 - f1;
    asm("cvt.rn.bf16x2.f32 %0, %1, %2;" : "=r"(lo) : "f"(r1), "f"(r0));
    hi = h;
}
__device__ __forceinline__ void cpa16(uint32_t dst, const void* src) {
    asm volatile("cp.async.cg.shared.global [%0], [%1], 16;" :: "r"(dst), "l"(src));
}
#define CPA_COMMIT() asm volatile("cp.async.commit_group;" ::: "memory")
#define CPA_WAIT1()  asm volatile("cp.async.wait_group 1;" ::: "memory")
#define CPA_WAIT0()  asm volatile("cp.async.wait_group 0;" ::: "memory")

// ============================================================
// Prep kernels
// ============================================================
__global__ __launch_bounds__(256)
void pack_in_kernel(const float* __restrict__ q, const float* __restrict__ k,
                    const float* __restrict__ v)
{
    const float* src = blockIdx.y == 0 ? q : (blockIdx.y == 1 ? k : v);
    uint32_t* H = g_inh + (size_t)blockIdx.y * IN_SZ;
    uint32_t* L = g_inl + (size_t)blockIdx.y * IN_SZ;
    int idx = blockIdx.x * 256 + threadIdx.x;
    float4 vv = ((const float4*)src)[idx];
    uint32_t h0, l0, h1, l1;
    split2(vv.x, vv.y, h0, l0);
    split2(vv.z, vv.w, h1, l1);
    H[idx * 2] = h0; H[idx * 2 + 1] = h1;
    L[idx * 2] = l0; L[idx * 2 + 1] = l1;
}

__global__ __launch_bounds__(256)
void pack_w_kernel(const float* __restrict__ Wq, const float* __restrict__ Wk,
                   const float* __restrict__ Wv, const float* __restrict__ Wo)
{
    __shared__ float smw[64][33];
    const float* W = blockIdx.z == 0 ? Wq : (blockIdx.z == 1 ? Wk :
                     (blockIdx.z == 2 ? Wv : Wo));
    uint32_t* H = g_wph + (size_t)blockIdx.z * W_SZ;
    uint32_t* L = g_wpl + (size_t)blockIdx.z * W_SZ;
    const int k0 = blockIdx.x * 64, n0 = blockIdx.y * 32;
    const int t = threadIdx.x;
#pragma unroll
    for (int i = 0; i < 8; i++) {
        int idx = i * 256 + t;
        int kk = idx >> 5, nn = idx & 31;
        smw[kk][nn] = W[(size_t)(k0 + kk) * DMc + n0 + nn];
    }
    __syncthreads();
#pragma unroll
    for (int i = 0; i < 4; i++) {
        int idx = i * 256 + t;
        int n = idx >> 5, kp = idx & 31;
        uint32_t h, l;
        split2(smw[2 * kp][n], smw[2 * kp + 1][n], h, l);
        size_t o = (size_t)(n0 + n) * 256 + (k0 >> 1) + kp;
        H[o] = h; L[o] = l;
    }
}

// ============================================================
// Packed GEMM body: cp.async double-buffered.
// ============================================================
static constexpr int GRS = 20;
static constexpr int GA_H = 0, GA_L = 5120, GW_H = 10240, GW_L = 15360;
static constexpr int GEMM_SMEM = 20480 * 4;

__device__ __forceinline__ void gemm_stage(uint32_t sbase, int buf,
        const uint32_t* __restrict__ Ah, const uint32_t* __restrict__ Al,
        const uint32_t* __restrict__ Wh, const uint32_t* __restrict__ Wl,
        int mb, int nb, int kc, int tid)
{
    const int row = tid >> 1, half = tid & 1;
    size_t asrc = (size_t)(mb + row) * 256 + kc * 16 + half * 8;
    uint32_t d = sbase + (uint32_t)(GA_H + buf * 2560 + row * GRS + half * 8) * 4;
    cpa16(d, Ah + asrc); cpa16(d + 16, Ah + asrc + 4);
    d = sbase + (uint32_t)(GA_L + buf * 2560 + row * GRS + half * 8) * 4;
    cpa16(d, Al + asrc); cpa16(d + 16, Al + asrc + 4);
    size_t wsrc = (size_t)(nb + row) * 256 + kc * 16 + half * 8;
    d = sbase + (uint32_t)(GW_H + buf * 2560 + row * GRS + half * 8) * 4;
    cpa16(d, Wh + wsrc); cpa16(d + 16, Wh + wsrc + 4);
    d = sbase + (uint32_t)(GW_L + buf * 2560 + row * GRS + half * 8) * 4;
    cpa16(d, Wl + wsrc); cpa16(d + 16, Wl + wsrc + 4);
}

__device__ __forceinline__ void gemm_body_pk(
    const uint32_t* __restrict__ Ah, const uint32_t* __restrict__ Al,
    const uint32_t* __restrict__ Wh, const uint32_t* __restrict__ Wl,
    const float* __restrict__ bias,
    float* __restrict__ C, uint32_t* __restrict__ Hp, uint32_t* __restrict__ Lp,
    __nv_bfloat16* __restrict__ Ht, __nv_bfloat16* __restrict__ Lt,
    bool writeF, bool writeP, bool writeT, int mb, int nb)
{
    extern __shared__ uint32_t smp[];
    const int tid = threadIdx.x;
    const int w = tid >> 5, lane = tid & 31;
    const int g = lane >> 2, t = lane & 3;
    const int wm = (w >> 1) * 32, wn = (w & 1) * 64;
    const uint32_t sbase = smem_u32(smp);

    float c[2][8][4];
#pragma unroll
    for (int mi = 0; mi < 2; mi++)
#pragma unroll
        for (int nf = 0; nf < 8; nf++)
#pragma unroll
            for (int r = 0; r < 4; r++) c[mi][nf][r] = 0.f;

    gemm_stage(sbase, 0, Ah, Al, Wh, Wl, mb, nb, 0, tid);
    CPA_COMMIT();

    for (int kc = 0; kc < 16; kc++) {
        const int buf = kc & 1;
        if (kc < 15) {
            gemm_stage(sbase, buf ^ 1, Ah, Al, Wh, Wl, mb, nb, kc + 1, tid);
            CPA_COMMIT();
            CPA_WAIT1();
        } else {
            CPA_WAIT0();
        }
        __syncthreads();

        const uint32_t ah_b = sbase + (uint32_t)(GA_H + buf * 2560) * 4;
        const uint32_t al_b = sbase + (uint32_t)(GA_L + buf * 2560) * 4;
        const uint32_t wh_b = sbase + (uint32_t)(GW_H + buf * 2560) * 4;
        const uint32_t wl_b = sbase + (uint32_t)(GW_L + buf * 2560) * 4;
#pragma unroll
        for (int kk = 0; kk < 2; kk++) {
            uint32_t ah[2][4], al[2][4];
#pragma unroll
            for (int mi = 0; mi < 2; mi++) {
                ldsm4(ah[mi], addrA(ah_b, wm + mi * 16, kk * 16, lane, GRS));
                ldsm4(al[mi], addrA(al_b, wm + mi * 16, kk * 16, lane, GRS));
            }
#pragma unroll
            for (int nb2 = 0; nb2 < 4; nb2++) {
                uint32_t bhf[4], blf[4];
                ldsm4(bhf, addrB(wh_b, wn + nb2 * 16, kk * 16, lane, GRS));
                ldsm4(blf, addrB(wl_b, wn + nb2 * 16, kk * 16, lane, GRS));
#pragma unroll
                for (int mi = 0; mi < 2; mi++) {
                    mma16816(c[mi][2 * nb2],     ah[mi], bhf[0], bhf[1]);
                    mma16816(c[mi][2 * nb2],     ah[mi], blf[0], blf[1]);
                    mma16816(c[mi][2 * nb2],     al[mi], bhf[0], bhf[1]);
                    mma16816(c[mi][2 * nb2 + 1], ah[mi], bhf[2], bhf[3]);
                    mma16816(c[mi][2 * nb2 + 1], ah[mi], blf[2], blf[3]);
                    mma16816(c[mi][2 * nb2 + 1], al[mi], bhf[2], bhf[3]);
                }
            }
        }
        __syncthreads();
    }

#pragma unroll
    for (int mi = 0; mi < 2; mi++)
#pragma unroll
        for (int hh = 0; hh < 2; hh++) {
            int row = mb + wm + mi * 16 + hh * 8 + g;
#pragma unroll
            for (int nf = 0; nf < 8; nf++) {
                int col = nb + wn + nf * 8 + 2 * t;
                float2 bv = *(const float2*)(bias + col);
                float ox = c[mi][nf][hh * 2 + 0] + bv.x;
                float oy = c[mi][nf][hh * 2 + 1] + bv.y;
                if (writeF)
                    *(float2*)(C + (size_t)row * DMc + col) = make_float2(ox, oy);
                if (writeP) {
                    uint32_t hi, lo;
                    split2(ox, oy, hi, lo);
                    size_t pi = ((size_t)row * DMc + col) >> 1;
                    Hp[pi] = hi;
                    Lp[pi] = lo;
                }
                if (writeT) {
                    uint32_t hi, lo;
                    split2(ox, oy, hi, lo);
                    size_t i0 = ((size_t)(((row >> 11) * Hc + (col >> 6)) * DHc + (col & 63))) * Sc
                              + (row & (Sc - 1));
                    Ht[i0] = __ushort_as_bfloat16((unsigned short)(hi & 0xffff));
                    Lt[i0] = __ushort_as_bfloat16((unsigned short)(lo & 0xffff));
                    Ht[i0 + Sc] = __ushort_as_bfloat16((unsigned short)(hi >> 16));
                    Lt[i0 + Sc] = __ushort_as_bfloat16((unsigned short)(lo >> 16));
                }
            }
        }
}

// K1: fused Q/K/V projections. grid = (4, 32, 3), block 256.
__global__ __launch_bounds__(256, 2)
void qkv_kernel(const float* __restrict__ bq, const float* __restrict__ bk,
                const float* __restrict__ bv)
{
    const int mb = blockIdx.y * 128, nb = blockIdx.x * 128;
    const int z = blockIdx.z;
    const uint32_t* Ah = g_inh + (size_t)z * IN_SZ;
    const uint32_t* Al = g_inl + (size_t)z * IN_SZ;
    const uint32_t* Wh = g_wph + (size_t)z * W_SZ;
    const uint32_t* Wl = g_wpl + (size_t)z * W_SZ;
    if (z == 0)
        gemm_body_pk(Ah, Al, Wh, Wl, bq, g_qp, g_qph, g_qpl, nullptr, nullptr,
                     true, true, false, mb, nb);
    else if (z == 1)
        gemm_body_pk(Ah, Al, Wh, Wl, bk, nullptr, g_kph, g_kpl, nullptr, nullptr,
                     false, true, false, mb, nb);
    else
        gemm_body_pk(Ah, Al, Wh, Wl, bv, nullptr, nullptr, nullptr, g_vth, g_vtl,
                     false, false, true, mb, nb);
}

// K4: final projection. grid = (4, 32).
__global__ __launch_bounds__(256, 2)
void out_kernel(const float* __restrict__ bo, float* __restrict__ out)
{
    gemm_body_pk(g_oph, g_opl, g_wph + 3 * (size_t)W_SZ, g_wpl + 3 * (size_t)W_SZ,
                 bo, out, nullptr, nullptr, nullptr, nullptr,
                 true, false, false, blockIdx.y * 128, blockIdx.x * 128);
}

// ============================================================
// K2: a,b heads. grid = 256, block 256, warp handles 2 rows.
// ============================================================
__global__ __launch_bounds__(256)
void ab_kernel(const float* __restrict__ Wa, const float* __restrict__ ba,
               const float* __restrict__ Wb, const float* __restrict__ bb)
{
    __shared__ float4 sWa[512][2];
    __shared__ float4 sWb[512][2];
    const int tid = threadIdx.x;
#pragma unroll
    for (int i = 0; i < 4; i++) {
        int idx = tid + i * 256;
        ((float4*)sWa)[idx] = ((const float4*)Wa)[idx];
        ((float4*)sWb)[idx] = ((const float4*)Wb)[idx];
    }
    __syncthreads();

    const int w = tid >> 5, lane = tid & 31;
    const int rbase = blockIdx.x * 16 + w * 2;

    float acc[2][16];
#pragma unroll
    for (int j = 0; j < 2; j++)
#pragma unroll
        for (int h = 0; h < 16; h++) acc[j][h] = 0.f;

#pragma unroll
    for (int tt = 0; tt < 4; tt++) {
        const int d0 = tt * 128 + lane * 4;
        float4 x[2];
#pragma unroll
        for (int j = 0; j < 2; j++)
            x[j] = *(const float4*)(g_qp + (size_t)(rbase + j) * DMc + d0);
#pragma unroll
        for (int dd = 0; dd < 4; dd++) {
            float4 wa0 = sWa[d0 + dd][0], wa1 = sWa[d0 + dd][1];
            float4 wb0 = sWb[d0 + dd][0], wb1 = sWb[d0 + dd][1];
#pragma unroll
            for (int j = 0; j < 2; j++) {
                float xv = (&x[j].x)[dd];
                acc[j][0]  = fmaf(xv, wa0.x, acc[j][0]);
                acc[j][1]  = fmaf(xv, wa0.y, acc[j][1]);
                acc[j][2]  = fmaf(xv, wa0.z, acc[j][2]);
                acc[j][3]  = fmaf(xv, wa0.w, acc[j][3]);
                acc[j][4]  = fmaf(xv, wa1.x, acc[j][4]);
                acc[j][5]  = fmaf(xv, wa1.y, acc[j][5]);
                acc[j][6]  = fmaf(xv, wa1.z, acc[j][6]);
                acc[j][7]  = fmaf(xv, wa1.w, acc[j][7]);
                acc[j][8]  = fmaf(xv, wb0.x, acc[j][8]);
                acc[j][9]  = fmaf(xv, wb0.y, acc[j][9]);
                acc[j][10] = fmaf(xv, wb0.z, acc[j][10]);
                acc[j][11] = fmaf(xv, wb0.w, acc[j][11]);
                acc[j][12] = fmaf(xv, wb1.x, acc[j][12]);
                acc[j][13] = fmaf(xv, wb1.y, acc[j][13]);
                acc[j][14] = fmaf(xv, wb1.z, acc[j][14]);
                acc[j][15] = fmaf(xv, wb1.w, acc[j][15]);
            }
        }
    }
#pragma unroll
    for (int o = 16; o > 0; o >>= 1)
#pragma unroll
        for (int j = 0; j < 2; j++)
#pragma unroll
            for (int h = 0; h < 16; h++)
                acc[j][h] += __shfl_xor_sync(0xffffffff, acc[j][h], o);

    if (lane < 2) {
        int row = rbase + lane;
        int b = row >> 11, s = row & (Sc - 1);
#pragma unroll
        for (int h = 0; h < 8; h++) {
            g_a[(b * Hc + h) * Sc + s] = acc[lane][h] + ba[h];
            g_b[(b * Hc + h) * Sc + s] = acc[lane][h + 8] + bb[h];
        }
    }
}

// ============================================================
// Fused flash attention. grid = (16 qtile128, 16 bh), block = 512
// (16 warps: 8 m16-groups x 2 k32-halves). cp.async double-buffered K/V.
// smem (u32 words): QH[128][36]@0, QL@4608, KH[2]@9216, KL[2]@13824,
//                   VH[2]@18432, VL[2]@23040, RMT[32][16][16]@27648
// ============================================================
static constexpr int QH_O = 0, QL_O = 4608, KH_O = 9216, KL_O = 13824;
static constexpr int VH_O = 18432, VL_O = 23040, RMT_O = 27648;
static constexpr int RSQ = 36;
static constexpr int TILE_W = 2304;
static constexpr int FUSE_SMEM = 35840 * 4;   // 143360 B

// Q stage: 128 rows x 32 words (hi/lo), 512 threads, 8 words each.
__device__ __forceinline__ void stage_q(uint32_t* sm,
        const uint32_t* __restrict__ srcH, const uint32_t* __restrict__ srcL,
        size_t rowbase, int tid)
{
    const int row = tid >> 2, q4 = tid & 3;
    const size_t s0 = rowbase + (size_t)row * 256 + q4 * 8;
    const uint4* sH = (const uint4*)(srcH + s0);
    const uint4* sL = (const uint4*)(srcL + s0);
    uint4* dH = (uint4*)(sm + QH_O + row * RSQ + q4 * 8);
    uint4* dL = (uint4*)(sm + QL_O + row * RSQ + q4 * 8);
    dH[0] = sH[0]; dH[1] = sH[1];
    dL[0] = sL[0]; dL[1] = sL[1];
}

// async stage of one 64-key tile (K + V^T hi/lo). 4 cp.async/thread (512 thr).
__device__ __forceinline__ void stage_async(uint32_t sbase, int buf, int b, int bh, int h,
                                            int kb, int tid)
{
    const int row = tid >> 3;            // 0..63
    const int ch  = tid & 7;             // 16B chunk index
    const uint32_t* kh = g_kph + (size_t)(b * Sc + kb + row) * 256 + h * 32 + ch * 4;
    const uint32_t* kl = g_kpl + (size_t)(b * Sc + kb + row) * 256 + h * 32 + ch * 4;
    cpa16(sbase + (uint32_t)(KH_O + buf * TILE_W + row * RSQ + ch * 4) * 4, kh);
    cpa16(sbase + (uint32_t)(KL_O + buf * TILE_W + row * RSQ + ch * 4) * 4, kl);
    const uint32_t* vh = (const uint32_t*)g_vth + (size_t)(bh * DHc + row) * 1024 + (kb >> 1) + ch * 4;
    const uint32_t* vl = (const uint32_t*)g_vtl + (size_t)(bh * DHc + row) * 1024 + (kb >> 1) + ch * 4;
    cpa16(sbase + (uint32_t)(VH_O + buf * TILE_W + row * RSQ + ch * 4) * 4, vh);
    cpa16(sbase + (uint32_t)(VL_O + buf * TILE_W + row * RSQ + ch * 4) * 4, vl);
}

__global__ __launch_bounds__(512, 1)
void fused_attn_kernel(const float* __restrict__ xdiff, const int* __restrict__ mask,
                       float* __restrict__ attn)
{
    extern __shared__ uint32_t sm[];
    const int tid = threadIdx.x, w = tid >> 5, lane = tid & 31;
    const int g = lane >> 2, t = lane & 3;
    const int bh = blockIdx.y, b = bh >> 3, h = bh & 7;
    const int qb = blockIdx.x * 128;
    const int wm = (w >> 1) * 16, wn = (w & 1) * 32;
    const uint32_t sbase = smem_u32(sm);

    stage_async(sbase, 0, b, bh, h, 0, tid);
    CPA_COMMIT();
    stage_q(sm, g_qph, g_qpl, (size_t)(b * Sc + qb) * 256 + h * 32, tid);

    const int lr0 = wm + g, lr1 = wm + 8 + g;
    float rm0 = -3.0e38f, rm1 = -3.0e38f, rs0 = 0.f, rs1 = 0.f;
    const float aq0 = g_a[bh * Sc + qb + lr0], bq0 = g_b[bh * Sc + qb + lr0];
    const float aq1 = g_a[bh * Sc + qb + lr1], bq1 = g_b[bh * Sc + qb + lr1];
    const float* xr0 = xdiff + ((size_t)b * Sc + qb + lr0) * Sc;
    const float* xr1 = xdiff + ((size_t)b * Sc + qb + lr1) * Sc;
    float* lrow0 = attn + ((size_t)bh * Sc + qb + lr0) * Sc;
    float* lrow1 = attn + ((size_t)bh * Sc + qb + lr1) * Sc;
    const int* mrow = mask + b * Sc;

    float o[8][4];
#pragma unroll
    for (int nf = 0; nf < 8; nf++)
#pragma unroll
        for (int r = 0; r < 4; r++) o[nf][r] = 0.f;

    for (int kt = 0; kt < 32; kt++) {
        const int kb = kt * 64;
        const int cur = kt & 1;
        if (kt < 31) {
            stage_async(sbase, cur ^ 1, b, bh, h, (kt + 1) * 64, tid);
            CPA_COMMIT();
            CPA_WAIT1();
        } else {
            CPA_WAIT0();
        }
        __syncthreads();

        int2 mv[4];
        float2 x0v[4], x1v[4];
#pragma unroll
        for (int nf = 0; nf < 4; nf++) {
            int col = kb + wn + nf * 8 + 2 * t;
            mv[nf]  = *(const int2*)(mrow + col);
            x0v[nf] = *(const float2*)(xr0 + col);
            x1v[nf] = *(const float2*)(xr1 + col);
        }

        float c[4][4];
#pragma unroll
        for (int nf = 0; nf < 4; nf++)
#pragma unroll
            for (int r = 0; r < 4; r++) c[nf][r] = 0.f;
        const uint32_t kh_b = sbase + (uint32_t)(KH_O + cur * TILE_W) * 4;
        const uint32_t kl_b = sbase + (uint32_t)(KL_O + cur * TILE_W) * 4;
#pragma unroll
        for (int kk = 0; kk < 4; kk++) {
            uint32_t ah[4], al[4];
            ldsm4(ah, addrA(sbase + QH_O * 4, wm, kk * 16, lane, RSQ));
            ldsm4(al, addrA(sbase + QL_O * 4, wm, kk * 16, lane, RSQ));
#pragma unroll
            for (int nb2 = 0; nb2 < 2; nb2++) {
                uint32_t bhf[4], blf[4];
                ldsm4(bhf, addrB(kh_b, wn + nb2 * 16, kk * 16, lane, RSQ));
                ldsm4(blf, addrB(kl_b, wn + nb2 * 16, kk * 16, lane, RSQ));
                mma16816(c[2 * nb2],     ah, bhf[0], bhf[1]);
                mma16816(c[2 * nb2],     ah, blf[0], blf[1]);
                mma16816(c[2 * nb2],     al, bhf[0], bhf[1]);
                mma16816(c[2 * nb2 + 1], ah, bhf[2], bhf[3]);
                mma16816(c[2 * nb2 + 1], ah, blf[2], blf[3]);
                mma16816(c[2 * nb2 + 1], al, bhf[2], bhf[3]);
            }
        }

        float tm0 = -3.0e38f, tm1 = -3.0e38f;
#pragma unroll
        for (int nf = 0; nf < 4; nf++) {
            float mt0 = (float)mv[nf].x * -1e9f, mt1 = (float)mv[nf].y * -1e9f;
            float2 x0 = x0v[nf], x1 = x1v[nf];
            c[nf][0] = c[nf][0] * 0.125f + mt0 + aq0 * x0.x + bq0 * x0.x * x0.x;
            c[nf][1] = c[nf][1] * 0.125f + mt1 + aq0 * x0.y + bq0 * x0.y * x0.y;
            c[nf][2] = c[nf][2] * 0.125f + mt0 + aq1 * x1.x + bq1 * x1.x * x1.x;
            c[nf][3] = c[nf][3] * 0.125f + mt1 + aq1 * x1.y + bq1 * x1.y * x1.y;
            tm0 = fmaxf(tm0, fmaxf(c[nf][0], c[nf][1]));
            tm1 = fmaxf(tm1, fmaxf(c[nf][2], c[nf][3]));
        }
        tm0 = fmaxf(tm0, __shfl_xor_sync(0xffffffff, tm0, 1));
        tm0 = fmaxf(tm0, __shfl_xor_sync(0xffffffff, tm0, 2));
        tm1 = fmaxf(tm1, __shfl_xor_sync(0xffffffff, tm1, 1));
        tm1 = fmaxf(tm1, __shfl_xor_sync(0xffffffff, tm1, 2));
        float m0 = fmaxf(rm0, tm0), m1 = fmaxf(rm1, tm1);
        float sc0 = __expf(rm0 - m0), sc1 = __expf(rm1 - m1);
        rs0 *= sc0; rs1 *= sc1;
#pragma unroll
        for (int nf = 0; nf < 8; nf++) {
            o[nf][0] *= sc0; o[nf][1] *= sc0;
            o[nf][2] *= sc1; o[nf][3] *= sc1;
        }
        rm0 = m0; rm1 = m1;
        if (t == 0) {
            float* rmt = (float*)(sm + RMT_O);
            rmt[(kt * 16 + w) * 16 + g]     = rm0;
            rmt[(kt * 16 + w) * 16 + 8 + g] = rm1;
        }

        const uint32_t vh_b = sbase + (uint32_t)(VH_O + cur * TILE_W) * 4;
        const uint32_t vl_b = sbase + (uint32_t)(VL_O + cur * TILE_W) * 4;
#pragma unroll
        for (int j = 0; j < 2; j++) {
            uint32_t pah[4], pal[4];
#pragma unroll
            for (int nn = 0; nn < 2; nn++) {
                int nf = 2 * j + nn;
                int col = kb + wn + nf * 8 + 2 * t;
                float p0 = __expf(c[nf][0] - rm0), p1 = __expf(c[nf][1] - rm0);
                float p2 = __expf(c[nf][2] - rm1), p3 = __expf(c[nf][3] - rm1);
                rs0 += p0 + p1; rs1 += p2 + p3;
                *(float2*)(lrow0 + col) = make_float2(p0, p1);
                *(float2*)(lrow1 + col) = make_float2(p2, p3);
                split2(p0, p1, pah[nn * 2 + 0], pal[nn * 2 + 0]);
                split2(p2, p3, pah[nn * 2 + 1], pal[nn * 2 + 1]);
            }
#pragma unroll
            for (int nd = 0; nd < 4; nd++) {
                uint32_t vh[4], vl[4];
                ldsm4(vh, addrB(vh_b, nd * 16, wn + j * 16, lane, RSQ));
                ldsm4(vl, addrB(vl_b, nd * 16, wn + j * 16, lane, RSQ));
                mma16816(o[2 * nd],     pah, vh[0], vh[1]);
                mma16816(o[2 * nd],     pah, vl[0], vl[1]);
                mma16816(o[2 * nd],     pal, vh[0], vh[1]);
                mma16816(o[2 * nd + 1], pah, vh[2], vh[3]);
                mma16816(o[2 * nd + 1], pah, vl[2], vl[3]);
                mma16816(o[2 * nd + 1], pal, vh[2], vh[3]);
            }
        }
        __syncthreads();
    }

    rs0 += __shfl_xor_sync(0xffffffff, rs0, 1);
    rs0 += __shfl_xor_sync(0xffffffff, rs0, 2);
    rs1 += __shfl_xor_sync(0xffffffff, rs1, 1);
    rs1 += __shfl_xor_sync(0xffffffff, rs1, 2);

    // stats merge across warp k-half pairs
    float2* sred = (float2*)sm;                       // QH area
    if (t == 0) {
        sred[w * 16 + g]     = make_float2(rm0, rs0);
        sred[w * 16 + 8 + g] = make_float2(rm1, rs1);
    }
    __syncthreads();
    float* mfin = (float*)(sm + QL_O);                // [128]
    float* ifin = mfin + 128;                         // [128]
    if (!(w & 1) && t == 0) {
#pragma unroll
        for (int hh = 0; hh < 2; hh++) {
            int rl = hh * 8 + g;
            float2 A2 = sred[w * 16 + rl], B2 = sred[(w ^ 1) * 16 + rl];
            float mf = fmaxf(A2.x, B2.x);
            float sf = A2.y * __expf(A2.x - mf) + B2.y * __expf(B2.x - mf);
            mfin[wm + rl] = mf;
            ifin[wm + rl] = 1.0f / sf;
        }
    }
    __syncthreads();

    // scale table: rmt -> exp(rmt - m_final) * inv
    {
        float* rmt = (float*)(sm + RMT_O);
        for (int i = tid; i < 8192; i += 512) {
            int ww = (i >> 4) & 15, r = i & 15;
            int row = (ww >> 1) * 16 + r;
            rmt[i] = __expf(rmt[i] - mfin[row]) * ifin[row];
        }
    }
    // o merge across warp k-half pairs
    float f0 = __expf(rm0 - mfin[lr0]);
    float f1 = __expf(rm1 - mfin[lr1]);
    float* red = (float*)(sm + KH_O);
    if (w & 1) {
        float* dst = red + ((w >> 1) * 32 + lane) * 33;
#pragma unroll
        for (int nf = 0; nf < 8; nf++) {
            dst[nf * 4 + 0] = o[nf][0] * f0;
            dst[nf * 4 + 1] = o[nf][1] * f0;
            dst[nf * 4 + 2] = o[nf][2] * f1;
            dst[nf * 4 + 3] = o[nf][3] * f1;
        }
    }
    __syncthreads();
    if (!(w & 1)) {
        const float* src = red + ((w >> 1) * 32 + lane) * 33;
        float i0 = ifin[lr0], i1 = ifin[lr1];
        int q0 = qb + lr0, q1 = qb + lr1;
#pragma unroll
        for (int nf = 0; nf < 8; nf++) {
            float v0 = (o[nf][0] * f0 + src[nf * 4 + 0]) * i0;
            float v1 = (o[nf][1] * f0 + src[nf * 4 + 1]) * i0;
            float v2 = (o[nf][2] * f1 + src[nf * 4 + 2]) * i1;
            float v3 = (o[nf][3] * f1 + src[nf * 4 + 3]) * i1;
            uint32_t h0, l0, h1, l1;
            split2(v0, v1, h0, l0);
            split2(v2, v3, h1, l1);
            size_t pi0 = (size_t)(b * Sc + q0) * 256 + h * 32 + nf * 4 + t;
            size_t pi1 = (size_t)(b * Sc + q1) * 256 + h * 32 + nf * 4 + t;
            g_oph[pi0] = h0; g_opl[pi0] = l0;
            g_oph[pi1] = h1; g_opl[pi1] = l1;
        }
    }

    // phase 3: normalize attn in place (coalesced)
    const float* rmt = (const float*)(sm + RMT_O);
    const size_t abase = ((size_t)bh * Sc + qb) * Sc;
#pragma unroll 4
    for (int i = 0; i < 128; i++) {
        int f4 = i * 512 + tid;
        int row = f4 >> 9;
        int col = (f4 & 511) * 4;
        int tile = col >> 6;
        int half = (col >> 5) & 1;
        int wwr = (row >> 4) * 2 + half;
        float s = rmt[(tile * 16 + wwr) * 16 + (row & 15)];
        float* ptr = attn + abase + (size_t)row * Sc + col;
        float4 P = *(float4*)ptr;
        P.x *= s; P.y *= s; P.z *= s; P.w *= s;
        *(float4*)ptr = P;
    }
}

// ============================================================
extern "C" void kernel_launch(void* const* d_in, const int* in_sizes, int n_in,
                              void* d_out, int out_size)
{
    const float* q     = (const float*)d_in[0];
    const float* k     = (const float*)d_in[1];
    const float* v     = (const float*)d_in[2];
    const float* xdiff = (const float*)d_in[3];
    const int*   mask  = (const int*)d_in[4];
    const float* Wq = (const float*)d_in[5];
    const float* bq = (const float*)d_in[6];
    const float* Wk = (const float*)d_in[7];
    const float* bk = (const float*)d_in[8];
    const float* Wv = (const float*)d_in[9];
    const float* bv = (const float*)d_in[10];
    const float* Wa = (const float*)d_in[11];
    const float* ba = (const float*)d_in[12];
    const float* Wb = (const float*)d_in[13];
    const float* bb = (const float*)d_in[14];
    const float* Wo = (const float*)d_in[15];
    const float* bo = (const float*)d_in[16];

    float* out  = (float*)d_out;                 // (B,S,DM)
    float* attn = out + (size_t)Bc * Sc * DMc;   // (B,H,S,S)

    cudaFuncSetAttribute(fused_attn_kernel, cudaFuncAttributeMaxDynamicSharedMemorySize, FUSE_SMEM);
    cudaFuncSetAttribute(qkv_kernel, cudaFuncAttributeMaxDynamicSharedMemorySize, GEMM_SMEM);
    cudaFuncSetAttribute(out_kernel, cudaFuncAttributeMaxDynamicSharedMemorySize, GEMM_SMEM);

    pack_w_kernel<<<dim3(8, 16, 4), 256>>>(Wq, Wk, Wv, Wo);
    pack_in_kernel<<<dim3(2048, 3), 256>>>(q, k, v);
    qkv_kernel<<<dim3(DMc / 128, Mrows / 128, 3), 256, GEMM_SMEM>>>(bq, bk, bv);
    ab_kernel<<<Mrows / 16, 256>>>(Wa, ba, Wb, bb);
    fused_attn_kernel<<<dim3(Sc / 128, BHc), 512, FUSE_SMEM>>>(xdiff, mask, attn);
    out_kernel<<<dim3(DMc / 128, Mrows / 128), 256, GEMM_SMEM>>>(bo, out);
}

// round 16
// speedup vs baseline: 1.4332x; 1.0169x over previous
#include <cuda_runtime.h>
#include <cuda_bf16.h>
#include <cstdint>

// Shapes (fixed by the problem)
static constexpr int Bc  = 2;
static constexpr int Sc  = 2048;
static constexpr int DMc = 512;
static constexpr int Hc  = 8;
static constexpr int DHc = 64;
static constexpr int BHc = Bc * Hc;          // 16
static constexpr int Mrows = Bc * Sc;        // 4096
static constexpr int IN_SZ = Mrows * 256;    // packed u32 per input plane
static constexpr int W_SZ  = 512 * 256;      // packed u32 per weight plane

// -------- device scratch (no allocations allowed) --------
__device__ float g_a[BHc * Sc];
__device__ float g_b[BHc * Sc];
// packed bf16 hi/lo operands
__device__ __align__(16) uint32_t g_inh[3 * IN_SZ];   // q,k,v inputs packed
__device__ __align__(16) uint32_t g_inl[3 * IN_SZ];
__device__ __align__(16) uint32_t g_wph[4 * W_SZ];    // Wq,Wk,Wv,Wo packed [n][kp]
__device__ __align__(16) uint32_t g_wpl[4 * W_SZ];
__device__ __align__(16) uint32_t g_oph[IN_SZ];       // attn@V output packed
__device__ __align__(16) uint32_t g_opl[IN_SZ];
__device__ __align__(16) uint32_t g_qph[IN_SZ];       // projected Q/K packed
__device__ __align__(16) uint32_t g_qpl[IN_SZ];
__device__ __align__(16) uint32_t g_kph[IN_SZ];
__device__ __align__(16) uint32_t g_kpl[IN_SZ];
__device__ __align__(16) __nv_bfloat16 g_vth[Mrows * DMc];   // V^T [bh][d][s]
__device__ __align__(16) __nv_bfloat16 g_vtl[Mrows * DMc];

// ==================== helpers ====================
__device__ __forceinline__ uint32_t smem_u32(const void* p) {
    uint32_t a;
    asm("{ .reg .u64 t; cvta.to.shared.u64 t, %1; cvt.u32.u64 %0, t; }" : "=r"(a) : "l"(p));
    return a;
}
__device__ __forceinline__ void ldsm4(uint32_t (&r)[4], uint32_t addr) {
    asm volatile("ldmatrix.sync.aligned.m8n8.x4.shared.b16 {%0,%1,%2,%3}, [%4];"
        : "=r"(r[0]), "=r"(r[1]), "=r"(r[2]), "=r"(r[3]) : "r"(addr));
}
__device__ __forceinline__ void mma16816(float (&c)[4], const uint32_t (&a)[4],
                                         uint32_t b0, uint32_t b1) {
    asm volatile(
        "mma.sync.aligned.m16n8k16.row.col.f32.bf16.bf16.f32 "
        "{%0,%1,%2,%3}, {%4,%5,%6,%7}, {%8,%9}, {%0,%1,%2,%3};"
        : "+f"(c[0]), "+f"(c[1]), "+f"(c[2]), "+f"(c[3])
        : "r"(a[0]), "r"(a[1]), "r"(a[2]), "r"(a[3]), "r"(b0), "r"(b1));
}
__device__ __forceinline__ uint32_t addrA(uint32_t base, int r0, int k0, int lane, int stride) {
    return base + (uint32_t)(((r0 + (lane & 15)) * stride + (k0 >> 1) + (lane >> 4) * 4) * 4);
}
__device__ __forceinline__ uint32_t addrB(uint32_t base, int n0, int k0, int lane, int stride) {
    int r = n0 + (lane & 7) + ((lane >> 4) & 1) * 8;
    int c = (k0 >> 1) + ((lane >> 3) & 1) * 4;
    return base + (uint32_t)((r * stride + c) * 4);
}
__device__ __forceinline__ void split2(float x0, float x1, uint32_t& hi, uint32_t& lo) {
    uint32_t h;
    asm("cvt.rn.bf16x2.f32 %0, %1, %2;" : "=r"(h) : "f"(x1), "f"(x0));
    float f0 = __uint_as_float(h << 16);
    float f1 = __uint_as_float(h & 0xffff0000u);
    float r0 = x0 - f0, r1 = x1 - f1;
    asm("cvt.rn.bf16x2.f32 %0, %1, %2;" : "=r"(lo) : "f"(r1), "f"(r0));
    hi = h;
}
__device__ __forceinline__ void cpa16(uint32_t dst, const void* src) {
    asm volatile("cp.async.cg.shared.global [%0], [%1], 16;" :: "r"(dst), "l"(src));
}
#define CPA_COMMIT() asm volatile("cp.async.commit_group;" ::: "memory")
#define CPA_WAIT1()  asm volatile("cp.async.wait_group 1;" ::: "memory")
#define CPA_WAIT0()  asm volatile("cp.async.wait_group 0;" ::: "memory")

// ============================================================
// Prep kernels
// ============================================================
__global__ __launch_bounds__(256)
void pack_in_kernel(const float* __restrict__ q, const float* __restrict__ k,
                    const float* __restrict__ v)
{
    const float* src = blockIdx.y == 0 ? q : (blockIdx.y == 1 ? k : v);
    uint32_t* H = g_inh + (size_t)blockIdx.y * IN_SZ;
    uint32_t* L = g_inl + (size_t)blockIdx.y * IN_SZ;
    int idx = blockIdx.x * 256 + threadIdx.x;
    float4 vv = ((const float4*)src)[idx];
    uint32_t h0, l0, h1, l1;
    split2(vv.x, vv.y, h0, l0);
    split2(vv.z, vv.w, h1, l1);
    H[idx * 2] = h0; H[idx * 2 + 1] = h1;
    L[idx * 2] = l0; L[idx * 2 + 1] = l1;
}

__global__ __launch_bounds__(256)
void pack_w_kernel(const float* __restrict__ Wq, const float* __restrict__ Wk,
                   const float* __restrict__ Wv, const float* __restrict__ Wo)
{
    __shared__ float smw[64][33];
    const float* W = blockIdx.z == 0 ? Wq : (blockIdx.z == 1 ? Wk :
                     (blockIdx.z == 2 ? Wv : Wo));
    uint32_t* H = g_wph + (size_t)blockIdx.z * W_SZ;
    uint32_t* L = g_wpl + (size_t)blockIdx.z * W_SZ;
    const int k0 = blockIdx.x * 64, n0 = blockIdx.y * 32;
    const int t = threadIdx.x;
#pragma unroll
    for (int i = 0; i < 8; i++) {
        int idx = i * 256 + t;
        int kk = idx >> 5, nn = idx & 31;
        smw[kk][nn] = W[(size_t)(k0 + kk) * DMc + n0 + nn];
    }
    __syncthreads();
#pragma unroll
    for (int i = 0; i < 4; i++) {
        int idx = i * 256 + t;
        int n = idx >> 5, kp = idx & 31;
        uint32_t h, l;
        split2(smw[2 * kp][n], smw[2 * kp + 1][n], h, l);
        size_t o = (size_t)(n0 + n) * 256 + (k0 >> 1) + kp;
        H[o] = h; L[o] = l;
    }
}

// ============================================================
// Packed GEMM body: cp.async double-buffered.
// ============================================================
static constexpr int GRS = 20;
static constexpr int GA_H = 0, GA_L = 5120, GW_H = 10240, GW_L = 15360;
static constexpr int GEMM_SMEM = 20480 * 4;

__device__ __forceinline__ void gemm_stage(uint32_t sbase, int buf,
        const uint32_t* __restrict__ Ah, const uint32_t* __restrict__ Al,
        const uint32_t* __restrict__ Wh, const uint32_t* __restrict__ Wl,
        int mb, int nb, int kc, int tid)
{
    const int row = tid >> 1, half = tid & 1;
    size_t asrc = (size_t)(mb + row) * 256 + kc * 16 + half * 8;
    uint32_t d = sbase + (uint32_t)(GA_H + buf * 2560 + row * GRS + half * 8) * 4;
    cpa16(d, Ah + asrc); cpa16(d + 16, Ah + asrc + 4);
    d = sbase + (uint32_t)(GA_L + buf * 2560 + row * GRS + half * 8) * 4;
    cpa16(d, Al + asrc); cpa16(d + 16, Al + asrc + 4);
    size_t wsrc = (size_t)(nb + row) * 256 + kc * 16 + half * 8;
    d = sbase + (uint32_t)(GW_H + buf * 2560 + row * GRS + half * 8) * 4;
    cpa16(d, Wh + wsrc); cpa16(d + 16, Wh + wsrc + 4);
    d = sbase + (uint32_t)(GW_L + buf * 2560 + row * GRS + half * 8) * 4;
    cpa16(d, Wl + wsrc); cpa16(d + 16, Wl + wsrc + 4);
}

__device__ __forceinline__ void gemm_body_pk(
    const uint32_t* __restrict__ Ah, const uint32_t* __restrict__ Al,
    const uint32_t* __restrict__ Wh, const uint32_t* __restrict__ Wl,
    const float* __restrict__ bias,
    float* __restrict__ C, uint32_t* __restrict__ Hp, uint32_t* __restrict__ Lp,
    __nv_bfloat16* __restrict__ Ht, __nv_bfloat16* __restrict__ Lt,
    bool writeF, bool writeP, bool writeT, int mb, int nb)
{
    extern __shared__ uint32_t smp[];
    const int tid = threadIdx.x;
    const int w = tid >> 5, lane = tid & 31;
    const int g = lane >> 2, t = lane & 3;
    const int wm = (w >> 1) * 32, wn = (w & 1) * 64;
    const uint32_t sbase = smem_u32(smp);

    float c[2][8][4];
#pragma unroll
    for (int mi = 0; mi < 2; mi++)
#pragma unroll
        for (int nf = 0; nf < 8; nf++)
#pragma unroll
            for (int r = 0; r < 4; r++) c[mi][nf][r] = 0.f;

    gemm_stage(sbase, 0, Ah, Al, Wh, Wl, mb, nb, 0, tid);
    CPA_COMMIT();

    for (int kc = 0; kc < 16; kc++) {
        const int buf = kc & 1;
        if (kc < 15) {
            gemm_stage(sbase, buf ^ 1, Ah, Al, Wh, Wl, mb, nb, kc + 1, tid);
            CPA_COMMIT();
            CPA_WAIT1();
        } else {
            CPA_WAIT0();
        }
        __syncthreads();

        const uint32_t ah_b = sbase + (uint32_t)(GA_H + buf * 2560) * 4;
        const uint32_t al_b = sbase + (uint32_t)(GA_L + buf * 2560) * 4;
        const uint32_t wh_b = sbase + (uint32_t)(GW_H + buf * 2560) * 4;
        const uint32_t wl_b = sbase + (uint32_t)(GW_L + buf * 2560) * 4;
#pragma unroll
        for (int kk = 0; kk < 2; kk++) {
            uint32_t ah[2][4], al[2][4];
#pragma unroll
            for (int mi = 0; mi < 2; mi++) {
                ldsm4(ah[mi], addrA(ah_b, wm + mi * 16, kk * 16, lane, GRS));
                ldsm4(al[mi], addrA(al_b, wm + mi * 16, kk * 16, lane, GRS));
            }
#pragma unroll
            for (int nb2 = 0; nb2 < 4; nb2++) {
                uint32_t bhf[4], blf[4];
                ldsm4(bhf, addrB(wh_b, wn + nb2 * 16, kk * 16, lane, GRS));
                ldsm4(blf, addrB(wl_b, wn + nb2 * 16, kk * 16, lane, GRS));
#pragma unroll
                for (int mi = 0; mi < 2; mi++) {
                    mma16816(c[mi][2 * nb2],     ah[mi], bhf[0], bhf[1]);
                    mma16816(c[mi][2 * nb2],     ah[mi], blf[0], blf[1]);
                    mma16816(c[mi][2 * nb2],     al[mi], bhf[0], bhf[1]);
                    mma16816(c[mi][2 * nb2 + 1], ah[mi], bhf[2], bhf[3]);
                    mma16816(c[mi][2 * nb2 + 1], ah[mi], blf[2], blf[3]);
                    mma16816(c[mi][2 * nb2 + 1], al[mi], bhf[2], bhf[3]);
                }
            }
        }
        __syncthreads();
    }

#pragma unroll
    for (int mi = 0; mi < 2; mi++)
#pragma unroll
        for (int hh = 0; hh < 2; hh++) {
            int row = mb + wm + mi * 16 + hh * 8 + g;
#pragma unroll
            for (int nf = 0; nf < 8; nf++) {
                int col = nb + wn + nf * 8 + 2 * t;
                float2 bv = *(const float2*)(bias + col);
                float ox = c[mi][nf][hh * 2 + 0] + bv.x;
                float oy = c[mi][nf][hh * 2 + 1] + bv.y;
                if (writeF)
                    *(float2*)(C + (size_t)row * DMc + col) = make_float2(ox, oy);
                if (writeP) {
                    uint32_t hi, lo;
                    split2(ox, oy, hi, lo);
                    size_t pi = ((size_t)row * DMc + col) >> 1;
                    Hp[pi] = hi;
                    Lp[pi] = lo;
                }
                if (writeT) {
                    uint32_t hi, lo;
                    split2(ox, oy, hi, lo);
                    size_t i0 = ((size_t)(((row >> 11) * Hc + (col >> 6)) * DHc + (col & 63))) * Sc
                              + (row & (Sc - 1));
                    Ht[i0] = __ushort_as_bfloat16((unsigned short)(hi & 0xffff));
                    Lt[i0] = __ushort_as_bfloat16((unsigned short)(lo & 0xffff));
                    Ht[i0 + Sc] = __ushort_as_bfloat16((unsigned short)(hi >> 16));
                    Lt[i0 + Sc] = __ushort_as_bfloat16((unsigned short)(lo >> 16));
                }
            }
        }
}

// K1: fused Q/K/V projections. grid = (4, 32, 3), block 256.
__global__ __launch_bounds__(256, 2)
void qkv_kernel(const float* __restrict__ bq, const float* __restrict__ bk,
                const float* __restrict__ bv)
{
    const int mb = blockIdx.y * 128, nb = blockIdx.x * 128;
    const int z = blockIdx.z;
    const uint32_t* Ah = g_inh + (size_t)z * IN_SZ;
    const uint32_t* Al = g_inl + (size_t)z * IN_SZ;
    const uint32_t* Wh = g_wph + (size_t)z * W_SZ;
    const uint32_t* Wl = g_wpl + (size_t)z * W_SZ;
    if (z == 0)
        gemm_body_pk(Ah, Al, Wh, Wl, bq, nullptr, g_qph, g_qpl, nullptr, nullptr,
                     false, true, false, mb, nb);
    else if (z == 1)
        gemm_body_pk(Ah, Al, Wh, Wl, bk, nullptr, g_kph, g_kpl, nullptr, nullptr,
                     false, true, false, mb, nb);
    else
        gemm_body_pk(Ah, Al, Wh, Wl, bv, nullptr, nullptr, nullptr, g_vth, g_vtl,
                     false, false, true, mb, nb);
}

// K4: final projection. grid = (4, 32).
__global__ __launch_bounds__(256, 2)
void out_kernel(const float* __restrict__ bo, float* __restrict__ out)
{
    gemm_body_pk(g_oph, g_opl, g_wph + 3 * (size_t)W_SZ, g_wpl + 3 * (size_t)W_SZ,
                 bo, out, nullptr, nullptr, nullptr, nullptr,
                 true, false, false, blockIdx.y * 128, blockIdx.x * 128);
}

// ============================================================
// K2: a,b heads from packed qp (hi+lo reconstruct). grid = 128, block 256,
// warp handles 4 rows, W cached in smem.
// ============================================================
__global__ __launch_bounds__(256)
void ab_kernel(const float* __restrict__ Wa, const float* __restrict__ ba,
               const float* __restrict__ Wb, const float* __restrict__ bb)
{
    __shared__ float4 sWa[512][2];
    __shared__ float4 sWb[512][2];
    const int tid = threadIdx.x;
#pragma unroll
    for (int i = 0; i < 4; i++) {
        int idx = tid + i * 256;
        ((float4*)sWa)[idx] = ((const float4*)Wa)[idx];
        ((float4*)sWb)[idx] = ((const float4*)Wb)[idx];
    }
    __syncthreads();

    const int w = tid >> 5, lane = tid & 31;
    const int rbase = blockIdx.x * 32 + w * 4;

    float acc[4][16];
#pragma unroll
    for (int j = 0; j < 4; j++)
#pragma unroll
        for (int h = 0; h < 16; h++) acc[j][h] = 0.f;

#pragma unroll
    for (int tt = 0; tt < 4; tt++) {
        const int d0 = tt * 128 + lane * 4;      // column base (4 floats)
        const int p0 = d0 >> 1;                  // packed u32 index (2 words)
        float x[4][4];
#pragma unroll
        for (int j = 0; j < 4; j++) {
            size_t base = (size_t)(rbase + j) * 256 + p0;
            uint2 hv = *(const uint2*)(g_qph + base);
            uint2 lv = *(const uint2*)(g_qpl + base);
            x[j][0] = __uint_as_float(hv.x << 16)        + __uint_as_float(lv.x << 16);
            x[j][1] = __uint_as_float(hv.x & 0xffff0000u) + __uint_as_float(lv.x & 0xffff0000u);
            x[j][2] = __uint_as_float(hv.y << 16)        + __uint_as_float(lv.y << 16);
            x[j][3] = __uint_as_float(hv.y & 0xffff0000u) + __uint_as_float(lv.y & 0xffff0000u);
        }
#pragma unroll
        for (int dd = 0; dd < 4; dd++) {
            float4 wa0 = sWa[d0 + dd][0], wa1 = sWa[d0 + dd][1];
            float4 wb0 = sWb[d0 + dd][0], wb1 = sWb[d0 + dd][1];
#pragma unroll
            for (int j = 0; j < 4; j++) {
                float xv = x[j][dd];
                acc[j][0]  = fmaf(xv, wa0.x, acc[j][0]);
                acc[j][1]  = fmaf(xv, wa0.y, acc[j][1]);
                acc[j][2]  = fmaf(xv, wa0.z, acc[j][2]);
                acc[j][3]  = fmaf(xv, wa0.w, acc[j][3]);
                acc[j][4]  = fmaf(xv, wa1.x, acc[j][4]);
                acc[j][5]  = fmaf(xv, wa1.y, acc[j][5]);
                acc[j][6]  = fmaf(xv, wa1.z, acc[j][6]);
                acc[j][7]  = fmaf(xv, wa1.w, acc[j][7]);
                acc[j][8]  = fmaf(xv, wb0.x, acc[j][8]);
                acc[j][9]  = fmaf(xv, wb0.y, acc[j][9]);
                acc[j][10] = fmaf(xv, wb0.z, acc[j][10]);
                acc[j][11] = fmaf(xv, wb0.w, acc[j][11]);
                acc[j][12] = fmaf(xv, wb1.x, acc[j][12]);
                acc[j][13] = fmaf(xv, wb1.y, acc[j][13]);
                acc[j][14] = fmaf(xv, wb1.z, acc[j][14]);
                acc[j][15] = fmaf(xv, wb1.w, acc[j][15]);
            }
        }
    }
#pragma unroll
    for (int o = 16; o > 0; o >>= 1)
#pragma unroll
        for (int j = 0; j < 4; j++)
#pragma unroll
            for (int h = 0; h < 16; h++)
                acc[j][h] += __shfl_xor_sync(0xffffffff, acc[j][h], o);

    if (lane < 4) {
        int row = rbase + lane;
        int b = row >> 11, s = row & (Sc - 1);
#pragma unroll
        for (int h = 0; h < 8; h++) {
            g_a[(b * Hc + h) * Sc + s] = acc[lane][h] + ba[h];
            g_b[(b * Hc + h) * Sc + s] = acc[lane][h + 8] + bb[h];
        }
    }
}

// ============================================================
// Fused flash attention. grid = (16 qtile128, 16 bh), block = 512
// (16 warps: 8 m16-groups x 2 k32-halves). cp.async double-buffered K/V.
// ============================================================
static constexpr int QH_O = 0, QL_O = 4608, KH_O = 9216, KL_O = 13824;
static constexpr int VH_O = 18432, VL_O = 23040, RMT_O = 27648;
static constexpr int RSQ = 36;
static constexpr int TILE_W = 2304;
static constexpr int FUSE_SMEM = 35840 * 4;   // 143360 B

__device__ __forceinline__ void stage_q(uint32_t* sm,
        const uint32_t* __restrict__ srcH, const uint32_t* __restrict__ srcL,
        size_t rowbase, int tid)
{
    const int row = tid >> 2, q4 = tid & 3;
    const size_t s0 = rowbase + (size_t)row * 256 + q4 * 8;
    const uint4* sH = (const uint4*)(srcH + s0);
    const uint4* sL = (const uint4*)(srcL + s0);
    uint4* dH = (uint4*)(sm + QH_O + row * RSQ + q4 * 8);
    uint4* dL = (uint4*)(sm + QL_O + row * RSQ + q4 * 8);
    dH[0] = sH[0]; dH[1] = sH[1];
    dL[0] = sL[0]; dL[1] = sL[1];
}

__device__ __forceinline__ void stage_async(uint32_t sbase, int buf, int b, int bh, int h,
                                            int kb, int tid)
{
    const int row = tid >> 3;
    const int ch  = tid & 7;
    const uint32_t* kh = g_kph + (size_t)(b * Sc + kb + row) * 256 + h * 32 + ch * 4;
    const uint32_t* kl = g_kpl + (size_t)(b * Sc + kb + row) * 256 + h * 32 + ch * 4;
    cpa16(sbase + (uint32_t)(KH_O + buf * TILE_W + row * RSQ + ch * 4) * 4, kh);
    cpa16(sbase + (uint32_t)(KL_O + buf * TILE_W + row * RSQ + ch * 4) * 4, kl);
    const uint32_t* vh = (const uint32_t*)g_vth + (size_t)(bh * DHc + row) * 1024 + (kb >> 1) + ch * 4;
    const uint32_t* vl = (const uint32_t*)g_vtl + (size_t)(bh * DHc + row) * 1024 + (kb >> 1) + ch * 4;
    cpa16(sbase + (uint32_t)(VH_O + buf * TILE_W + row * RSQ + ch * 4) * 4, vh);
    cpa16(sbase + (uint32_t)(VL_O + buf * TILE_W + row * RSQ + ch * 4) * 4, vl);
}

__global__ __launch_bounds__(512, 1)
void fused_attn_kernel(const float* __restrict__ xdiff, const int* __restrict__ mask,
                       float* __restrict__ attn)
{
    extern __shared__ uint32_t sm[];
    const int tid = threadIdx.x, w = tid >> 5, lane = tid & 31;
    const int g = lane >> 2, t = lane & 3;
    const int bh = blockIdx.y, b = bh >> 3, h = bh & 7;
    const int qb = blockIdx.x * 128;
    const int wm = (w >> 1) * 16, wn = (w & 1) * 32;
    const uint32_t sbase = smem_u32(sm);

    stage_async(sbase, 0, b, bh, h, 0, tid);
    CPA_COMMIT();
    stage_q(sm, g_qph, g_qpl, (size_t)(b * Sc + qb) * 256 + h * 32, tid);

    const int lr0 = wm + g, lr1 = wm + 8 + g;
    float rm0 = -3.0e38f, rm1 = -3.0e38f, rs0 = 0.f, rs1 = 0.f;
    const float aq0 = g_a[bh * Sc + qb + lr0], bq0 = g_b[bh * Sc + qb + lr0];
    const float aq1 = g_a[bh * Sc + qb + lr1], bq1 = g_b[bh * Sc + qb + lr1];
    const float* xr0 = xdiff + ((size_t)b * Sc + qb + lr0) * Sc;
    const float* xr1 = xdiff + ((size_t)b * Sc + qb + lr1) * Sc;
    float* lrow0 = attn + ((size_t)bh * Sc + qb + lr0) * Sc;
    float* lrow1 = attn + ((size_t)bh * Sc + qb + lr1) * Sc;
    const int* mrow = mask + b * Sc;

    float o[8][4];
#pragma unroll
    for (int nf = 0; nf < 8; nf++)
#pragma unroll
        for (int r = 0; r < 4; r++) o[nf][r] = 0.f;

    for (int kt = 0; kt < 32; kt++) {
        const int kb = kt * 64;
        const int cur = kt & 1;
        if (kt < 31) {
            stage_async(sbase, cur ^ 1, b, bh, h, (kt + 1) * 64, tid);
            CPA_COMMIT();
            CPA_WAIT1();
        } else {
            CPA_WAIT0();
        }
        __syncthreads();

        int2 mv[4];
        float2 x0v[4], x1v[4];
#pragma unroll
        for (int nf = 0; nf < 4; nf++) {
            int col = kb + wn + nf * 8 + 2 * t;
            mv[nf]  = *(const int2*)(mrow + col);
            x0v[nf] = *(const float2*)(xr0 + col);
            x1v[nf] = *(const float2*)(xr1 + col);
        }

        float c[4][4];
#pragma unroll
        for (int nf = 0; nf < 4; nf++)
#pragma unroll
            for (int r = 0; r < 4; r++) c[nf][r] = 0.f;
        const uint32_t kh_b = sbase + (uint32_t)(KH_O + cur * TILE_W) * 4;
        const uint32_t kl_b = sbase + (uint32_t)(KL_O + cur * TILE_W) * 4;
#pragma unroll
        for (int kk = 0; kk < 4; kk++) {
            uint32_t ah[4], al[4];
            ldsm4(ah, addrA(sbase + QH_O * 4, wm, kk * 16, lane, RSQ));
            ldsm4(al, addrA(sbase + QL_O * 4, wm, kk * 16, lane, RSQ));
#pragma unroll
            for (int nb2 = 0; nb2 < 2; nb2++) {
                uint32_t bhf[4], blf[4];
                ldsm4(bhf, addrB(kh_b, wn + nb2 * 16, kk * 16, lane, RSQ));
                ldsm4(blf, addrB(kl_b, wn + nb2 * 16, kk * 16, lane, RSQ));
                mma16816(c[2 * nb2],     ah, bhf[0], bhf[1]);
                mma16816(c[2 * nb2],     ah, blf[0], blf[1]);
                mma16816(c[2 * nb2],     al, bhf[0], bhf[1]);
                mma16816(c[2 * nb2 + 1], ah, bhf[2], bhf[3]);
                mma16816(c[2 * nb2 + 1], ah, blf[2], blf[3]);
                mma16816(c[2 * nb2 + 1], al, bhf[2], bhf[3]);
            }
        }

        float tm0 = -3.0e38f, tm1 = -3.0e38f;
#pragma unroll
        for (int nf = 0; nf < 4; nf++) {
            float mt0 = (float)mv[nf].x * -1e9f, mt1 = (float)mv[nf].y * -1e9f;
            float2 x0 = x0v[nf], x1 = x1v[nf];
            c[nf][0] = c[nf][0] * 0.125f + mt0 + aq0 * x0.x + bq0 * x0.x * x0.x;
            c[nf][1] = c[nf][1] * 0.125f + mt1 + aq0 * x0.y + bq0 * x0.y * x0.y;
            c[nf][2] = c[nf][2] * 0.125f + mt0 + aq1 * x1.x + bq1 * x1.x * x1.x;
            c[nf][3] = c[nf][3] * 0.125f + mt1 + aq1 * x1.y + bq1 * x1.y * x1.y;
            tm0 = fmaxf(tm0, fmaxf(c[nf][0], c[nf][1]));
            tm1 = fmaxf(tm1, fmaxf(c[nf][2], c[nf][3]));
        }
        tm0 = fmaxf(tm0, __shfl_xor_sync(0xffffffff, tm0, 1));
        tm0 = fmaxf(tm0, __shfl_xor_sync(0xffffffff, tm0, 2));
        tm1 = fmaxf(tm1, __shfl_xor_sync(0xffffffff, tm1, 1));
        tm1 = fmaxf(tm1, __shfl_xor_sync(0xffffffff, tm1, 2));
        float m0 = fmaxf(rm0, tm0), m1 = fmaxf(rm1, tm1);
        float sc0 = __expf(rm0 - m0), sc1 = __expf(rm1 - m1);
        rs0 *= sc0; rs1 *= sc1;
#pragma unroll
        for (int nf = 0; nf < 8; nf++) {
            o[nf][0] *= sc0; o[nf][1] *= sc0;
            o[nf][2] *= sc1; o[nf][3] *= sc1;
        }
        rm0 = m0; rm1 = m1;
        if (t == 0) {
            float* rmt = (float*)(sm + RMT_O);
            rmt[(kt * 16 + w) * 16 + g]     = rm0;
            rmt[(kt * 16 + w) * 16 + 8 + g] = rm1;
        }

        const uint32_t vh_b = sbase + (uint32_t)(VH_O + cur * TILE_W) * 4;
        const uint32_t vl_b = sbase + (uint32_t)(VL_O + cur * TILE_W) * 4;
#pragma unroll
        for (int j = 0; j < 2; j++) {
            uint32_t pah[4], pal[4];
#pragma unroll
            for (int nn = 0; nn < 2; nn++) {
                int nf = 2 * j + nn;
                int col = kb + wn + nf * 8 + 2 * t;
                float p0 = __expf(c[nf][0] - rm0), p1 = __expf(c[nf][1] - rm0);
                float p2 = __expf(c[nf][2] - rm1), p3 = __expf(c[nf][3] - rm1);
                rs0 += p0 + p1; rs1 += p2 + p3;
                *(float2*)(lrow0 + col) = make_float2(p0, p1);
                *(float2*)(lrow1 + col) = make_float2(p2, p3);
                split2(p0, p1, pah[nn * 2 + 0], pal[nn * 2 + 0]);
                split2(p2, p3, pah[nn * 2 + 1], pal[nn * 2 + 1]);
            }
#pragma unroll
            for (int nd = 0; nd < 4; nd++) {
                uint32_t vh[4], vl[4];
                ldsm4(vh, addrB(vh_b, nd * 16, wn + j * 16, lane, RSQ));
                ldsm4(vl, addrB(vl_b, nd * 16, wn + j * 16, lane, RSQ));
                mma16816(o[2 * nd],     pah, vh[0], vh[1]);
                mma16816(o[2 * nd],     pah, vl[0], vl[1]);
                mma16816(o[2 * nd],     pal, vh[0], vh[1]);
                mma16816(o[2 * nd + 1], pah, vh[2], vh[3]);
                mma16816(o[2 * nd + 1], pah, vl[2], vl[3]);
                mma16816(o[2 * nd + 1], pal, vh[2], vh[3]);
            }
        }
        __syncthreads();
    }

    rs0 += __shfl_xor_sync(0xffffffff, rs0, 1);
    rs0 += __shfl_xor_sync(0xffffffff, rs0, 2);
    rs1 += __shfl_xor_sync(0xffffffff, rs1, 1);
    rs1 += __shfl_xor_sync(0xffffffff, rs1, 2);

    float2* sred = (float2*)sm;
    if (t == 0) {
        sred[w * 16 + g]     = make_float2(rm0, rs0);
        sred[w * 16 + 8 + g] = make_float2(rm1, rs1);
    }
    __syncthreads();
    float* mfin = (float*)(sm + QL_O);
    float* ifin = mfin + 128;
    if (!(w & 1) && t == 0) {
#pragma unroll
        for (int hh = 0; hh < 2; hh++) {
            int rl = hh * 8 + g;
            float2 A2 = sred[w * 16 + rl], B2 = sred[(w ^ 1) * 16 + rl];
            float mf = fmaxf(A2.x, B2.x);
            float sf = A2.y * __expf(A2.x - mf) + B2.y * __expf(B2.x - mf);
            mfin[wm + rl] = mf;
            ifin[wm + rl] = 1.0f / sf;
        }
    }
    __syncthreads();

    {
        float* rmt = (float*)(sm + RMT_O);
        for (int i = tid; i < 8192; i += 512) {
            int ww = (i >> 4) & 15, r = i & 15;
            int row = (ww >> 1) * 16 + r;
            rmt[i] = __expf(rmt[i] - mfin[row]) * ifin[row];
        }
    }
    float f0 = __expf(rm0 - mfin[lr0]);
    float f1 = __expf(rm1 - mfin[lr1]);
    float* red = (float*)(sm + KH_O);
    if (w & 1) {
        float* dst = red + ((w >> 1) * 32 + lane) * 33;
#pragma unroll
        for (int nf = 0; nf < 8; nf++) {
            dst[nf * 4 + 0] = o[nf][0] * f0;
            dst[nf * 4 + 1] = o[nf][1] * f0;
            dst[nf * 4 + 2] = o[nf][2] * f1;
            dst[nf * 4 + 3] = o[nf][3] * f1;
        }
    }
    __syncthreads();
    if (!(w & 1)) {
        const float* src = red + ((w >> 1) * 32 + lane) * 33;
        float i0 = ifin[lr0], i1 = ifin[lr1];
        int q0 = qb + lr0, q1 = qb + lr1;
#pragma unroll
        for (int nf = 0; nf < 8; nf++) {
            float v0 = (o[nf][0] * f0 + src[nf * 4 + 0]) * i0;
            float v1 = (o[nf][1] * f0 + src[nf * 4 + 1]) * i0;
            float v2 = (o[nf][2] * f1 + src[nf * 4 + 2]) * i1;
            float v3 = (o[nf][3] * f1 + src[nf * 4 + 3]) * i1;
            uint32_t h0, l0, h1, l1;
            split2(v0, v1, h0, l0);
            split2(v2, v3, h1, l1);
            size_t pi0 = (size_t)(b * Sc + q0) * 256 + h * 32 + nf * 4 + t;
            size_t pi1 = (size_t)(b * Sc + q1) * 256 + h * 32 + nf * 4 + t;
            g_oph[pi0] = h0; g_opl[pi0] = l0;
            g_oph[pi1] = h1; g_opl[pi1] = l1;
        }
    }

    // phase 3: normalize attn in place (coalesced)
    const float* rmt = (const float*)(sm + RMT_O);
    const size_t abase = ((size_t)bh * Sc + qb) * Sc;
#pragma unroll 4
    for (int i = 0; i < 128; i++) {
        int f4 = i * 512 + tid;
        int row = f4 >> 9;
        int col = (f4 & 511) * 4;
        int tile = col >> 6;
        int half = (col >> 5) & 1;
        int wwr = (row >> 4) * 2 + half;
        float s = rmt[(tile * 16 + wwr) * 16 + (row & 15)];
        float* ptr = attn + abase + (size_t)row * Sc + col;
        float4 P = *(float4*)ptr;
        P.x *= s; P.y *= s; P.z *= s; P.w *= s;
        *(float4*)ptr = P;
    }
}

// ============================================================
extern "C" void kernel_launch(void* const* d_in, const int* in_sizes, int n_in,
                              void* d_out, int out_size)
{
    const float* q     = (const float*)d_in[0];
    const float* k     = (const float*)d_in[1];
    const float* v     = (const float*)d_in[2];
    const float* xdiff = (const float*)d_in[3];
    const int*   mask  = (const int*)d_in[4];
    const float* Wq = (const float*)d_in[5];
    const float* bq = (const float*)d_in[6];
    const float* Wk = (const float*)d_in[7];
    const float* bk = (const float*)d_in[8];
    const float* Wv = (const float*)d_in[9];
    const float* bv = (const float*)d_in[10];
    const float* Wa = (const float*)d_in[11];
    const float* ba = (const float*)d_in[12];
    const float* Wb = (const float*)d_in[13];
    const float* bb = (const float*)d_in[14];
    const float* Wo = (const float*)d_in[15];
    const float* bo = (const float*)d_in[16];

    float* out  = (float*)d_out;                 // (B,S,DM)
    float* attn = out + (size_t)Bc * Sc * DMc;   // (B,H,S,S)

    cudaFuncSetAttribute(fused_attn_kernel, cudaFuncAttributeMaxDynamicSharedMemorySize, FUSE_SMEM);
    cudaFuncSetAttribute(qkv_kernel, cudaFuncAttributeMaxDynamicSharedMemorySize, GEMM_SMEM);
    cudaFuncSetAttribute(out_kernel, cudaFuncAttributeMaxDynamicSharedMemorySize, GEMM_SMEM);

    pack_w_kernel<<<dim3(8, 16, 4), 256>>>(Wq, Wk, Wv, Wo);
    pack_in_kernel<<<dim3(2048, 3), 256>>>(q, k, v);
    qkv_kernel<<<dim3(DMc / 128, Mrows / 128, 3), 256, GEMM_SMEM>>>(bq, bk, bv);
    ab_kernel<<<Mrows / 32, 256>>>(Wa, ba, Wb, bb);
    fused_attn_kernel<<<dim3(Sc / 128, BHc), 512, FUSE_SMEM>>>(xdiff, mask, attn);
    out_kernel<<<dim3(DMc / 128, Mrows / 128), 256, GEMM_SMEM>>>(bo, out);
}